// round 1
// baseline (speedup 1.0000x reference)
#include <cuda_runtime.h>
#include <math.h>

#define N_NODES 8192
#define NE      49152
#define ETOT    (NE + N_NODES)       // 57344
#define IN_F    128
#define H1      64
#define HID     64
#define F1      (H1*HID)             // 4096
#define H2      5
#define OUTF    32
#define F2      (H2*OUTF)            // 160
#define NB      64

// ------------------------------ scratch (static, no allocation) --------------
__device__ float g_h1[(size_t)N_NODES * F1];   // 134 MB
__device__ float g_x1[(size_t)N_NODES * F1];   // 134 MB
__device__ float g_as1[N_NODES * H1];
__device__ float g_ad1[N_NODES * H1];
__device__ float g_h2[N_NODES * F2];
__device__ float g_as2[N_NODES * H2];
__device__ float g_ad2[N_NODES * H2];
__device__ float g_x2[N_NODES * OUTF];
__device__ int   g_counts[N_NODES];
__device__ int   g_off[N_NODES + 1];
__device__ int   g_cursor[N_NODES];
__device__ int   g_csr_src[ETOT];

// ------------------------------ packed fp32 FMA ------------------------------
__device__ __forceinline__ void ffma2(unsigned long long &d,
                                      unsigned long long a,
                                      unsigned long long b) {
    asm("fma.rn.f32x2 %0, %1, %2, %0;" : "+l"(d) : "l"(a), "l"(b));
}

// ------------------------------ CSR build ------------------------------------
__global__ void k_init_counts() {
    int i = blockIdx.x * blockDim.x + threadIdx.x;
    if (i < N_NODES) g_counts[i] = 1;  // self-loop
}

__global__ void k_count(const int* __restrict__ ei) {
    int e = blockIdx.x * blockDim.x + threadIdx.x;
    if (e < NE) atomicAdd(&g_counts[ei[NE + e]], 1);
}

__global__ void k_scan() {
    __shared__ int sh[1024];
    int t = threadIdx.x;
    int loc[8];
    int s = 0;
#pragma unroll
    for (int j = 0; j < 8; j++) { loc[j] = g_counts[t * 8 + j]; s += loc[j]; }
    sh[t] = s;
    __syncthreads();
    for (int off = 1; off < 1024; off <<= 1) {
        int v = (t >= off) ? sh[t - off] : 0;
        __syncthreads();
        sh[t] += v;
        __syncthreads();
    }
    int run = (t == 0) ? 0 : sh[t - 1];
#pragma unroll
    for (int j = 0; j < 8; j++) {
        int idx = t * 8 + j;
        g_off[idx] = run;
        g_cursor[idx] = run;
        run += loc[j];
    }
    if (t == 1023) g_off[N_NODES] = run;
}

__global__ void k_scatter(const int* __restrict__ ei) {
    int i = blockIdx.x * blockDim.x + threadIdx.x;
    if (i >= ETOT) return;
    int src, dst;
    if (i < NE) { src = ei[i]; dst = ei[NE + i]; }
    else        { src = i - NE; dst = src; }
    int pos = atomicAdd(&g_cursor[dst], 1);
    g_csr_src[pos] = src;
}

// ------------------------------ GEMM: C[M,N] = A[M,K] * B[N,K]^T --------------
// fp32, FFMA2 inner loop (pairs along M, B duplicated in shared)
#define BM 64
#define BN 64
#define BK 16

__global__ __launch_bounds__(256)
void gemm_nt_f32x2(const float* __restrict__ A, const float* __restrict__ B,
                   float* __restrict__ C, int M, int N, int K) {
    __shared__ float As[BK][BM + 4];
    __shared__ float Bsd[BK][2 * BN + 4];
    const int tx = threadIdx.x;
    const int m0 = blockIdx.y * BM, n0 = blockIdx.x * BN;
    const int tm = (tx >> 4) << 2;   // 0..60
    const int tn = (tx & 15) << 2;   // 0..60
    unsigned long long acc[2][4] = {};

    for (int k0 = 0; k0 < K; k0 += BK) {
#pragma unroll
        for (int u = 0; u < (BM * BK) / 256; u++) {
            int idx = tx + u * 256;
            int r = idx >> 4, c = idx & 15;
            int gm = m0 + r;
            As[c][r] = (gm < M) ? A[(size_t)gm * K + k0 + c] : 0.f;
        }
#pragma unroll
        for (int u = 0; u < (BN * BK) / 256; u++) {
            int idx = tx + u * 256;
            int r = idx >> 4, c = idx & 15;
            int gn = n0 + r;
            float v = (gn < N) ? B[(size_t)gn * K + k0 + c] : 0.f;
            Bsd[c][2 * r] = v;
            Bsd[c][2 * r + 1] = v;
        }
        __syncthreads();
#pragma unroll
        for (int k = 0; k < BK; k++) {
            unsigned long long a2[2], b2[4];
            const unsigned long long* pa =
                reinterpret_cast<const unsigned long long*>(&As[k][tm]);
            a2[0] = pa[0]; a2[1] = pa[1];
            const unsigned long long* pb =
                reinterpret_cast<const unsigned long long*>(&Bsd[k][2 * tn]);
            b2[0] = pb[0]; b2[1] = pb[1]; b2[2] = pb[2]; b2[3] = pb[3];
#pragma unroll
            for (int i = 0; i < 2; i++)
#pragma unroll
                for (int j = 0; j < 4; j++) ffma2(acc[i][j], a2[i], b2[j]);
        }
        __syncthreads();
    }
#pragma unroll
    for (int i = 0; i < 2; i++)
#pragma unroll
        for (int j = 0; j < 4; j++) {
            float2 v = *reinterpret_cast<float2*>(&acc[i][j]);
            int gm = m0 + tm + 2 * i;
            int gn = n0 + tn + j;
            if (gn < N) {
                if (gm < M)     C[(size_t)gm * N + gn]       = v.x;
                if (gm + 1 < M) C[(size_t)(gm + 1) * N + gn] = v.y;
            }
        }
}

// ------------------------------ attention dots: layer 1 ----------------------
// one warp per (node, head): alpha = sum_c h[n,h,c] * att[h,c]
__global__ __launch_bounds__(256)
void k_alpha1(const float* __restrict__ att_s, const float* __restrict__ att_d) {
    int w = blockIdx.x * 8 + (threadIdx.x >> 5);
    int lane = threadIdx.x & 31;
    int n = w >> 6, head = w & 63;
    const float* hp = g_h1 + (size_t)n * F1 + head * HID;
    float h0 = hp[lane], h1v = hp[lane + 32];
    float s = h0 * att_s[head * HID + lane] + h1v * att_s[head * HID + lane + 32];
    float d = h0 * att_d[head * HID + lane] + h1v * att_d[head * HID + lane + 32];
#pragma unroll
    for (int o = 16; o > 0; o >>= 1) {
        s += __shfl_down_sync(0xffffffffu, s, o);
        d += __shfl_down_sync(0xffffffffu, d, o);
    }
    if (!lane) { g_as1[n * H1 + head] = s; g_ad1[n * H1 + head] = d; }
}

// ------------------------------ layer-1 aggregation + ELU --------------------
// block per dst node; streaming softmax (max pass, then exp/denom fused with
// the weighted sum). Thread t owns 16 contiguous features [t*16, t*16+16).
__global__ __launch_bounds__(256)
void k_agg1(const float* __restrict__ b1) {
    const int n = blockIdx.x;
    const int t = threadIdx.x;
    const int start = g_off[n];
    const int deg = g_off[n + 1] - start;

    __shared__ float sh_m[H1], sh_den[H1], sh_ad[H1];
    __shared__ float sh_w[32 * H1];
    __shared__ int   s_src[32];

    if (t < H1) {
        float adv = g_ad1[n * H1 + t];
        float m = -1e30f;
        for (int e = 0; e < deg; e++) {
            int s = g_csr_src[start + e];
            float l = g_as1[s * H1 + t] + adv;
            l = l > 0.f ? l : 0.2f * l;
            m = fmaxf(m, l);
        }
        float den = 0.f;
        for (int e = 0; e < deg; e++) {
            int s = g_csr_src[start + e];
            float l = g_as1[s * H1 + t] + adv;
            l = l > 0.f ? l : 0.2f * l;
            den += __expf(l - m);
        }
        sh_m[t] = m; sh_den[t] = den; sh_ad[t] = adv;
    }
    __syncthreads();

    float acc[16];
#pragma unroll
    for (int i = 0; i < 16; i++) acc[i] = 0.f;
    const int h = t >> 2;  // head of this thread's 16-feature slice

    for (int e0 = 0; e0 < deg; e0 += 32) {
        int ce = min(32, deg - e0);
        if (t < ce) s_src[t] = g_csr_src[start + e0 + t];
        __syncthreads();
        for (int k = t; k < ce * H1; k += 256) {
            int e = k >> 6, hh = k & 63;
            float l = g_as1[s_src[e] * H1 + hh] + sh_ad[hh];
            l = l > 0.f ? l : 0.2f * l;
            sh_w[k] = __expf(l - sh_m[hh]);
        }
        __syncthreads();
        for (int e = 0; e < ce; e++) {
            const float4* hp = reinterpret_cast<const float4*>(
                g_h1 + (size_t)s_src[e] * F1 + t * 16);
            float wv = sh_w[(e << 6) + h];
#pragma unroll
            for (int q = 0; q < 4; q++) {
                float4 v = hp[q];
                acc[4 * q + 0] += wv * v.x;
                acc[4 * q + 1] += wv * v.y;
                acc[4 * q + 2] += wv * v.z;
                acc[4 * q + 3] += wv * v.w;
            }
        }
        __syncthreads();
    }

    float invden = 1.f / sh_den[h];
    float4* outp = reinterpret_cast<float4*>(g_x1 + (size_t)n * F1 + t * 16);
    const float4* bp = reinterpret_cast<const float4*>(b1 + t * 16);
#pragma unroll
    for (int q = 0; q < 4; q++) {
        float4 bv = bp[q];
        float v0 = acc[4 * q + 0] * invden + bv.x;
        float v1 = acc[4 * q + 1] * invden + bv.y;
        float v2 = acc[4 * q + 2] * invden + bv.z;
        float v3 = acc[4 * q + 3] * invden + bv.w;
        float4 o;
        o.x = v0 > 0.f ? v0 : __expf(v0) - 1.f;
        o.y = v1 > 0.f ? v1 : __expf(v1) - 1.f;
        o.z = v2 > 0.f ? v2 : __expf(v2) - 1.f;
        o.w = v3 > 0.f ? v3 : __expf(v3) - 1.f;
        outp[q] = o;
    }
}

// ------------------------------ attention dots: layer 2 ----------------------
// one warp per node
__global__ __launch_bounds__(256)
void k_alpha2(const float* __restrict__ att_s, const float* __restrict__ att_d) {
    int n = blockIdx.x * 8 + (threadIdx.x >> 5);
    int lane = threadIdx.x & 31;
    if (n >= N_NODES) return;
    const float* hp = g_h2 + (size_t)n * F2;
#pragma unroll
    for (int hh = 0; hh < H2; hh++) {
        float v = hp[hh * OUTF + lane];
        float s = v * att_s[hh * OUTF + lane];
        float d = v * att_d[hh * OUTF + lane];
#pragma unroll
        for (int o = 16; o > 0; o >>= 1) {
            s += __shfl_down_sync(0xffffffffu, s, o);
            d += __shfl_down_sync(0xffffffffu, d, o);
        }
        if (!lane) { g_as2[n * H2 + hh] = s; g_ad2[n * H2 + hh] = d; }
    }
}

// ------------------------------ layer-2 aggregation + head mean --------------
__global__ __launch_bounds__(192)
void k_agg2(const float* __restrict__ b2) {
    const int n = blockIdx.x;
    const int t = threadIdx.x;
    const int start = g_off[n];
    const int deg = g_off[n + 1] - start;

    __shared__ float sh_m[H2], sh_den[H2], sh_ad[H2];
    __shared__ float sh_r[F2];

    if (t < H2) {
        float adv = g_ad2[n * H2 + t];
        float m = -1e30f;
        for (int e = 0; e < deg; e++) {
            int s = g_csr_src[start + e];
            float l = g_as2[s * H2 + t] + adv;
            l = l > 0.f ? l : 0.2f * l;
            m = fmaxf(m, l);
        }
        float den = 0.f;
        for (int e = 0; e < deg; e++) {
            int s = g_csr_src[start + e];
            float l = g_as2[s * H2 + t] + adv;
            l = l > 0.f ? l : 0.2f * l;
            den += __expf(l - m);
        }
        sh_m[t] = m; sh_den[t] = den; sh_ad[t] = adv;
    }
    __syncthreads();

    if (t < F2) {
        int hh = t >> 5;
        float m = sh_m[hh], adv = sh_ad[hh];
        float acc = 0.f;
        for (int e = 0; e < deg; e++) {
            int s = g_csr_src[start + e];
            float l = g_as2[s * H2 + hh] + adv;
            l = l > 0.f ? l : 0.2f * l;
            acc += __expf(l - m) * g_h2[s * F2 + t];
        }
        sh_r[t] = acc / sh_den[hh];
    }
    __syncthreads();

    if (t < OUTF) {
        float v = (sh_r[t] + sh_r[32 + t] + sh_r[64 + t] + sh_r[96 + t] +
                   sh_r[128 + t]) * 0.2f + b2[t];
        g_x2[n * OUTF + t] = v;
    }
}

// ------------------------------ bond scores + softmax ------------------------
__global__ void k_score(const int* __restrict__ lefts,
                        const int* __restrict__ rights,
                        float* __restrict__ out) {
    __shared__ float sm[NB];
    int t = threadIdx.x;
    int l = lefts[t], r = rights[t];
    float s = 0.f;
#pragma unroll
    for (int c = 0; c < OUTF; c++) s += g_x2[l * OUTF + c] + g_x2[r * OUTF + c];
    sm[t] = s;
    __syncthreads();
    float mx = -1e30f;
    for (int j = 0; j < NB; j++) mx = fmaxf(mx, sm[j]);
    float e = __expf(s - mx);
    __syncthreads();
    sm[t] = e;
    __syncthreads();
    float sum = 0.f;
    for (int j = 0; j < NB; j++) sum += sm[j];
    out[t] = e / sum;
}

// ------------------------------ launch ---------------------------------------
extern "C" void kernel_launch(void* const* d_in, const int* in_sizes, int n_in,
                              void* d_out, int out_size) {
    const float* x   = (const float*)d_in[0];
    const int*   ei  = (const int*)d_in[1];
    const int*   lf  = (const int*)d_in[2];
    const int*   rt  = (const int*)d_in[3];
    const float* W1  = (const float*)d_in[4];
    const float* as1 = (const float*)d_in[5];
    const float* ad1 = (const float*)d_in[6];
    const float* b1  = (const float*)d_in[7];
    const float* W2  = (const float*)d_in[8];
    const float* as2 = (const float*)d_in[9];
    const float* ad2 = (const float*)d_in[10];
    const float* b2  = (const float*)d_in[11];
    float* out = (float*)d_out;

    void *p_h1, *p_x1, *p_h2;
    cudaGetSymbolAddress(&p_h1, g_h1);
    cudaGetSymbolAddress(&p_x1, g_x1);
    cudaGetSymbolAddress(&p_h2, g_h2);

    // CSR by destination (self-loops included)
    k_init_counts<<<(N_NODES + 255) / 256, 256>>>();
    k_count<<<(NE + 255) / 256, 256>>>(ei);
    k_scan<<<1, 1024>>>();
    k_scatter<<<(ETOT + 255) / 256, 256>>>(ei);

    // layer 1
    gemm_nt_f32x2<<<dim3(F1 / BN, N_NODES / BM), 256>>>(
        x, W1, (float*)p_h1, N_NODES, F1, IN_F);
    k_alpha1<<<(N_NODES * H1) / 8, 256>>>(as1, ad1);
    k_agg1<<<N_NODES, 256>>>(b1);

    // layer 2
    gemm_nt_f32x2<<<dim3((F2 + BN - 1) / BN, N_NODES / BM), 256>>>(
        (const float*)p_x1, W2, (float*)p_h2, N_NODES, F2, F1);
    k_alpha2<<<N_NODES / 8, 256>>>(as2, ad2);
    k_agg2<<<N_NODES, 192>>>(b2);

    // bonds
    k_score<<<1, NB>>>(lf, rt, out);
}

// round 4
// speedup vs baseline: 2.1439x; 2.1439x over previous
#include <cuda_runtime.h>
#include <cuda_bf16.h>
#include <stdint.h>
#include <math.h>

#define N_NODES 8192
#define NE      49152
#define ETOT    (NE + N_NODES)       // 57344
#define IN_F    128
#define H1      64
#define HID     64
#define F1      (H1*HID)             // 4096
#define H2      5
#define OUTF    32
#define F2      (H2*OUTF)            // 160
#define NB      64

// ------------------------------ scratch (static, no allocation) --------------
__device__ float g_h1[(size_t)N_NODES * F1];                 // 134 MB
__device__ __nv_bfloat16 g_x1h[(size_t)N_NODES * F1];        // 67 MB
__device__ __nv_bfloat16 g_x1l[(size_t)N_NODES * F1];        // 67 MB
__device__ __nv_bfloat16 g_xh[N_NODES * IN_F];
__device__ __nv_bfloat16 g_xl[N_NODES * IN_F];
__device__ __nv_bfloat16 g_w1h[F1 * IN_F];
__device__ __nv_bfloat16 g_w1l[F1 * IN_F];
__device__ __nv_bfloat16 g_w2h[F2 * F1];
__device__ __nv_bfloat16 g_w2l[F2 * F1];
__device__ float g_as1[N_NODES * H1];
__device__ float g_ad1[N_NODES * H1];
__device__ float g_h2[N_NODES * F2];
__device__ float g_as2[N_NODES * H2];
__device__ float g_ad2[N_NODES * H2];
__device__ float g_x2[N_NODES * OUTF];
__device__ int   g_counts[N_NODES];
__device__ int   g_off[N_NODES + 1];
__device__ int   g_cursor[N_NODES];
__device__ int   g_csr_src[ETOT];

// ------------------------------ PTX helpers ----------------------------------
__device__ __forceinline__ uint32_t smem_u32(const void* p) {
    uint32_t a;
    asm("{ .reg .u64 t; cvta.to.shared.u64 t, %1; cvt.u32.u64 %0, t; }"
        : "=r"(a) : "l"(p));
    return a;
}

__device__ __forceinline__ void cpa16(uint32_t d, const void* s) {
    asm volatile("cp.async.cg.shared.global [%0], [%1], 16;" :: "r"(d), "l"(s));
}
__device__ __forceinline__ void cpa_commit() {
    asm volatile("cp.async.commit_group;" ::: "memory");
}
template <int N> __device__ __forceinline__ void cpa_wait() {
    asm volatile("cp.async.wait_group %0;" :: "n"(N) : "memory");
}

__device__ __forceinline__ void ldsm4(uint32_t* r, uint32_t addr) {
    asm volatile("ldmatrix.sync.aligned.m8n8.x4.shared.b16 {%0,%1,%2,%3}, [%4];"
                 : "=r"(r[0]), "=r"(r[1]), "=r"(r[2]), "=r"(r[3]) : "r"(addr));
}

__device__ __forceinline__ void mma16816(float* c, const uint32_t* a,
                                         const uint32_t* b) {
    asm volatile(
        "mma.sync.aligned.m16n8k16.row.col.f32.bf16.bf16.f32 "
        "{%0,%1,%2,%3}, {%4,%5,%6,%7}, {%8,%9}, {%0,%1,%2,%3};"
        : "+f"(c[0]), "+f"(c[1]), "+f"(c[2]), "+f"(c[3])
        : "r"(a[0]), "r"(a[1]), "r"(a[2]), "r"(a[3]), "r"(b[0]), "r"(b[1]));
}

// ------------------------------ CSR build ------------------------------------
__global__ void k_init_counts() {
    int i = blockIdx.x * blockDim.x + threadIdx.x;
    if (i < N_NODES) g_counts[i] = 1;  // self-loop
}

__global__ void k_count(const int* __restrict__ ei) {
    int e = blockIdx.x * blockDim.x + threadIdx.x;
    if (e < NE) atomicAdd(&g_counts[ei[NE + e]], 1);
}

__global__ void k_scan() {
    __shared__ int sh[1024];
    int t = threadIdx.x;
    int loc[8];
    int s = 0;
#pragma unroll
    for (int j = 0; j < 8; j++) { loc[j] = g_counts[t * 8 + j]; s += loc[j]; }
    sh[t] = s;
    __syncthreads();
    for (int off = 1; off < 1024; off <<= 1) {
        int v = (t >= off) ? sh[t - off] : 0;
        __syncthreads();
        sh[t] += v;
        __syncthreads();
    }
    int run = (t == 0) ? 0 : sh[t - 1];
#pragma unroll
    for (int j = 0; j < 8; j++) {
        int idx = t * 8 + j;
        g_off[idx] = run;
        g_cursor[idx] = run;
        run += loc[j];
    }
    if (t == 1023) g_off[N_NODES] = run;
}

__global__ void k_scatter(const int* __restrict__ ei) {
    int i = blockIdx.x * blockDim.x + threadIdx.x;
    if (i >= ETOT) return;
    int src, dst;
    if (i < NE) { src = ei[i]; dst = ei[NE + i]; }
    else        { src = i - NE; dst = src; }
    int pos = atomicAdd(&g_cursor[dst], 1);
    g_csr_src[pos] = src;
}

// ------------------------------ fp32 -> bf16 hi/lo split ---------------------
__global__ void k_split(const float* __restrict__ in, __nv_bfloat16* __restrict__ hi,
                        __nv_bfloat16* __restrict__ lo, int n) {
    int i = blockIdx.x * blockDim.x + threadIdx.x;
    if (i < n) {
        float v = in[i];
        __nv_bfloat16 h = __float2bfloat16_rn(v);
        hi[i] = h;
        lo[i] = __float2bfloat16_rn(v - __bfloat162float(h));
    }
}

// ------------------------------ mma.sync GEMM --------------------------------
// C[M,N] = (Ah+Al)[M,K] * (Bh+Bl)[N,K]^T  (3-term hi/lo compensation)
// Tiles: BM=128, BN=128, BK=32 bf16. 256 threads (8 warps, 4m x 2n).
#define TSTRIDE 80                        // bytes per smem row (5 x 16B segs)
#define TILEB   (128 * TSTRIDE)           // 10240 B
#define STAGEB  (4 * TILEB)               // Ah, Al, Bh, Bl
#define GEMM_SMEM (2 * STAGEB)            // 81920 B

__global__ __launch_bounds__(256, 1)
void gemm_mma(const __nv_bfloat16* __restrict__ Ah, const __nv_bfloat16* __restrict__ Al,
              const __nv_bfloat16* __restrict__ Bh, const __nv_bfloat16* __restrict__ Bl,
              float* __restrict__ C, int N, int K) {
    extern __shared__ char smem[];
    const int tid = threadIdx.x;
    const int wid = tid >> 5, lane = tid & 31;
    const int m0 = blockIdx.y * 128, n0 = blockIdx.x * 128;
    const int wm = wid >> 1, wn = wid & 1;
    const int NC = K >> 5;                // BK = 32
    const uint32_t sb = smem_u32(smem);

    float acc[2][8][4];
#pragma unroll
    for (int im = 0; im < 2; ++im)
#pragma unroll
        for (int j = 0; j < 8; ++j)
#pragma unroll
            for (int q = 0; q < 4; ++q) acc[im][j][q] = 0.f;

    auto load_stage = [&](int c, int s) {
        uint32_t base = sb + (uint32_t)s * STAGEB;
        const size_t kc = (size_t)c * 32;
#pragma unroll
        for (int i = tid; i < 512; i += 256) {
            int r = i >> 2, seg = i & 3;
            uint32_t off = (uint32_t)(r * TSTRIDE + seg * 16);
            const size_t ga = (size_t)(m0 + r) * K + kc + seg * 8;
            cpa16(base + off, Ah + ga);
            cpa16(base + TILEB + off, Al + ga);
            int rn = n0 + r;
            if (rn >= N) rn = N - 1;
            const size_t gb = (size_t)rn * K + kc + seg * 8;
            cpa16(base + 2 * TILEB + off, Bh + gb);
            cpa16(base + 3 * TILEB + off, Bl + gb);
        }
        cpa_commit();
    };

    load_stage(0, 0);
    for (int c = 0; c < NC; ++c) {
        if (c + 1 < NC) {
            load_stage(c + 1, (c + 1) & 1);
            cpa_wait<1>();
        } else {
            cpa_wait<0>();
        }
        __syncthreads();

        const uint32_t base = sb + (uint32_t)(c & 1) * STAGEB;
#pragma unroll
        for (int ks = 0; ks < 2; ++ks) {
            const uint32_t kb = ks * 32;   // byte offset of 16 bf16
            uint32_t ah[2][4], al[2][4], bh[4][4], bl[4][4];
#pragma unroll
            for (int im = 0; im < 2; ++im) {
                uint32_t ra = (uint32_t)((wm * 32 + im * 16 + (lane & 15)) * TSTRIDE)
                              + kb + ((lane >> 4) & 1) * 16;
                ldsm4(ah[im], base + ra);
                ldsm4(al[im], base + TILEB + ra);
            }
#pragma unroll
            for (int p = 0; p < 4; ++p) {
                uint32_t rb = (uint32_t)((wn * 64 + p * 16 + ((lane >> 4) & 1) * 8 +
                                          (lane & 7)) * TSTRIDE)
                              + kb + ((lane >> 3) & 1) * 16;
                ldsm4(bh[p], base + 2 * TILEB + rb);
                ldsm4(bl[p], base + 3 * TILEB + rb);
            }
#pragma unroll
            for (int im = 0; im < 2; ++im)
#pragma unroll
                for (int j = 0; j < 8; ++j) {
                    const uint32_t* pbh = &bh[j >> 1][(j & 1) * 2];
                    const uint32_t* pbl = &bl[j >> 1][(j & 1) * 2];
                    mma16816(acc[im][j], ah[im], pbh);
                    mma16816(acc[im][j], ah[im], pbl);
                    mma16816(acc[im][j], al[im], pbh);
                }
        }
        __syncthreads();
    }

    // epilogue: direct global stores (float2 per pair)
#pragma unroll
    for (int im = 0; im < 2; ++im)
#pragma unroll
        for (int j = 0; j < 8; ++j) {
            int gm = m0 + wm * 32 + im * 16 + (lane >> 2);
            int gn = n0 + wn * 64 + j * 8 + (lane & 3) * 2;
            if (gn < N) {
                *(float2*)&C[(size_t)gm * N + gn] =
                    make_float2(acc[im][j][0], acc[im][j][1]);
                *(float2*)&C[(size_t)(gm + 8) * N + gn] =
                    make_float2(acc[im][j][2], acc[im][j][3]);
            }
        }
}

// ------------------------------ attention dots: layer 1 ----------------------
__global__ __launch_bounds__(256)
void k_alpha1(const float* __restrict__ att_s, const float* __restrict__ att_d) {
    int w = blockIdx.x * 8 + (threadIdx.x >> 5);
    int lane = threadIdx.x & 31;
    int n = w >> 6, head = w & 63;
    const float* hp = g_h1 + (size_t)n * F1 + head * HID;
    float h0 = hp[lane], h1v = hp[lane + 32];
    float s = h0 * att_s[head * HID + lane] + h1v * att_s[head * HID + lane + 32];
    float d = h0 * att_d[head * HID + lane] + h1v * att_d[head * HID + lane + 32];
#pragma unroll
    for (int o = 16; o > 0; o >>= 1) {
        s += __shfl_down_sync(0xffffffffu, s, o);
        d += __shfl_down_sync(0xffffffffu, d, o);
    }
    if (!lane) { g_as1[n * H1 + head] = s; g_ad1[n * H1 + head] = d; }
}

// ------------------------------ layer-1 aggregation + ELU + bf16 split -------
__global__ __launch_bounds__(256)
void k_agg1(const float* __restrict__ b1) {
    const int n = blockIdx.x;
    const int t = threadIdx.x;
    const int start = g_off[n];
    const int deg = g_off[n + 1] - start;

    __shared__ float sh_m[H1], sh_den[H1], sh_ad[H1];
    __shared__ float sh_w[32 * H1];
    __shared__ int   s_src[32];

    if (t < H1) {
        float adv = g_ad1[n * H1 + t];
        float m = -1e30f;
        for (int e = 0; e < deg; e++) {
            int s = g_csr_src[start + e];
            float l = g_as1[s * H1 + t] + adv;
            l = l > 0.f ? l : 0.2f * l;
            m = fmaxf(m, l);
        }
        float den = 0.f;
        for (int e = 0; e < deg; e++) {
            int s = g_csr_src[start + e];
            float l = g_as1[s * H1 + t] + adv;
            l = l > 0.f ? l : 0.2f * l;
            den += __expf(l - m);
        }
        sh_m[t] = m; sh_den[t] = den; sh_ad[t] = adv;
    }
    __syncthreads();

    float acc[16];
#pragma unroll
    for (int i = 0; i < 16; i++) acc[i] = 0.f;
    const int h = t >> 2;  // head of this thread's 16-feature slice

    for (int e0 = 0; e0 < deg; e0 += 32) {
        int ce = min(32, deg - e0);
        if (t < ce) s_src[t] = g_csr_src[start + e0 + t];
        __syncthreads();
        for (int k = t; k < ce * H1; k += 256) {
            int e = k >> 6, hh = k & 63;
            float l = g_as1[s_src[e] * H1 + hh] + sh_ad[hh];
            l = l > 0.f ? l : 0.2f * l;
            sh_w[k] = __expf(l - sh_m[hh]);
        }
        __syncthreads();
        for (int e = 0; e < ce; e++) {
            const float4* hp = reinterpret_cast<const float4*>(
                g_h1 + (size_t)s_src[e] * F1 + t * 16);
            float wv = sh_w[(e << 6) + h];
#pragma unroll
            for (int q = 0; q < 4; q++) {
                float4 v = hp[q];
                acc[4 * q + 0] += wv * v.x;
                acc[4 * q + 1] += wv * v.y;
                acc[4 * q + 2] += wv * v.z;
                acc[4 * q + 3] += wv * v.w;
            }
        }
        __syncthreads();
    }

    float invden = 1.f / sh_den[h];
    const float4* bp = reinterpret_cast<const float4*>(b1 + t * 16);
    float vals[16];
#pragma unroll
    for (int q = 0; q < 4; q++) {
        float4 bv = bp[q];
        float v0 = acc[4 * q + 0] * invden + bv.x;
        float v1 = acc[4 * q + 1] * invden + bv.y;
        float v2 = acc[4 * q + 2] * invden + bv.z;
        float v3 = acc[4 * q + 3] * invden + bv.w;
        vals[4 * q + 0] = v0 > 0.f ? v0 : __expf(v0) - 1.f;
        vals[4 * q + 1] = v1 > 0.f ? v1 : __expf(v1) - 1.f;
        vals[4 * q + 2] = v2 > 0.f ? v2 : __expf(v2) - 1.f;
        vals[4 * q + 3] = v3 > 0.f ? v3 : __expf(v3) - 1.f;
    }
    // split to bf16 hi/lo, pack pairs, write as uint4
    uint32_t ph[8], pl[8];
#pragma unroll
    for (int i = 0; i < 8; i++) {
        float a = vals[2 * i], b = vals[2 * i + 1];
        __nv_bfloat16 ahh = __float2bfloat16_rn(a);
        __nv_bfloat16 bhh = __float2bfloat16_rn(b);
        __nv_bfloat16 alo = __float2bfloat16_rn(a - __bfloat162float(ahh));
        __nv_bfloat16 blo = __float2bfloat16_rn(b - __bfloat162float(bhh));
        __nv_bfloat162 hp2 = {ahh, bhh};
        __nv_bfloat162 lp2 = {alo, blo};
        ph[i] = *reinterpret_cast<uint32_t*>(&hp2);
        pl[i] = *reinterpret_cast<uint32_t*>(&lp2);
    }
    size_t off = (size_t)n * F1 + t * 16;
    uint4* oh = reinterpret_cast<uint4*>(g_x1h + off);
    uint4* ol = reinterpret_cast<uint4*>(g_x1l + off);
    oh[0] = make_uint4(ph[0], ph[1], ph[2], ph[3]);
    oh[1] = make_uint4(ph[4], ph[5], ph[6], ph[7]);
    ol[0] = make_uint4(pl[0], pl[1], pl[2], pl[3]);
    ol[1] = make_uint4(pl[4], pl[5], pl[6], pl[7]);
}

// ------------------------------ attention dots: layer 2 ----------------------
__global__ __launch_bounds__(256)
void k_alpha2(const float* __restrict__ att_s, const float* __restrict__ att_d) {
    int n = blockIdx.x * 8 + (threadIdx.x >> 5);
    int lane = threadIdx.x & 31;
    if (n >= N_NODES) return;
    const float* hp = g_h2 + (size_t)n * F2;
#pragma unroll
    for (int hh = 0; hh < H2; hh++) {
        float v = hp[hh * OUTF + lane];
        float s = v * att_s[hh * OUTF + lane];
        float d = v * att_d[hh * OUTF + lane];
#pragma unroll
        for (int o = 16; o > 0; o >>= 1) {
            s += __shfl_down_sync(0xffffffffu, s, o);
            d += __shfl_down_sync(0xffffffffu, d, o);
        }
        if (!lane) { g_as2[n * H2 + hh] = s; g_ad2[n * H2 + hh] = d; }
    }
}

// ------------------------------ layer-2 aggregation + head mean --------------
__global__ __launch_bounds__(192)
void k_agg2(const float* __restrict__ b2) {
    const int n = blockIdx.x;
    const int t = threadIdx.x;
    const int start = g_off[n];
    const int deg = g_off[n + 1] - start;

    __shared__ float sh_m[H2], sh_den[H2], sh_ad[H2];
    __shared__ float sh_r[F2];

    if (t < H2) {
        float adv = g_ad2[n * H2 + t];
        float m = -1e30f;
        for (int e = 0; e < deg; e++) {
            int s = g_csr_src[start + e];
            float l = g_as2[s * H2 + t] + adv;
            l = l > 0.f ? l : 0.2f * l;
            m = fmaxf(m, l);
        }
        float den = 0.f;
        for (int e = 0; e < deg; e++) {
            int s = g_csr_src[start + e];
            float l = g_as2[s * H2 + t] + adv;
            l = l > 0.f ? l : 0.2f * l;
            den += __expf(l - m);
        }
        sh_m[t] = m; sh_den[t] = den; sh_ad[t] = adv;
    }
    __syncthreads();

    if (t < F2) {
        int hh = t >> 5;
        float m = sh_m[hh], adv = sh_ad[hh];
        float acc = 0.f;
        for (int e = 0; e < deg; e++) {
            int s = g_csr_src[start + e];
            float l = g_as2[s * H2 + hh] + adv;
            l = l > 0.f ? l : 0.2f * l;
            acc += __expf(l - m) * g_h2[s * F2 + t];
        }
        sh_r[t] = acc / sh_den[hh];
    }
    __syncthreads();

    if (t < OUTF) {
        float v = (sh_r[t] + sh_r[32 + t] + sh_r[64 + t] + sh_r[96 + t] +
                   sh_r[128 + t]) * 0.2f + b2[t];
        g_x2[n * OUTF + t] = v;
    }
}

// ------------------------------ bond scores + softmax ------------------------
__global__ void k_score(const int* __restrict__ lefts,
                        const int* __restrict__ rights,
                        float* __restrict__ out) {
    __shared__ float sm[NB];
    int t = threadIdx.x;
    int l = lefts[t], r = rights[t];
    float s = 0.f;
#pragma unroll
    for (int c = 0; c < OUTF; c++) s += g_x2[l * OUTF + c] + g_x2[r * OUTF + c];
    sm[t] = s;
    __syncthreads();
    float mx = -1e30f;
    for (int j = 0; j < NB; j++) mx = fmaxf(mx, sm[j]);
    float e = __expf(s - mx);
    __syncthreads();
    sm[t] = e;
    __syncthreads();
    float sum = 0.f;
    for (int j = 0; j < NB; j++) sum += sm[j];
    out[t] = e / sum;
}

// ------------------------------ launch ---------------------------------------
extern "C" void kernel_launch(void* const* d_in, const int* in_sizes, int n_in,
                              void* d_out, int out_size) {
    const float* x   = (const float*)d_in[0];
    const int*   ei  = (const int*)d_in[1];
    const int*   lf  = (const int*)d_in[2];
    const int*   rt  = (const int*)d_in[3];
    const float* W1  = (const float*)d_in[4];
    const float* as1 = (const float*)d_in[5];
    const float* ad1 = (const float*)d_in[6];
    const float* b1  = (const float*)d_in[7];
    const float* W2  = (const float*)d_in[8];
    const float* as2 = (const float*)d_in[9];
    const float* ad2 = (const float*)d_in[10];
    const float* b2  = (const float*)d_in[11];
    float* out = (float*)d_out;

    cudaFuncSetAttribute(gemm_mma, cudaFuncAttributeMaxDynamicSharedMemorySize,
                         GEMM_SMEM);

    void *p_xh, *p_xl, *p_w1h, *p_w1l, *p_w2h, *p_w2l;
    void *p_h1, *p_h2, *p_x1h, *p_x1l;
    cudaGetSymbolAddress(&p_xh, g_xh);
    cudaGetSymbolAddress(&p_xl, g_xl);
    cudaGetSymbolAddress(&p_w1h, g_w1h);
    cudaGetSymbolAddress(&p_w1l, g_w1l);
    cudaGetSymbolAddress(&p_w2h, g_w2h);
    cudaGetSymbolAddress(&p_w2l, g_w2l);
    cudaGetSymbolAddress(&p_h1, g_h1);
    cudaGetSymbolAddress(&p_h2, g_h2);
    cudaGetSymbolAddress(&p_x1h, g_x1h);
    cudaGetSymbolAddress(&p_x1l, g_x1l);

    // input conversions
    k_split<<<(N_NODES * IN_F + 255) / 256, 256>>>(
        x, (__nv_bfloat16*)p_xh, (__nv_bfloat16*)p_xl, N_NODES * IN_F);
    k_split<<<(F1 * IN_F + 255) / 256, 256>>>(
        W1, (__nv_bfloat16*)p_w1h, (__nv_bfloat16*)p_w1l, F1 * IN_F);
    k_split<<<(F2 * F1 + 255) / 256, 256>>>(
        W2, (__nv_bfloat16*)p_w2h, (__nv_bfloat16*)p_w2l, F2 * F1);

    // CSR by destination (self-loops included)
    k_init_counts<<<(N_NODES + 255) / 256, 256>>>();
    k_count<<<(NE + 255) / 256, 256>>>(ei);
    k_scan<<<1, 1024>>>();
    k_scatter<<<(ETOT + 255) / 256, 256>>>(ei);

    // layer 1: h1 = x @ W1^T   [8192 x 4096]
    gemm_mma<<<dim3(F1 / 128, N_NODES / 128), 256, GEMM_SMEM>>>(
        (const __nv_bfloat16*)p_xh, (const __nv_bfloat16*)p_xl,
        (const __nv_bfloat16*)p_w1h, (const __nv_bfloat16*)p_w1l,
        (float*)p_h1, F1, IN_F);
    k_alpha1<<<(N_NODES * H1) / 8, 256>>>(as1, ad1);
    k_agg1<<<N_NODES, 256>>>(b1);

    // layer 2: h2 = x1 @ W2^T  [8192 x 160]
    gemm_mma<<<dim3(2, N_NODES / 128), 256, GEMM_SMEM>>>(
        (const __nv_bfloat16*)p_x1h, (const __nv_bfloat16*)p_x1l,
        (const __nv_bfloat16*)p_w2h, (const __nv_bfloat16*)p_w2l,
        (float*)p_h2, F2, F1);
    k_alpha2<<<N_NODES / 8, 256>>>(as2, ad2);
    k_agg2<<<N_NODES, 192>>>(b2);

    // bonds
    k_score<<<1, NB>>>(lf, rt, out);
}

// round 5
// speedup vs baseline: 4.4237x; 2.0634x over previous
#include <cuda_runtime.h>
#include <cuda_bf16.h>
#include <cuda_fp16.h>
#include <stdint.h>
#include <math.h>

#define N_NODES 8192
#define NE      49152
#define ETOT    (NE + N_NODES)       // 57344
#define IN_F    128
#define H1      64
#define HID     64
#define F1      (H1*HID)             // 4096
#define H2      5
#define OUTF    32
#define F2      (H2*OUTF)            // 160
#define NB      64
#define KSPLIT  8
#define KSLC    (F1 / KSPLIT)        // 512

// ------------------------------ scratch (static, no allocation) --------------
__device__ __half g_h1[(size_t)N_NODES * F1];                // 67 MB (L2-resident)
__device__ __nv_bfloat16 g_x1h[(size_t)N_NODES * F1];        // 67 MB
__device__ __nv_bfloat16 g_x1l[(size_t)N_NODES * F1];        // 67 MB
__device__ __nv_bfloat16 g_xh[N_NODES * IN_F];
__device__ __nv_bfloat16 g_xl[N_NODES * IN_F];
__device__ __nv_bfloat16 g_w1h[F1 * IN_F];
__device__ __nv_bfloat16 g_w1l[F1 * IN_F];
__device__ __nv_bfloat16 g_w2h[F2 * F1];
__device__ __nv_bfloat16 g_w2l[F2 * F1];
__device__ float g_as1[N_NODES * H1];
__device__ float g_ad1[N_NODES * H1];
__device__ float g_h2p[(size_t)KSPLIT * N_NODES * F2];       // 42 MB partials
__device__ float g_h2[N_NODES * F2];
__device__ float g_as2[N_NODES * H2];
__device__ float g_ad2[N_NODES * H2];
__device__ float g_x2[N_NODES * OUTF];
__device__ int   g_counts[N_NODES];
__device__ int   g_off[N_NODES + 1];
__device__ int   g_cursor[N_NODES];
__device__ int   g_csr_src[ETOT];

// ------------------------------ PTX helpers ----------------------------------
__device__ __forceinline__ uint32_t smem_u32(const void* p) {
    uint32_t a;
    asm("{ .reg .u64 t; cvta.to.shared.u64 t, %1; cvt.u32.u64 %0, t; }"
        : "=r"(a) : "l"(p));
    return a;
}

__device__ __forceinline__ void cpa16(uint32_t d, const void* s) {
    asm volatile("cp.async.cg.shared.global [%0], [%1], 16;" :: "r"(d), "l"(s));
}
__device__ __forceinline__ void cpa_commit() {
    asm volatile("cp.async.commit_group;" ::: "memory");
}
template <int N> __device__ __forceinline__ void cpa_wait() {
    asm volatile("cp.async.wait_group %0;" :: "n"(N) : "memory");
}

__device__ __forceinline__ void ldsm4(uint32_t* r, uint32_t addr) {
    asm volatile("ldmatrix.sync.aligned.m8n8.x4.shared.b16 {%0,%1,%2,%3}, [%4];"
                 : "=r"(r[0]), "=r"(r[1]), "=r"(r[2]), "=r"(r[3]) : "r"(addr));
}

__device__ __forceinline__ void mma16816(float* c, const uint32_t* a,
                                         const uint32_t* b) {
    asm volatile(
        "mma.sync.aligned.m16n8k16.row.col.f32.bf16.bf16.f32 "
        "{%0,%1,%2,%3}, {%4,%5,%6,%7}, {%8,%9}, {%0,%1,%2,%3};"
        : "+f"(c[0]), "+f"(c[1]), "+f"(c[2]), "+f"(c[3])
        : "r"(a[0]), "r"(a[1]), "r"(a[2]), "r"(a[3]), "r"(b[0]), "r"(b[1]));
}

// ------------------------------ CSR build ------------------------------------
__global__ void k_init_counts() {
    int i = blockIdx.x * blockDim.x + threadIdx.x;
    if (i < N_NODES) g_counts[i] = 1;  // self-loop
}

__global__ void k_count(const int* __restrict__ ei) {
    int e = blockIdx.x * blockDim.x + threadIdx.x;
    if (e < NE) atomicAdd(&g_counts[ei[NE + e]], 1);
}

__global__ void k_scan() {
    __shared__ int sh[1024];
    int t = threadIdx.x;
    int loc[8];
    int s = 0;
#pragma unroll
    for (int j = 0; j < 8; j++) { loc[j] = g_counts[t * 8 + j]; s += loc[j]; }
    sh[t] = s;
    __syncthreads();
    for (int off = 1; off < 1024; off <<= 1) {
        int v = (t >= off) ? sh[t - off] : 0;
        __syncthreads();
        sh[t] += v;
        __syncthreads();
    }
    int run = (t == 0) ? 0 : sh[t - 1];
#pragma unroll
    for (int j = 0; j < 8; j++) {
        int idx = t * 8 + j;
        g_off[idx] = run;
        g_cursor[idx] = run;
        run += loc[j];
    }
    if (t == 1023) g_off[N_NODES] = run;
}

__global__ void k_scatter(const int* __restrict__ ei) {
    int i = blockIdx.x * blockDim.x + threadIdx.x;
    if (i >= ETOT) return;
    int src, dst;
    if (i < NE) { src = ei[i]; dst = ei[NE + i]; }
    else        { src = i - NE; dst = src; }
    int pos = atomicAdd(&g_cursor[dst], 1);
    g_csr_src[pos] = src;
}

// ------------------------------ fp32 -> bf16 hi/lo split ---------------------
__global__ void k_split(const float* __restrict__ in, __nv_bfloat16* __restrict__ hi,
                        __nv_bfloat16* __restrict__ lo, int n) {
    int i = blockIdx.x * blockDim.x + threadIdx.x;
    if (i < n) {
        float v = in[i];
        __nv_bfloat16 h = __float2bfloat16_rn(v);
        hi[i] = h;
        lo[i] = __float2bfloat16_rn(v - __bfloat162float(h));
    }
}

// ------------------------------ GEMM1 (mma.sync, out fp16) -------------------
// h1[M,4096] = (xh+xl)[M,128] * (W1h+W1l)[4096,128]^T, 3-term compensation.
// BM=128, BN=128, BK=32. 256 threads (8 warps, 4m x 2n). Output __half.
#define TSTRIDE 80                        // bytes per smem row (5 x 16B segs)
#define TILEB   (128 * TSTRIDE)           // 10240 B
#define STAGEB  (4 * TILEB)               // Ah, Al, Bh, Bl
#define GEMM_SMEM (2 * STAGEB)            // 81920 B

__global__ __launch_bounds__(256, 1)
void gemm1_mma(const __nv_bfloat16* __restrict__ Ah, const __nv_bfloat16* __restrict__ Al,
               const __nv_bfloat16* __restrict__ Bh, const __nv_bfloat16* __restrict__ Bl,
               __half* __restrict__ C) {
    extern __shared__ char smem[];
    const int N = F1, K = IN_F;
    const int tid = threadIdx.x;
    const int wid = tid >> 5, lane = tid & 31;
    const int m0 = blockIdx.y * 128, n0 = blockIdx.x * 128;
    const int wm = wid >> 1, wn = wid & 1;
    const int NC = K >> 5;                // 4
    const uint32_t sb = smem_u32(smem);

    float acc[2][8][4];
#pragma unroll
    for (int im = 0; im < 2; ++im)
#pragma unroll
        for (int j = 0; j < 8; ++j)
#pragma unroll
            for (int q = 0; q < 4; ++q) acc[im][j][q] = 0.f;

    auto load_stage = [&](int c, int s) {
        uint32_t base = sb + (uint32_t)s * STAGEB;
        const size_t kc = (size_t)c * 32;
#pragma unroll
        for (int i = tid; i < 512; i += 256) {
            int r = i >> 2, seg = i & 3;
            uint32_t off = (uint32_t)(r * TSTRIDE + seg * 16);
            const size_t ga = (size_t)(m0 + r) * K + kc + seg * 8;
            cpa16(base + off, Ah + ga);
            cpa16(base + TILEB + off, Al + ga);
            const size_t gb = (size_t)(n0 + r) * K + kc + seg * 8;
            cpa16(base + 2 * TILEB + off, Bh + gb);
            cpa16(base + 3 * TILEB + off, Bl + gb);
        }
        cpa_commit();
    };

    load_stage(0, 0);
    for (int c = 0; c < NC; ++c) {
        if (c + 1 < NC) {
            load_stage(c + 1, (c + 1) & 1);
            cpa_wait<1>();
        } else {
            cpa_wait<0>();
        }
        __syncthreads();

        const uint32_t base = sb + (uint32_t)(c & 1) * STAGEB;
#pragma unroll
        for (int ks = 0; ks < 2; ++ks) {
            const uint32_t kb = ks * 32;
            uint32_t ah[2][4], al[2][4], bh[4][4], bl[4][4];
#pragma unroll
            for (int im = 0; im < 2; ++im) {
                uint32_t ra = (uint32_t)((wm * 32 + im * 16 + (lane & 15)) * TSTRIDE)
                              + kb + ((lane >> 4) & 1) * 16;
                ldsm4(ah[im], base + ra);
                ldsm4(al[im], base + TILEB + ra);
            }
#pragma unroll
            for (int p = 0; p < 4; ++p) {
                uint32_t rb = (uint32_t)((wn * 64 + p * 16 + ((lane >> 4) & 1) * 8 +
                                          (lane & 7)) * TSTRIDE)
                              + kb + ((lane >> 3) & 1) * 16;
                ldsm4(bh[p], base + 2 * TILEB + rb);
                ldsm4(bl[p], base + 3 * TILEB + rb);
            }
#pragma unroll
            for (int im = 0; im < 2; ++im)
#pragma unroll
                for (int j = 0; j < 8; ++j) {
                    const uint32_t* pbh = &bh[j >> 1][(j & 1) * 2];
                    const uint32_t* pbl = &bl[j >> 1][(j & 1) * 2];
                    mma16816(acc[im][j], ah[im], pbh);
                    mma16816(acc[im][j], ah[im], pbl);
                    mma16816(acc[im][j], al[im], pbh);
                }
        }
        __syncthreads();
    }

    // epilogue: fp16 stores (pairs)
#pragma unroll
    for (int im = 0; im < 2; ++im)
#pragma unroll
        for (int j = 0; j < 8; ++j) {
            int gm = m0 + wm * 32 + im * 16 + (lane >> 2);
            int gn = n0 + wn * 64 + j * 8 + (lane & 3) * 2;
            __half2 v0 = __floats2half2_rn(acc[im][j][0], acc[im][j][1]);
            __half2 v1 = __floats2half2_rn(acc[im][j][2], acc[im][j][3]);
            *(__half2*)&C[(size_t)gm * N + gn] = v0;
            *(__half2*)&C[(size_t)(gm + 8) * N + gn] = v1;
        }
}

// ------------------------------ GEMM2 (split-K, BN=160) ----------------------
// h2_part[z][M,160] = (x1h+x1l)[M, z-slice] * (W2h+W2l)[160, z-slice]^T
// BM=128, BN=160, BK=32, KSPLIT z-blocks of 512.
#define A2TILE (128 * TSTRIDE)            // 10240
#define B2TILE (160 * TSTRIDE)            // 12800
#define STAGE2 (2 * A2TILE + 2 * B2TILE)  // 46080
#define GEMM2_SMEM (2 * STAGE2)           // 92160

__global__ __launch_bounds__(256, 1)
void gemm2_mma(const __nv_bfloat16* __restrict__ Ah, const __nv_bfloat16* __restrict__ Al,
               const __nv_bfloat16* __restrict__ Bh, const __nv_bfloat16* __restrict__ Bl,
               float* __restrict__ Cp) {
    extern __shared__ char smem[];
    const int K = F1;
    const int tid = threadIdx.x;
    const int wid = tid >> 5, lane = tid & 31;
    const int m0 = blockIdx.y * 128;
    const size_t kb0 = (size_t)blockIdx.z * KSLC;
    const int wm = wid >> 1, wn = wid & 1;
    const int NC = KSLC >> 5;             // 16
    const uint32_t sb = smem_u32(smem);

    float acc[2][10][4];
#pragma unroll
    for (int im = 0; im < 2; ++im)
#pragma unroll
        for (int j = 0; j < 10; ++j)
#pragma unroll
            for (int q = 0; q < 4; ++q) acc[im][j][q] = 0.f;

    auto load_stage = [&](int c, int s) {
        uint32_t base = sb + (uint32_t)s * STAGE2;
        const size_t kc = kb0 + (size_t)c * 32;
#pragma unroll
        for (int i = tid; i < 512; i += 256) {
            int r = i >> 2, seg = i & 3;
            uint32_t off = (uint32_t)(r * TSTRIDE + seg * 16);
            const size_t ga = (size_t)(m0 + r) * K + kc + seg * 8;
            cpa16(base + off, Ah + ga);
            cpa16(base + A2TILE + off, Al + ga);
        }
#pragma unroll
        for (int i = tid; i < 640; i += 256) {
            int r = i >> 2, seg = i & 3;
            uint32_t off = (uint32_t)(r * TSTRIDE + seg * 16);
            const size_t gb = (size_t)r * K + kc + seg * 8;
            cpa16(base + 2 * A2TILE + off, Bh + gb);
            cpa16(base + 2 * A2TILE + B2TILE + off, Bl + gb);
        }
        cpa_commit();
    };

    load_stage(0, 0);
    for (int c = 0; c < NC; ++c) {
        if (c + 1 < NC) {
            load_stage(c + 1, (c + 1) & 1);
            cpa_wait<1>();
        } else {
            cpa_wait<0>();
        }
        __syncthreads();

        const uint32_t base = sb + (uint32_t)(c & 1) * STAGE2;
#pragma unroll
        for (int ks = 0; ks < 2; ++ks) {
            const uint32_t kb = ks * 32;
            uint32_t ah[2][4], al[2][4], bh[5][4], bl[5][4];
#pragma unroll
            for (int im = 0; im < 2; ++im) {
                uint32_t ra = (uint32_t)((wm * 32 + im * 16 + (lane & 15)) * TSTRIDE)
                              + kb + ((lane >> 4) & 1) * 16;
                ldsm4(ah[im], base + ra);
                ldsm4(al[im], base + A2TILE + ra);
            }
#pragma unroll
            for (int p = 0; p < 5; ++p) {
                uint32_t rb = (uint32_t)((wn * 80 + p * 16 + ((lane >> 4) & 1) * 8 +
                                          (lane & 7)) * TSTRIDE)
                              + kb + ((lane >> 3) & 1) * 16;
                ldsm4(bh[p], base + 2 * A2TILE + rb);
                ldsm4(bl[p], base + 2 * A2TILE + B2TILE + rb);
            }
#pragma unroll
            for (int im = 0; im < 2; ++im)
#pragma unroll
                for (int j = 0; j < 10; ++j) {
                    const uint32_t* pbh = &bh[j >> 1][(j & 1) * 2];
                    const uint32_t* pbl = &bl[j >> 1][(j & 1) * 2];
                    mma16816(acc[im][j], ah[im], pbh);
                    mma16816(acc[im][j], ah[im], pbl);
                    mma16816(acc[im][j], al[im], pbh);
                }
        }
        __syncthreads();
    }

    float* out = Cp + (size_t)blockIdx.z * N_NODES * F2;
#pragma unroll
    for (int im = 0; im < 2; ++im)
#pragma unroll
        for (int j = 0; j < 10; ++j) {
            int gm = m0 + wm * 32 + im * 16 + (lane >> 2);
            int gn = wn * 80 + j * 8 + (lane & 3) * 2;
            *(float2*)&out[(size_t)gm * F2 + gn] =
                make_float2(acc[im][j][0], acc[im][j][1]);
            *(float2*)&out[(size_t)(gm + 8) * F2 + gn] =
                make_float2(acc[im][j][2], acc[im][j][3]);
        }
}

// fixed-order split-K reduction (deterministic)
__global__ void k_reduce2() {
    int i = blockIdx.x * blockDim.x + threadIdx.x;   // float4 index
    const int tot = N_NODES * F2 / 4;
    if (i >= tot) return;
    const float4* p = (const float4*)g_h2p;
    float4 s = p[i];
#pragma unroll
    for (int z = 1; z < KSPLIT; ++z) {
        float4 v = p[(size_t)z * tot + i];
        s.x += v.x; s.y += v.y; s.z += v.z; s.w += v.w;
    }
    ((float4*)g_h2)[i] = s;
}

// ------------------------------ attention dots: layer 1 ----------------------
__global__ __launch_bounds__(256)
void k_alpha1(const float* __restrict__ att_s, const float* __restrict__ att_d) {
    int w = blockIdx.x * 8 + (threadIdx.x >> 5);
    int lane = threadIdx.x & 31;
    int n = w >> 6, head = w & 63;
    const __half* hp = g_h1 + (size_t)n * F1 + head * HID;
    float h0 = __half2float(hp[lane]), h1v = __half2float(hp[lane + 32]);
    float s = h0 * att_s[head * HID + lane] + h1v * att_s[head * HID + lane + 32];
    float d = h0 * att_d[head * HID + lane] + h1v * att_d[head * HID + lane + 32];
#pragma unroll
    for (int o = 16; o > 0; o >>= 1) {
        s += __shfl_down_sync(0xffffffffu, s, o);
        d += __shfl_down_sync(0xffffffffu, d, o);
    }
    if (!lane) { g_as1[n * H1 + head] = s; g_ad1[n * H1 + head] = d; }
}

// ------------------------------ layer-1 aggregation + ELU + bf16 split -------
__global__ __launch_bounds__(256)
void k_agg1(const float* __restrict__ b1) {
    const int n = blockIdx.x;
    const int t = threadIdx.x;
    const int start = g_off[n];
    const int deg = g_off[n + 1] - start;

    __shared__ float sh_m[H1], sh_den[H1], sh_ad[H1];
    __shared__ float sh_w[32 * H1];
    __shared__ int   s_src[32];

    if (t < H1) {
        float adv = g_ad1[n * H1 + t];
        float m = -1e30f;
        for (int e = 0; e < deg; e++) {
            int s = g_csr_src[start + e];
            float l = g_as1[s * H1 + t] + adv;
            l = l > 0.f ? l : 0.2f * l;
            m = fmaxf(m, l);
        }
        float den = 0.f;
        for (int e = 0; e < deg; e++) {
            int s = g_csr_src[start + e];
            float l = g_as1[s * H1 + t] + adv;
            l = l > 0.f ? l : 0.2f * l;
            den += __expf(l - m);
        }
        sh_m[t] = m; sh_den[t] = den; sh_ad[t] = adv;
    }
    __syncthreads();

    float acc[16];
#pragma unroll
    for (int i = 0; i < 16; i++) acc[i] = 0.f;
    const int h = t >> 2;  // head of this thread's 16-feature slice

    for (int e0 = 0; e0 < deg; e0 += 32) {
        int ce = min(32, deg - e0);
        if (t < ce) s_src[t] = g_csr_src[start + e0 + t];
        __syncthreads();
        for (int k = t; k < ce * H1; k += 256) {
            int e = k >> 6, hh = k & 63;
            float l = g_as1[s_src[e] * H1 + hh] + sh_ad[hh];
            l = l > 0.f ? l : 0.2f * l;
            sh_w[k] = __expf(l - sh_m[hh]);
        }
        __syncthreads();
        for (int e = 0; e < ce; e++) {
            // 16 fp16 features = 32B = 2 x uint4
            const uint4* hp = reinterpret_cast<const uint4*>(
                g_h1 + (size_t)s_src[e] * F1 + t * 16);
            float wv = sh_w[(e << 6) + h];
#pragma unroll
            for (int q = 0; q < 2; q++) {
                uint4 u = hp[q];
                float2 f0 = __half22float2(*(const __half2*)&u.x);
                float2 f1 = __half22float2(*(const __half2*)&u.y);
                float2 f2 = __half22float2(*(const __half2*)&u.z);
                float2 f3 = __half22float2(*(const __half2*)&u.w);
                acc[8 * q + 0] += wv * f0.x;
                acc[8 * q + 1] += wv * f0.y;
                acc[8 * q + 2] += wv * f1.x;
                acc[8 * q + 3] += wv * f1.y;
                acc[8 * q + 4] += wv * f2.x;
                acc[8 * q + 5] += wv * f2.y;
                acc[8 * q + 6] += wv * f3.x;
                acc[8 * q + 7] += wv * f3.y;
            }
        }
        __syncthreads();
    }

    float invden = 1.f / sh_den[h];
    const float4* bp = reinterpret_cast<const float4*>(b1 + t * 16);
    float vals[16];
#pragma unroll
    for (int q = 0; q < 4; q++) {
        float4 bv = bp[q];
        float v0 = acc[4 * q + 0] * invden + bv.x;
        float v1 = acc[4 * q + 1] * invden + bv.y;
        float v2 = acc[4 * q + 2] * invden + bv.z;
        float v3 = acc[4 * q + 3] * invden + bv.w;
        vals[4 * q + 0] = v0 > 0.f ? v0 : __expf(v0) - 1.f;
        vals[4 * q + 1] = v1 > 0.f ? v1 : __expf(v1) - 1.f;
        vals[4 * q + 2] = v2 > 0.f ? v2 : __expf(v2) - 1.f;
        vals[4 * q + 3] = v3 > 0.f ? v3 : __expf(v3) - 1.f;
    }
    // split to bf16 hi/lo, pack pairs, write as uint4
    uint32_t ph[8], pl[8];
#pragma unroll
    for (int i = 0; i < 8; i++) {
        float a = vals[2 * i], b = vals[2 * i + 1];
        __nv_bfloat16 ahh = __float2bfloat16_rn(a);
        __nv_bfloat16 bhh = __float2bfloat16_rn(b);
        __nv_bfloat16 alo = __float2bfloat16_rn(a - __bfloat162float(ahh));
        __nv_bfloat16 blo = __float2bfloat16_rn(b - __bfloat162float(bhh));
        __nv_bfloat162 hp2 = {ahh, bhh};
        __nv_bfloat162 lp2 = {alo, blo};
        ph[i] = *reinterpret_cast<uint32_t*>(&hp2);
        pl[i] = *reinterpret_cast<uint32_t*>(&lp2);
    }
    size_t off = (size_t)n * F1 + t * 16;
    uint4* oh = reinterpret_cast<uint4*>(g_x1h + off);
    uint4* ol = reinterpret_cast<uint4*>(g_x1l + off);
    oh[0] = make_uint4(ph[0], ph[1], ph[2], ph[3]);
    oh[1] = make_uint4(ph[4], ph[5], ph[6], ph[7]);
    ol[0] = make_uint4(pl[0], pl[1], pl[2], pl[3]);
    ol[1] = make_uint4(pl[4], pl[5], pl[6], pl[7]);
}

// ------------------------------ attention dots: layer 2 ----------------------
__global__ __launch_bounds__(256)
void k_alpha2(const float* __restrict__ att_s, const float* __restrict__ att_d) {
    int n = blockIdx.x * 8 + (threadIdx.x >> 5);
    int lane = threadIdx.x & 31;
    if (n >= N_NODES) return;
    const float* hp = g_h2 + (size_t)n * F2;
#pragma unroll
    for (int hh = 0; hh < H2; hh++) {
        float v = hp[hh * OUTF + lane];
        float s = v * att_s[hh * OUTF + lane];
        float d = v * att_d[hh * OUTF + lane];
#pragma unroll
        for (int o = 16; o > 0; o >>= 1) {
            s += __shfl_down_sync(0xffffffffu, s, o);
            d += __shfl_down_sync(0xffffffffu, d, o);
        }
        if (!lane) { g_as2[n * H2 + hh] = s; g_ad2[n * H2 + hh] = d; }
    }
}

// ------------------------------ layer-2 aggregation + head mean --------------
__global__ __launch_bounds__(192)
void k_agg2(const float* __restrict__ b2) {
    const int n = blockIdx.x;
    const int t = threadIdx.x;
    const int start = g_off[n];
    const int deg = g_off[n + 1] - start;

    __shared__ float sh_m[H2], sh_den[H2], sh_ad[H2];
    __shared__ float sh_r[F2];

    if (t < H2) {
        float adv = g_ad2[n * H2 + t];
        float m = -1e30f;
        for (int e = 0; e < deg; e++) {
            int s = g_csr_src[start + e];
            float l = g_as2[s * H2 + t] + adv;
            l = l > 0.f ? l : 0.2f * l;
            m = fmaxf(m, l);
        }
        float den = 0.f;
        for (int e = 0; e < deg; e++) {
            int s = g_csr_src[start + e];
            float l = g_as2[s * H2 + t] + adv;
            l = l > 0.f ? l : 0.2f * l;
            den += __expf(l - m);
        }
        sh_m[t] = m; sh_den[t] = den; sh_ad[t] = adv;
    }
    __syncthreads();

    if (t < F2) {
        int hh = t >> 5;
        float m = sh_m[hh], adv = sh_ad[hh];
        float acc = 0.f;
        for (int e = 0; e < deg; e++) {
            int s = g_csr_src[start + e];
            float l = g_as2[s * H2 + hh] + adv;
            l = l > 0.f ? l : 0.2f * l;
            acc += __expf(l - m) * g_h2[s * F2 + t];
        }
        sh_r[t] = acc / sh_den[hh];
    }
    __syncthreads();

    if (t < OUTF) {
        float v = (sh_r[t] + sh_r[32 + t] + sh_r[64 + t] + sh_r[96 + t] +
                   sh_r[128 + t]) * 0.2f + b2[t];
        g_x2[n * OUTF + t] = v;
    }
}

// ------------------------------ bond scores + softmax ------------------------
__global__ void k_score(const int* __restrict__ lefts,
                        const int* __restrict__ rights,
                        float* __restrict__ out) {
    __shared__ float sm[NB];
    int t = threadIdx.x;
    int l = lefts[t], r = rights[t];
    float s = 0.f;
#pragma unroll
    for (int c = 0; c < OUTF; c++) s += g_x2[l * OUTF + c] + g_x2[r * OUTF + c];
    sm[t] = s;
    __syncthreads();
    float mx = -1e30f;
    for (int j = 0; j < NB; j++) mx = fmaxf(mx, sm[j]);
    float e = __expf(s - mx);
    __syncthreads();
    sm[t] = e;
    __syncthreads();
    float sum = 0.f;
    for (int j = 0; j < NB; j++) sum += sm[j];
    out[t] = e / sum;
}

// ------------------------------ launch ---------------------------------------
extern "C" void kernel_launch(void* const* d_in, const int* in_sizes, int n_in,
                              void* d_out, int out_size) {
    const float* x   = (const float*)d_in[0];
    const int*   ei  = (const int*)d_in[1];
    const int*   lf  = (const int*)d_in[2];
    const int*   rt  = (const int*)d_in[3];
    const float* W1  = (const float*)d_in[4];
    const float* as1 = (const float*)d_in[5];
    const float* ad1 = (const float*)d_in[6];
    const float* b1  = (const float*)d_in[7];
    const float* W2  = (const float*)d_in[8];
    const float* as2 = (const float*)d_in[9];
    const float* ad2 = (const float*)d_in[10];
    const float* b2  = (const float*)d_in[11];
    float* out = (float*)d_out;

    cudaFuncSetAttribute(gemm1_mma, cudaFuncAttributeMaxDynamicSharedMemorySize,
                         GEMM_SMEM);
    cudaFuncSetAttribute(gemm2_mma, cudaFuncAttributeMaxDynamicSharedMemorySize,
                         GEMM2_SMEM);

    void *p_xh, *p_xl, *p_w1h, *p_w1l, *p_w2h, *p_w2l;
    void *p_h1, *p_h2p, *p_x1h, *p_x1l;
    cudaGetSymbolAddress(&p_xh, g_xh);
    cudaGetSymbolAddress(&p_xl, g_xl);
    cudaGetSymbolAddress(&p_w1h, g_w1h);
    cudaGetSymbolAddress(&p_w1l, g_w1l);
    cudaGetSymbolAddress(&p_w2h, g_w2h);
    cudaGetSymbolAddress(&p_w2l, g_w2l);
    cudaGetSymbolAddress(&p_h1, g_h1);
    cudaGetSymbolAddress(&p_h2p, g_h2p);
    cudaGetSymbolAddress(&p_x1h, g_x1h);
    cudaGetSymbolAddress(&p_x1l, g_x1l);

    // input conversions
    k_split<<<(N_NODES * IN_F + 255) / 256, 256>>>(
        x, (__nv_bfloat16*)p_xh, (__nv_bfloat16*)p_xl, N_NODES * IN_F);
    k_split<<<(F1 * IN_F + 255) / 256, 256>>>(
        W1, (__nv_bfloat16*)p_w1h, (__nv_bfloat16*)p_w1l, F1 * IN_F);
    k_split<<<(F2 * F1 + 255) / 256, 256>>>(
        W2, (__nv_bfloat16*)p_w2h, (__nv_bfloat16*)p_w2l, F2 * F1);

    // CSR by destination (self-loops included)
    k_init_counts<<<(N_NODES + 255) / 256, 256>>>();
    k_count<<<(NE + 255) / 256, 256>>>(ei);
    k_scan<<<1, 1024>>>();
    k_scatter<<<(ETOT + 255) / 256, 256>>>(ei);

    // layer 1: h1 = x @ W1^T   [8192 x 4096], fp16 out
    gemm1_mma<<<dim3(F1 / 128, N_NODES / 128), 256, GEMM_SMEM>>>(
        (const __nv_bfloat16*)p_xh, (const __nv_bfloat16*)p_xl,
        (const __nv_bfloat16*)p_w1h, (const __nv_bfloat16*)p_w1l,
        (__half*)p_h1);
    k_alpha1<<<(N_NODES * H1) / 8, 256>>>(as1, ad1);
    k_agg1<<<N_NODES, 256>>>(b1);

    // layer 2: h2 = x1 @ W2^T  [8192 x 160], split-K x8 + reduce
    gemm2_mma<<<dim3(1, N_NODES / 128, KSPLIT), 256, GEMM2_SMEM>>>(
        (const __nv_bfloat16*)p_x1h, (const __nv_bfloat16*)p_x1l,
        (const __nv_bfloat16*)p_w2h, (const __nv_bfloat16*)p_w2l,
        (float*)p_h2p);
    k_reduce2<<<(N_NODES * F2 / 4 + 255) / 256, 256>>>();
    k_alpha2<<<N_NODES / 8, 256>>>(as2, ad2);
    k_agg2<<<N_NODES, 192>>>(b2);

    // bonds
    k_score<<<1, NB>>>(lf, rt, out);
}

// round 6
// speedup vs baseline: 5.0193x; 1.1346x over previous
#include <cuda_runtime.h>
#include <cuda_bf16.h>
#include <cuda_fp16.h>
#include <stdint.h>
#include <math.h>

#define N_NODES 8192
#define NE      49152
#define ETOT    (NE + N_NODES)       // 57344
#define IN_F    128
#define H1      64
#define HID     64
#define F1      (H1*HID)             // 4096
#define H2      5
#define OUTF    32
#define F2      (H2*OUTF)            // 160
#define NB      64
#define KSPLIT  8
#define KSLC    (F1 / KSPLIT)        // 512

// ------------------------------ scratch (static, no allocation) --------------
__device__ __half g_h1[(size_t)N_NODES * F1];                // 67 MB (L2-resident)
__device__ __nv_bfloat16 g_x1h[(size_t)N_NODES * F1];        // 67 MB
__device__ __nv_bfloat16 g_x1l[(size_t)N_NODES * F1];        // 67 MB
__device__ __nv_bfloat16 g_xh[N_NODES * IN_F];
__device__ __nv_bfloat16 g_xl[N_NODES * IN_F];
__device__ __nv_bfloat16 g_w1h[F1 * IN_F];
__device__ __nv_bfloat16 g_w1l[F1 * IN_F];
__device__ __nv_bfloat16 g_w2h[F2 * F1];
__device__ __nv_bfloat16 g_w2l[F2 * F1];
__device__ float g_as1[N_NODES * H1];
__device__ float g_ad1[N_NODES * H1];
__device__ float g_h2p[(size_t)KSPLIT * N_NODES * F2];       // 42 MB partials
__device__ float g_h2[N_NODES * F2];
__device__ float g_as2[N_NODES * H2];
__device__ float g_ad2[N_NODES * H2];
__device__ float g_x2[N_NODES * OUTF];
__device__ int   g_counts[N_NODES];
__device__ int   g_off[N_NODES + 1];
__device__ int   g_cursor[N_NODES];
__device__ int   g_csr_src[ETOT];

// ------------------------------ PTX helpers ----------------------------------
__device__ __forceinline__ uint32_t smem_u32(const void* p) {
    uint32_t a;
    asm("{ .reg .u64 t; cvta.to.shared.u64 t, %1; cvt.u32.u64 %0, t; }"
        : "=r"(a) : "l"(p));
    return a;
}

__device__ __forceinline__ void cpa16(uint32_t d, const void* s) {
    asm volatile("cp.async.cg.shared.global [%0], [%1], 16;" :: "r"(d), "l"(s));
}
__device__ __forceinline__ void cpa_commit() {
    asm volatile("cp.async.commit_group;" ::: "memory");
}
template <int N> __device__ __forceinline__ void cpa_wait() {
    asm volatile("cp.async.wait_group %0;" :: "n"(N) : "memory");
}

__device__ __forceinline__ void ldsm4(uint32_t* r, uint32_t addr) {
    asm volatile("ldmatrix.sync.aligned.m8n8.x4.shared.b16 {%0,%1,%2,%3}, [%4];"
                 : "=r"(r[0]), "=r"(r[1]), "=r"(r[2]), "=r"(r[3]) : "r"(addr));
}

__device__ __forceinline__ void mma16816(float* c, const uint32_t* a,
                                         const uint32_t* b) {
    asm volatile(
        "mma.sync.aligned.m16n8k16.row.col.f32.bf16.bf16.f32 "
        "{%0,%1,%2,%3}, {%4,%5,%6,%7}, {%8,%9}, {%0,%1,%2,%3};"
        : "+f"(c[0]), "+f"(c[1]), "+f"(c[2]), "+f"(c[3])
        : "r"(a[0]), "r"(a[1]), "r"(a[2]), "r"(a[3]), "r"(b[0]), "r"(b[1]));
}

// ------------------ fused input split (x, W1, W2) + counts init --------------
#define NXE (N_NODES * IN_F)     // 1048576
#define NW1 (F1 * IN_F)          // 524288
#define NW2 (F2 * F1)            // 655360
#define NSPLIT (NXE + NW1 + NW2)

__global__ void k_prep(const float* __restrict__ x, const float* __restrict__ W1,
                       const float* __restrict__ W2) {
    int i = blockIdx.x * blockDim.x + threadIdx.x;
    if (i < N_NODES) g_counts[i] = 1;  // self-loop
    const float* src;
    __nv_bfloat16 *hi, *lo;
    int k;
    if (i < NXE)            { src = x;  hi = g_xh;  lo = g_xl;  k = i; }
    else if (i < NXE + NW1) { src = W1; hi = g_w1h; lo = g_w1l; k = i - NXE; }
    else if (i < NSPLIT)    { src = W2; hi = g_w2h; lo = g_w2l; k = i - NXE - NW1; }
    else return;
    float v = src[k];
    __nv_bfloat16 h = __float2bfloat16_rn(v);
    hi[k] = h;
    lo[k] = __float2bfloat16_rn(v - __bfloat162float(h));
}

// ------------------------------ CSR build ------------------------------------
__global__ void k_count(const int* __restrict__ ei) {
    int e = blockIdx.x * blockDim.x + threadIdx.x;
    if (e < NE) atomicAdd(&g_counts[ei[NE + e]], 1);
}

__global__ void k_scan() {
    __shared__ int sh[1024];
    int t = threadIdx.x;
    int loc[8];
    int s = 0;
#pragma unroll
    for (int j = 0; j < 8; j++) { loc[j] = g_counts[t * 8 + j]; s += loc[j]; }
    sh[t] = s;
    __syncthreads();
    for (int off = 1; off < 1024; off <<= 1) {
        int v = (t >= off) ? sh[t - off] : 0;
        __syncthreads();
        sh[t] += v;
        __syncthreads();
    }
    int run = (t == 0) ? 0 : sh[t - 1];
#pragma unroll
    for (int j = 0; j < 8; j++) {
        int idx = t * 8 + j;
        g_off[idx] = run;
        g_cursor[idx] = run;
        run += loc[j];
    }
    if (t == 1023) g_off[N_NODES] = run;
}

__global__ void k_scatter(const int* __restrict__ ei) {
    int i = blockIdx.x * blockDim.x + threadIdx.x;
    if (i >= ETOT) return;
    int src, dst;
    if (i < NE) { src = ei[i]; dst = ei[NE + i]; }
    else        { src = i - NE; dst = src; }
    int pos = atomicAdd(&g_cursor[dst], 1);
    g_csr_src[pos] = src;
}

// ------------------------------ GEMM1 (mma.sync, out fp16 + fused alpha) -----
// h1[M,4096] = (xh+xl)[M,128] * (W1h+W1l)[4096,128]^T, 3-term compensation.
// BM=128, BN=128, BK=32. 256 threads (8 warps, 4m x 2n). Output __half.
// Epilogue also emits as1/ad1 = h1 . att_{src,dst} per (node, head).
#define TSTRIDE 80                        // bytes per smem row (5 x 16B segs)
#define TILEB   (128 * TSTRIDE)           // 10240 B
#define STAGEB  (4 * TILEB)               // Ah, Al, Bh, Bl
#define GEMM_SMEM (2 * STAGEB)            // 81920 B

__global__ __launch_bounds__(256, 1)
void gemm1_mma(const __nv_bfloat16* __restrict__ Ah, const __nv_bfloat16* __restrict__ Al,
               const __nv_bfloat16* __restrict__ Bh, const __nv_bfloat16* __restrict__ Bl,
               __half* __restrict__ C,
               const float* __restrict__ att_s, const float* __restrict__ att_d) {
    extern __shared__ char smem[];
    const int N = F1, K = IN_F;
    const int tid = threadIdx.x;
    const int wid = tid >> 5, lane = tid & 31;
    const int m0 = blockIdx.y * 128, n0 = blockIdx.x * 128;
    const int wm = wid >> 1, wn = wid & 1;
    const int NC = K >> 5;                // 4
    const uint32_t sb = smem_u32(smem);

    float acc[2][8][4];
#pragma unroll
    for (int im = 0; im < 2; ++im)
#pragma unroll
        for (int j = 0; j < 8; ++j)
#pragma unroll
            for (int q = 0; q < 4; ++q) acc[im][j][q] = 0.f;

    auto load_stage = [&](int c, int s) {
        uint32_t base = sb + (uint32_t)s * STAGEB;
        const size_t kc = (size_t)c * 32;
#pragma unroll
        for (int i = tid; i < 512; i += 256) {
            int r = i >> 2, seg = i & 3;
            uint32_t off = (uint32_t)(r * TSTRIDE + seg * 16);
            const size_t ga = (size_t)(m0 + r) * K + kc + seg * 8;
            cpa16(base + off, Ah + ga);
            cpa16(base + TILEB + off, Al + ga);
            const size_t gb = (size_t)(n0 + r) * K + kc + seg * 8;
            cpa16(base + 2 * TILEB + off, Bh + gb);
            cpa16(base + 3 * TILEB + off, Bl + gb);
        }
        cpa_commit();
    };

    load_stage(0, 0);
    for (int c = 0; c < NC; ++c) {
        if (c + 1 < NC) {
            load_stage(c + 1, (c + 1) & 1);
            cpa_wait<1>();
        } else {
            cpa_wait<0>();
        }
        __syncthreads();

        const uint32_t base = sb + (uint32_t)(c & 1) * STAGEB;
#pragma unroll
        for (int ks = 0; ks < 2; ++ks) {
            const uint32_t kb = ks * 32;
            uint32_t ah[2][4], al[2][4], bh[4][4], bl[4][4];
#pragma unroll
            for (int im = 0; im < 2; ++im) {
                uint32_t ra = (uint32_t)((wm * 32 + im * 16 + (lane & 15)) * TSTRIDE)
                              + kb + ((lane >> 4) & 1) * 16;
                ldsm4(ah[im], base + ra);
                ldsm4(al[im], base + TILEB + ra);
            }
#pragma unroll
            for (int p = 0; p < 4; ++p) {
                uint32_t rb = (uint32_t)((wn * 64 + p * 16 + ((lane >> 4) & 1) * 8 +
                                          (lane & 7)) * TSTRIDE)
                              + kb + ((lane >> 3) & 1) * 16;
                ldsm4(bh[p], base + 2 * TILEB + rb);
                ldsm4(bl[p], base + 3 * TILEB + rb);
            }
#pragma unroll
            for (int im = 0; im < 2; ++im)
#pragma unroll
                for (int j = 0; j < 8; ++j) {
                    const uint32_t* pbh = &bh[j >> 1][(j & 1) * 2];
                    const uint32_t* pbl = &bl[j >> 1][(j & 1) * 2];
                    mma16816(acc[im][j], ah[im], pbh);
                    mma16816(acc[im][j], ah[im], pbl);
                    mma16816(acc[im][j], al[im], pbh);
                }
        }
        __syncthreads();
    }

    // epilogue 1: fp16 stores (pairs)
#pragma unroll
    for (int im = 0; im < 2; ++im)
#pragma unroll
        for (int j = 0; j < 8; ++j) {
            int gm = m0 + wm * 32 + im * 16 + (lane >> 2);
            int gn = n0 + wn * 64 + j * 8 + (lane & 3) * 2;
            __half2 v0 = __floats2half2_rn(acc[im][j][0], acc[im][j][1]);
            __half2 v1 = __floats2half2_rn(acc[im][j][2], acc[im][j][3]);
            *(__half2*)&C[(size_t)gm * N + gn] = v0;
            *(__half2*)&C[(size_t)(gm + 8) * N + gn] = v1;
        }

    // epilogue 2: fused attention dots for this CTA's (rows, head)
    const int head = (blockIdx.x << 1) + wn;   // this warp's head
    float as_att[16], ad_att[16];
#pragma unroll
    for (int j = 0; j < 8; ++j) {
        int cc = head * HID + j * 8 + (lane & 3) * 2;
        as_att[2 * j] = att_s[cc];     as_att[2 * j + 1] = att_s[cc + 1];
        ad_att[2 * j] = att_d[cc];     ad_att[2 * j + 1] = att_d[cc + 1];
    }
#pragma unroll
    for (int im = 0; im < 2; ++im) {
        float s0 = 0.f, s1 = 0.f, d0 = 0.f, d1 = 0.f;
#pragma unroll
        for (int j = 0; j < 8; ++j) {
            s0 += acc[im][j][0] * as_att[2 * j] + acc[im][j][1] * as_att[2 * j + 1];
            s1 += acc[im][j][2] * as_att[2 * j] + acc[im][j][3] * as_att[2 * j + 1];
            d0 += acc[im][j][0] * ad_att[2 * j] + acc[im][j][1] * ad_att[2 * j + 1];
            d1 += acc[im][j][2] * ad_att[2 * j] + acc[im][j][3] * ad_att[2 * j + 1];
        }
#pragma unroll
        for (int o = 1; o < 4; o <<= 1) {
            s0 += __shfl_xor_sync(0xffffffffu, s0, o);
            s1 += __shfl_xor_sync(0xffffffffu, s1, o);
            d0 += __shfl_xor_sync(0xffffffffu, d0, o);
            d1 += __shfl_xor_sync(0xffffffffu, d1, o);
        }
        if ((lane & 3) == 0) {
            int r = m0 + wm * 32 + im * 16 + (lane >> 2);
            g_as1[r * H1 + head] = s0;
            g_ad1[r * H1 + head] = d0;
            g_as1[(r + 8) * H1 + head] = s1;
            g_ad1[(r + 8) * H1 + head] = d1;
        }
    }
}

// ------------------------------ GEMM2 (split-K, BN=160) ----------------------
#define A2TILE (128 * TSTRIDE)            // 10240
#define B2TILE (160 * TSTRIDE)            // 12800
#define STAGE2 (2 * A2TILE + 2 * B2TILE)  // 46080
#define GEMM2_SMEM (2 * STAGE2)           // 92160

__global__ __launch_bounds__(256, 1)
void gemm2_mma(const __nv_bfloat16* __restrict__ Ah, const __nv_bfloat16* __restrict__ Al,
               const __nv_bfloat16* __restrict__ Bh, const __nv_bfloat16* __restrict__ Bl,
               float* __restrict__ Cp) {
    extern __shared__ char smem[];
    const int K = F1;
    const int tid = threadIdx.x;
    const int wid = tid >> 5, lane = tid & 31;
    const int m0 = blockIdx.y * 128;
    const size_t kb0 = (size_t)blockIdx.z * KSLC;
    const int wm = wid >> 1, wn = wid & 1;
    const int NC = KSLC >> 5;             // 16
    const uint32_t sb = smem_u32(smem);

    float acc[2][10][4];
#pragma unroll
    for (int im = 0; im < 2; ++im)
#pragma unroll
        for (int j = 0; j < 10; ++j)
#pragma unroll
            for (int q = 0; q < 4; ++q) acc[im][j][q] = 0.f;

    auto load_stage = [&](int c, int s) {
        uint32_t base = sb + (uint32_t)s * STAGE2;
        const size_t kc = kb0 + (size_t)c * 32;
#pragma unroll
        for (int i = tid; i < 512; i += 256) {
            int r = i >> 2, seg = i & 3;
            uint32_t off = (uint32_t)(r * TSTRIDE + seg * 16);
            const size_t ga = (size_t)(m0 + r) * K + kc + seg * 8;
            cpa16(base + off, Ah + ga);
            cpa16(base + A2TILE + off, Al + ga);
        }
#pragma unroll
        for (int i = tid; i < 640; i += 256) {
            int r = i >> 2, seg = i & 3;
            uint32_t off = (uint32_t)(r * TSTRIDE + seg * 16);
            const size_t gb = (size_t)r * K + kc + seg * 8;
            cpa16(base + 2 * A2TILE + off, Bh + gb);
            cpa16(base + 2 * A2TILE + B2TILE + off, Bl + gb);
        }
        cpa_commit();
    };

    load_stage(0, 0);
    for (int c = 0; c < NC; ++c) {
        if (c + 1 < NC) {
            load_stage(c + 1, (c + 1) & 1);
            cpa_wait<1>();
        } else {
            cpa_wait<0>();
        }
        __syncthreads();

        const uint32_t base = sb + (uint32_t)(c & 1) * STAGE2;
#pragma unroll
        for (int ks = 0; ks < 2; ++ks) {
            const uint32_t kb = ks * 32;
            uint32_t ah[2][4], al[2][4], bh[5][4], bl[5][4];
#pragma unroll
            for (int im = 0; im < 2; ++im) {
                uint32_t ra = (uint32_t)((wm * 32 + im * 16 + (lane & 15)) * TSTRIDE)
                              + kb + ((lane >> 4) & 1) * 16;
                ldsm4(ah[im], base + ra);
                ldsm4(al[im], base + A2TILE + ra);
            }
#pragma unroll
            for (int p = 0; p < 5; ++p) {
                uint32_t rb = (uint32_t)((wn * 80 + p * 16 + ((lane >> 4) & 1) * 8 +
                                          (lane & 7)) * TSTRIDE)
                              + kb + ((lane >> 3) & 1) * 16;
                ldsm4(bh[p], base + 2 * A2TILE + rb);
                ldsm4(bl[p], base + 2 * A2TILE + B2TILE + rb);
            }
#pragma unroll
            for (int im = 0; im < 2; ++im)
#pragma unroll
                for (int j = 0; j < 10; ++j) {
                    const uint32_t* pbh = &bh[j >> 1][(j & 1) * 2];
                    const uint32_t* pbl = &bl[j >> 1][(j & 1) * 2];
                    mma16816(acc[im][j], ah[im], pbh);
                    mma16816(acc[im][j], ah[im], pbl);
                    mma16816(acc[im][j], al[im], pbh);
                }
        }
        __syncthreads();
    }

    float* out = Cp + (size_t)blockIdx.z * N_NODES * F2;
#pragma unroll
    for (int im = 0; im < 2; ++im)
#pragma unroll
        for (int j = 0; j < 10; ++j) {
            int gm = m0 + wm * 32 + im * 16 + (lane >> 2);
            int gn = wn * 80 + j * 8 + (lane & 3) * 2;
            *(float2*)&out[(size_t)gm * F2 + gn] =
                make_float2(acc[im][j][0], acc[im][j][1]);
            *(float2*)&out[(size_t)(gm + 8) * F2 + gn] =
                make_float2(acc[im][j][2], acc[im][j][3]);
        }
}

// ------------- split-K reduce (deterministic) + fused alpha2 dots ------------
// one block of 160 threads per node; warp w = head w (5 warps)
__global__ __launch_bounds__(160)
void k_reduce_alpha2(const float* __restrict__ att_s, const float* __restrict__ att_d) {
    const int n = blockIdx.x;
    const int t = threadIdx.x;          // 0..159
    const int lane = t & 31, head = t >> 5;
    float s = 0.f;
#pragma unroll
    for (int z = 0; z < KSPLIT; ++z)
        s += g_h2p[(size_t)z * (N_NODES * F2) + n * F2 + t];
    g_h2[n * F2 + t] = s;
    float vs = s * att_s[t];
    float vd = s * att_d[t];
#pragma unroll
    for (int o = 16; o > 0; o >>= 1) {
        vs += __shfl_down_sync(0xffffffffu, vs, o);
        vd += __shfl_down_sync(0xffffffffu, vd, o);
    }
    if (!lane) { g_as2[n * H2 + head] = vs; g_ad2[n * H2 + head] = vd; }
}

// ------------------------------ layer-1 aggregation + ELU + bf16 split -------
__global__ __launch_bounds__(256)
void k_agg1(const float* __restrict__ b1) {
    const int n = blockIdx.x;
    const int t = threadIdx.x;
    const int start = g_off[n];
    const int deg = g_off[n + 1] - start;

    __shared__ float sh_m[H1], sh_den[H1], sh_ad[H1];
    __shared__ float sh_w[32 * H1];
    __shared__ int   s_src[32];
    __shared__ float pm[4][H1], pd[4][H1];

    // softmax max/denominator: 4-way parallel over edges, online per stripe
    {
        const int h = t & 63, quarter = t >> 6;
        float adv = g_ad1[n * H1 + h];
        float m = -1e30f, den = 0.f;
        for (int e = quarter; e < deg; e += 4) {
            int s = g_csr_src[start + e];
            float l = g_as1[s * H1 + h] + adv;
            l = l > 0.f ? l : 0.2f * l;
            if (l > m) { den = den * __expf(m - l) + 1.f; m = l; }
            else       { den += __expf(l - m); }
        }
        pm[quarter][h] = m;
        pd[quarter][h] = den;
        if (quarter == 0) sh_ad[h] = adv;
    }
    __syncthreads();
    if (t < H1) {
        float m0 = pm[0][t], m1 = pm[1][t], m2 = pm[2][t], m3 = pm[3][t];
        float M = fmaxf(fmaxf(m0, m1), fmaxf(m2, m3));
        float D = pd[0][t] * __expf(m0 - M) + pd[1][t] * __expf(m1 - M) +
                  pd[2][t] * __expf(m2 - M) + pd[3][t] * __expf(m3 - M);
        sh_m[t] = M; sh_den[t] = D;
    }
    __syncthreads();

    float acc[16];
#pragma unroll
    for (int i = 0; i < 16; i++) acc[i] = 0.f;
    const int h = t >> 2;  // head of this thread's 16-feature slice

    for (int e0 = 0; e0 < deg; e0 += 32) {
        int ce = min(32, deg - e0);
        if (t < ce) s_src[t] = g_csr_src[start + e0 + t];
        __syncthreads();
        for (int k = t; k < ce * H1; k += 256) {
            int e = k >> 6, hh = k & 63;
            float l = g_as1[s_src[e] * H1 + hh] + sh_ad[hh];
            l = l > 0.f ? l : 0.2f * l;
            sh_w[k] = __expf(l - sh_m[hh]);
        }
        __syncthreads();
        for (int e = 0; e < ce; e++) {
            // 16 fp16 features = 32B = 2 x uint4
            const uint4* hp = reinterpret_cast<const uint4*>(
                g_h1 + (size_t)s_src[e] * F1 + t * 16);
            float wv = sh_w[(e << 6) + h];
#pragma unroll
            for (int q = 0; q < 2; q++) {
                uint4 u = hp[q];
                float2 f0 = __half22float2(*(const __half2*)&u.x);
                float2 f1 = __half22float2(*(const __half2*)&u.y);
                float2 f2 = __half22float2(*(const __half2*)&u.z);
                float2 f3 = __half22float2(*(const __half2*)&u.w);
                acc[8 * q + 0] += wv * f0.x;
                acc[8 * q + 1] += wv * f0.y;
                acc[8 * q + 2] += wv * f1.x;
                acc[8 * q + 3] += wv * f1.y;
                acc[8 * q + 4] += wv * f2.x;
                acc[8 * q + 5] += wv * f2.y;
                acc[8 * q + 6] += wv * f3.x;
                acc[8 * q + 7] += wv * f3.y;
            }
        }
        __syncthreads();
    }

    float invden = 1.f / sh_den[h];
    const float4* bp = reinterpret_cast<const float4*>(b1 + t * 16);
    float vals[16];
#pragma unroll
    for (int q = 0; q < 4; q++) {
        float4 bv = bp[q];
        float v0 = acc[4 * q + 0] * invden + bv.x;
        float v1 = acc[4 * q + 1] * invden + bv.y;
        float v2 = acc[4 * q + 2] * invden + bv.z;
        float v3 = acc[4 * q + 3] * invden + bv.w;
        vals[4 * q + 0] = v0 > 0.f ? v0 : __expf(v0) - 1.f;
        vals[4 * q + 1] = v1 > 0.f ? v1 : __expf(v1) - 1.f;
        vals[4 * q + 2] = v2 > 0.f ? v2 : __expf(v2) - 1.f;
        vals[4 * q + 3] = v3 > 0.f ? v3 : __expf(v3) - 1.f;
    }
    // split to bf16 hi/lo, pack pairs, write as uint4
    uint32_t ph[8], pl[8];
#pragma unroll
    for (int i = 0; i < 8; i++) {
        float a = vals[2 * i], b = vals[2 * i + 1];
        __nv_bfloat16 ahh = __float2bfloat16_rn(a);
        __nv_bfloat16 bhh = __float2bfloat16_rn(b);
        __nv_bfloat16 alo = __float2bfloat16_rn(a - __bfloat162float(ahh));
        __nv_bfloat16 blo = __float2bfloat16_rn(b - __bfloat162float(bhh));
        __nv_bfloat162 hp2 = {ahh, bhh};
        __nv_bfloat162 lp2 = {alo, blo};
        ph[i] = *reinterpret_cast<uint32_t*>(&hp2);
        pl[i] = *reinterpret_cast<uint32_t*>(&lp2);
    }
    size_t off = (size_t)n * F1 + t * 16;
    uint4* oh = reinterpret_cast<uint4*>(g_x1h + off);
    uint4* ol = reinterpret_cast<uint4*>(g_x1l + off);
    oh[0] = make_uint4(ph[0], ph[1], ph[2], ph[3]);
    oh[1] = make_uint4(ph[4], ph[5], ph[6], ph[7]);
    ol[0] = make_uint4(pl[0], pl[1], pl[2], pl[3]);
    ol[1] = make_uint4(pl[4], pl[5], pl[6], pl[7]);
}

// ------------------------------ layer-2 aggregation + head mean --------------
__global__ __launch_bounds__(192)
void k_agg2(const float* __restrict__ b2) {
    const int n = blockIdx.x;
    const int t = threadIdx.x;
    const int start = g_off[n];
    const int deg = g_off[n + 1] - start;

    __shared__ float sh_m[H2], sh_den[H2], sh_ad[H2];
    __shared__ float sh_r[F2];

    if (t < H2) {
        float adv = g_ad2[n * H2 + t];
        float m = -1e30f;
        for (int e = 0; e < deg; e++) {
            int s = g_csr_src[start + e];
            float l = g_as2[s * H2 + t] + adv;
            l = l > 0.f ? l : 0.2f * l;
            m = fmaxf(m, l);
        }
        float den = 0.f;
        for (int e = 0; e < deg; e++) {
            int s = g_csr_src[start + e];
            float l = g_as2[s * H2 + t] + adv;
            l = l > 0.f ? l : 0.2f * l;
            den += __expf(l - m);
        }
        sh_m[t] = m; sh_den[t] = den; sh_ad[t] = adv;
    }
    __syncthreads();

    if (t < F2) {
        int hh = t >> 5;
        float m = sh_m[hh], adv = sh_ad[hh];
        float acc = 0.f;
        for (int e = 0; e < deg; e++) {
            int s = g_csr_src[start + e];
            float l = g_as2[s * H2 + hh] + adv;
            l = l > 0.f ? l : 0.2f * l;
            acc += __expf(l - m) * g_h2[s * F2 + t];
        }
        sh_r[t] = acc / sh_den[hh];
    }
    __syncthreads();

    if (t < OUTF) {
        float v = (sh_r[t] + sh_r[32 + t] + sh_r[64 + t] + sh_r[96 + t] +
                   sh_r[128 + t]) * 0.2f + b2[t];
        g_x2[n * OUTF + t] = v;
    }
}

// ------------------------------ bond scores + softmax ------------------------
__global__ void k_score(const int* __restrict__ lefts,
                        const int* __restrict__ rights,
                        float* __restrict__ out) {
    __shared__ float sm[NB];
    int t = threadIdx.x;
    int l = lefts[t], r = rights[t];
    float s = 0.f;
#pragma unroll
    for (int c = 0; c < OUTF; c++) s += g_x2[l * OUTF + c] + g_x2[r * OUTF + c];
    sm[t] = s;
    __syncthreads();
    float mx = -1e30f;
    for (int j = 0; j < NB; j++) mx = fmaxf(mx, sm[j]);
    float e = __expf(s - mx);
    __syncthreads();
    sm[t] = e;
    __syncthreads();
    float sum = 0.f;
    for (int j = 0; j < NB; j++) sum += sm[j];
    out[t] = e / sum;
}

// ------------------------------ launch ---------------------------------------
extern "C" void kernel_launch(void* const* d_in, const int* in_sizes, int n_in,
                              void* d_out, int out_size) {
    const float* x   = (const float*)d_in[0];
    const int*   ei  = (const int*)d_in[1];
    const int*   lf  = (const int*)d_in[2];
    const int*   rt  = (const int*)d_in[3];
    const float* W1  = (const float*)d_in[4];
    const float* as1 = (const float*)d_in[5];
    const float* ad1 = (const float*)d_in[6];
    const float* b1  = (const float*)d_in[7];
    const float* W2  = (const float*)d_in[8];
    const float* as2 = (const float*)d_in[9];
    const float* ad2 = (const float*)d_in[10];
    const float* b2  = (const float*)d_in[11];
    float* out = (float*)d_out;

    cudaFuncSetAttribute(gemm1_mma, cudaFuncAttributeMaxDynamicSharedMemorySize,
                         GEMM_SMEM);
    cudaFuncSetAttribute(gemm2_mma, cudaFuncAttributeMaxDynamicSharedMemorySize,
                         GEMM2_SMEM);

    void *p_xh, *p_xl, *p_w1h, *p_w1l, *p_w2h, *p_w2l;
    void *p_h1, *p_h2p, *p_x1h, *p_x1l;
    cudaGetSymbolAddress(&p_xh, g_xh);
    cudaGetSymbolAddress(&p_xl, g_xl);
    cudaGetSymbolAddress(&p_w1h, g_w1h);
    cudaGetSymbolAddress(&p_w1l, g_w1l);
    cudaGetSymbolAddress(&p_w2h, g_w2h);
    cudaGetSymbolAddress(&p_w2l, g_w2l);
    cudaGetSymbolAddress(&p_h1, g_h1);
    cudaGetSymbolAddress(&p_h2p, g_h2p);
    cudaGetSymbolAddress(&p_x1h, g_x1h);
    cudaGetSymbolAddress(&p_x1l, g_x1l);

    // fused input conversions + counts init
    k_prep<<<(NSPLIT + 255) / 256, 256>>>(x, W1, W2);

    // CSR by destination (self-loops included)
    k_count<<<(NE + 255) / 256, 256>>>(ei);
    k_scan<<<1, 1024>>>();
    k_scatter<<<(ETOT + 255) / 256, 256>>>(ei);

    // layer 1: h1 = x @ W1^T (fp16 out) + fused alpha1
    gemm1_mma<<<dim3(F1 / 128, N_NODES / 128), 256, GEMM_SMEM>>>(
        (const __nv_bfloat16*)p_xh, (const __nv_bfloat16*)p_xl,
        (const __nv_bfloat16*)p_w1h, (const __nv_bfloat16*)p_w1l,
        (__half*)p_h1, as1, ad1);
    k_agg1<<<N_NODES, 256>>>(b1);

    // layer 2: h2 = x1 @ W2^T, split-K x8 + fused reduce/alpha2
    gemm2_mma<<<dim3(1, N_NODES / 128, KSPLIT), 256, GEMM2_SMEM>>>(
        (const __nv_bfloat16*)p_x1h, (const __nv_bfloat16*)p_x1l,
        (const __nv_bfloat16*)p_w2h, (const __nv_bfloat16*)p_w2l,
        (float*)p_h2p);
    k_reduce_alpha2<<<N_NODES, 160>>>(as2, ad2);
    k_agg2<<<N_NODES, 192>>>(b2);

    // bonds
    k_score<<<1, NB>>>(lf, rt, out);
}

// round 7
// speedup vs baseline: 6.2755x; 1.2503x over previous
#include <cuda_runtime.h>
#include <cuda_bf16.h>
#include <cuda_fp16.h>
#include <stdint.h>
#include <math.h>

#define N_NODES 8192
#define NE      49152
#define ETOT    (NE + N_NODES)       // 57344
#define IN_F    128
#define H1      64
#define HID     64
#define F1      (H1*HID)             // 4096
#define H2      5
#define OUTF    32
#define F2      (H2*OUTF)            // 160
#define NB      64
#define KSPLIT  8
#define KSLC    (F1 / KSPLIT)        // 512

// ------------------------------ scratch (static, no allocation) --------------
__device__ __half g_h1[(size_t)N_NODES * F1];                // 67 MB
__device__ __half g_x1[(size_t)N_NODES * F1];                // 67 MB (single fp16)
__device__ __half g_xf[N_NODES * IN_F];
__device__ __half g_w1h[F1 * IN_F];
__device__ __half g_w1l[F1 * IN_F];
__device__ __half g_w2h[F2 * F1];
__device__ __half g_w2l[F2 * F1];
__device__ float g_as1[N_NODES * H1];
__device__ float g_ad1[N_NODES * H1];
__device__ float g_h2p[(size_t)KSPLIT * N_NODES * F2];       // 42 MB partials
__device__ float g_h2[N_NODES * F2];
__device__ float g_as2[N_NODES * H2];
__device__ float g_ad2[N_NODES * H2];
__device__ float g_x2[N_NODES * OUTF];
__device__ int   g_counts[N_NODES];
__device__ int   g_off[N_NODES + 1];
__device__ int   g_cursor[N_NODES];
__device__ int   g_csr_src[ETOT];

// ------------------------------ PTX helpers ----------------------------------
__device__ __forceinline__ uint32_t smem_u32(const void* p) {
    uint32_t a;
    asm("{ .reg .u64 t; cvta.to.shared.u64 t, %1; cvt.u32.u64 %0, t; }"
        : "=r"(a) : "l"(p));
    return a;
}

__device__ __forceinline__ void cpa16(uint32_t d, const void* s) {
    asm volatile("cp.async.cg.shared.global [%0], [%1], 16;" :: "r"(d), "l"(s));
}
__device__ __forceinline__ void cpa_commit() {
    asm volatile("cp.async.commit_group;" ::: "memory");
}
template <int N> __device__ __forceinline__ void cpa_wait() {
    asm volatile("cp.async.wait_group %0;" :: "n"(N) : "memory");
}

__device__ __forceinline__ void ldsm4(uint32_t* r, uint32_t addr) {
    asm volatile("ldmatrix.sync.aligned.m8n8.x4.shared.b16 {%0,%1,%2,%3}, [%4];"
                 : "=r"(r[0]), "=r"(r[1]), "=r"(r[2]), "=r"(r[3]) : "r"(addr));
}

__device__ __forceinline__ void mma16816h(float* c, const uint32_t* a,
                                          const uint32_t* b) {
    asm volatile(
        "mma.sync.aligned.m16n8k16.row.col.f32.f16.f16.f32 "
        "{%0,%1,%2,%3}, {%4,%5,%6,%7}, {%8,%9}, {%0,%1,%2,%3};"
        : "+f"(c[0]), "+f"(c[1]), "+f"(c[2]), "+f"(c[3])
        : "r"(a[0]), "r"(a[1]), "r"(a[2]), "r"(a[3]), "r"(b[0]), "r"(b[1]));
}

// ------------------ fused input conversion + counts init ---------------------
#define NXE (N_NODES * IN_F)     // 1048576
#define NW1 (F1 * IN_F)          // 524288
#define NW2 (F2 * F1)            // 655360
#define NSPLIT (NXE + NW1 + NW2)

__global__ void k_prep(const float* __restrict__ x, const float* __restrict__ W1,
                       const float* __restrict__ W2) {
    int i = blockIdx.x * blockDim.x + threadIdx.x;
    if (i < N_NODES) g_counts[i] = 1;  // self-loop
    if (i < NXE) {
        g_xf[i] = __float2half_rn(x[i]);           // single fp16 A operand
        return;
    }
    const float* src;
    __half *hi, *lo;
    int k;
    if (i < NXE + NW1)   { src = W1; hi = g_w1h; lo = g_w1l; k = i - NXE; }
    else if (i < NSPLIT) { src = W2; hi = g_w2h; lo = g_w2l; k = i - NXE - NW1; }
    else return;
    float v = src[k];
    __half h = __float2half_rn(v);
    hi[k] = h;
    lo[k] = __float2half_rn(v - __half2float(h));
}

// ------------------------------ CSR build ------------------------------------
__global__ void k_count(const int* __restrict__ ei) {
    int e = blockIdx.x * blockDim.x + threadIdx.x;
    if (e < NE) atomicAdd(&g_counts[ei[NE + e]], 1);
}

__global__ void k_scan() {
    __shared__ int sh[1024];
    int t = threadIdx.x;
    int loc[8];
    int s = 0;
#pragma unroll
    for (int j = 0; j < 8; j++) { loc[j] = g_counts[t * 8 + j]; s += loc[j]; }
    sh[t] = s;
    __syncthreads();
    for (int off = 1; off < 1024; off <<= 1) {
        int v = (t >= off) ? sh[t - off] : 0;
        __syncthreads();
        sh[t] += v;
        __syncthreads();
    }
    int run = (t == 0) ? 0 : sh[t - 1];
#pragma unroll
    for (int j = 0; j < 8; j++) {
        int idx = t * 8 + j;
        g_off[idx] = run;
        g_cursor[idx] = run;
        run += loc[j];
    }
    if (t == 1023) g_off[N_NODES] = run;
}

__global__ void k_scatter(const int* __restrict__ ei) {
    int i = blockIdx.x * blockDim.x + threadIdx.x;
    if (i >= ETOT) return;
    int src, dst;
    if (i < NE) { src = ei[i]; dst = ei[NE + i]; }
    else        { src = i - NE; dst = src; }
    int pos = atomicAdd(&g_cursor[dst], 1);
    g_csr_src[pos] = src;
}

// ------------------------------ GEMM1 (fp16 2-term + fused alpha) ------------
// h1[M,4096] = xf[M,128] * (W1h+W1l)[4096,128]^T
// BM=128, BN=128, BK=32. 256 threads (8 warps, 4m x 2n). Output __half.
#define TSTRIDE 80                        // bytes per smem row (5 x 16B segs)
#define S1TILE  (128 * TSTRIDE)           // 10240 B
#define STAGE1  (3 * S1TILE)              // A, Bh, Bl
#define GEMM1_SMEM (2 * STAGE1)           // 61440 B

__global__ __launch_bounds__(256, 1)
void gemm1_mma(const __half* __restrict__ Af,
               const __half* __restrict__ Bh, const __half* __restrict__ Bl,
               __half* __restrict__ C,
               const float* __restrict__ att_s, const float* __restrict__ att_d) {
    extern __shared__ char smem[];
    const int N = F1, K = IN_F;
    const int tid = threadIdx.x;
    const int wid = tid >> 5, lane = tid & 31;
    const int m0 = blockIdx.y * 128, n0 = blockIdx.x * 128;
    const int wm = wid >> 1, wn = wid & 1;
    const int NC = K >> 5;                // 4
    const uint32_t sb = smem_u32(smem);

    float acc[2][8][4];
#pragma unroll
    for (int im = 0; im < 2; ++im)
#pragma unroll
        for (int j = 0; j < 8; ++j)
#pragma unroll
            for (int q = 0; q < 4; ++q) acc[im][j][q] = 0.f;

    auto load_stage = [&](int c, int s) {
        uint32_t base = sb + (uint32_t)s * STAGE1;
        const size_t kc = (size_t)c * 32;
#pragma unroll
        for (int i = tid; i < 512; i += 256) {
            int r = i >> 2, seg = i & 3;
            uint32_t off = (uint32_t)(r * TSTRIDE + seg * 16);
            cpa16(base + off, Af + (size_t)(m0 + r) * K + kc + seg * 8);
            const size_t gb = (size_t)(n0 + r) * K + kc + seg * 8;
            cpa16(base + S1TILE + off, Bh + gb);
            cpa16(base + 2 * S1TILE + off, Bl + gb);
        }
        cpa_commit();
    };

    load_stage(0, 0);
    for (int c = 0; c < NC; ++c) {
        if (c + 1 < NC) {
            load_stage(c + 1, (c + 1) & 1);
            cpa_wait<1>();
        } else {
            cpa_wait<0>();
        }
        __syncthreads();

        const uint32_t base = sb + (uint32_t)(c & 1) * STAGE1;
#pragma unroll
        for (int ks = 0; ks < 2; ++ks) {
            const uint32_t kb = ks * 32;
            uint32_t a[2][4], bh[4][4], bl[4][4];
#pragma unroll
            for (int im = 0; im < 2; ++im) {
                uint32_t ra = (uint32_t)((wm * 32 + im * 16 + (lane & 15)) * TSTRIDE)
                              + kb + ((lane >> 4) & 1) * 16;
                ldsm4(a[im], base + ra);
            }
#pragma unroll
            for (int p = 0; p < 4; ++p) {
                uint32_t rb = (uint32_t)((wn * 64 + p * 16 + ((lane >> 4) & 1) * 8 +
                                          (lane & 7)) * TSTRIDE)
                              + kb + ((lane >> 3) & 1) * 16;
                ldsm4(bh[p], base + S1TILE + rb);
                ldsm4(bl[p], base + 2 * S1TILE + rb);
            }
#pragma unroll
            for (int im = 0; im < 2; ++im)
#pragma unroll
                for (int j = 0; j < 8; ++j) {
                    mma16816h(acc[im][j], a[im], &bh[j >> 1][(j & 1) * 2]);
                    mma16816h(acc[im][j], a[im], &bl[j >> 1][(j & 1) * 2]);
                }
        }
        __syncthreads();
    }

    // epilogue 1: fp16 stores (pairs)
#pragma unroll
    for (int im = 0; im < 2; ++im)
#pragma unroll
        for (int j = 0; j < 8; ++j) {
            int gm = m0 + wm * 32 + im * 16 + (lane >> 2);
            int gn = n0 + wn * 64 + j * 8 + (lane & 3) * 2;
            __half2 v0 = __floats2half2_rn(acc[im][j][0], acc[im][j][1]);
            __half2 v1 = __floats2half2_rn(acc[im][j][2], acc[im][j][3]);
            *(__half2*)&C[(size_t)gm * N + gn] = v0;
            *(__half2*)&C[(size_t)(gm + 8) * N + gn] = v1;
        }

    // epilogue 2: fused attention dots for this CTA's (rows, head)
    const int head = (blockIdx.x << 1) + wn;   // this warp's head
    float as_att[16], ad_att[16];
#pragma unroll
    for (int j = 0; j < 8; ++j) {
        int cc = head * HID + j * 8 + (lane & 3) * 2;
        as_att[2 * j] = att_s[cc];     as_att[2 * j + 1] = att_s[cc + 1];
        ad_att[2 * j] = att_d[cc];     ad_att[2 * j + 1] = att_d[cc + 1];
    }
#pragma unroll
    for (int im = 0; im < 2; ++im) {
        float s0 = 0.f, s1 = 0.f, d0 = 0.f, d1 = 0.f;
#pragma unroll
        for (int j = 0; j < 8; ++j) {
            s0 += acc[im][j][0] * as_att[2 * j] + acc[im][j][1] * as_att[2 * j + 1];
            s1 += acc[im][j][2] * as_att[2 * j] + acc[im][j][3] * as_att[2 * j + 1];
            d0 += acc[im][j][0] * ad_att[2 * j] + acc[im][j][1] * ad_att[2 * j + 1];
            d1 += acc[im][j][2] * ad_att[2 * j] + acc[im][j][3] * ad_att[2 * j + 1];
        }
#pragma unroll
        for (int o = 1; o < 4; o <<= 1) {
            s0 += __shfl_xor_sync(0xffffffffu, s0, o);
            s1 += __shfl_xor_sync(0xffffffffu, s1, o);
            d0 += __shfl_xor_sync(0xffffffffu, d0, o);
            d1 += __shfl_xor_sync(0xffffffffu, d1, o);
        }
        if ((lane & 3) == 0) {
            int r = m0 + wm * 32 + im * 16 + (lane >> 2);
            g_as1[r * H1 + head] = s0;
            g_ad1[r * H1 + head] = d0;
            g_as1[(r + 8) * H1 + head] = s1;
            g_ad1[(r + 8) * H1 + head] = d1;
        }
    }
}

// ------------------------------ GEMM2 (split-K, BN=160, fp16 2-term) ---------
#define A2TILE (128 * TSTRIDE)            // 10240
#define B2TILE (160 * TSTRIDE)            // 12800
#define STAGE2 (A2TILE + 2 * B2TILE)      // 35840
#define GEMM2_SMEM (2 * STAGE2)           // 71680

__global__ __launch_bounds__(256, 1)
void gemm2_mma(const __half* __restrict__ Af,
               const __half* __restrict__ Bh, const __half* __restrict__ Bl,
               float* __restrict__ Cp) {
    extern __shared__ char smem[];
    const int K = F1;
    const int tid = threadIdx.x;
    const int wid = tid >> 5, lane = tid & 31;
    const int m0 = blockIdx.y * 128;
    const size_t kb0 = (size_t)blockIdx.z * KSLC;
    const int wm = wid >> 1, wn = wid & 1;
    const int NC = KSLC >> 5;             // 16
    const uint32_t sb = smem_u32(smem);

    float acc[2][10][4];
#pragma unroll
    for (int im = 0; im < 2; ++im)
#pragma unroll
        for (int j = 0; j < 10; ++j)
#pragma unroll
            for (int q = 0; q < 4; ++q) acc[im][j][q] = 0.f;

    auto load_stage = [&](int c, int s) {
        uint32_t base = sb + (uint32_t)s * STAGE2;
        const size_t kc = kb0 + (size_t)c * 32;
#pragma unroll
        for (int i = tid; i < 512; i += 256) {
            int r = i >> 2, seg = i & 3;
            uint32_t off = (uint32_t)(r * TSTRIDE + seg * 16);
            cpa16(base + off, Af + (size_t)(m0 + r) * K + kc + seg * 8);
        }
#pragma unroll
        for (int i = tid; i < 640; i += 256) {
            int r = i >> 2, seg = i & 3;
            uint32_t off = (uint32_t)(r * TSTRIDE + seg * 16);
            const size_t gb = (size_t)r * K + kc + seg * 8;
            cpa16(base + A2TILE + off, Bh + gb);
            cpa16(base + A2TILE + B2TILE + off, Bl + gb);
        }
        cpa_commit();
    };

    load_stage(0, 0);
    for (int c = 0; c < NC; ++c) {
        if (c + 1 < NC) {
            load_stage(c + 1, (c + 1) & 1);
            cpa_wait<1>();
        } else {
            cpa_wait<0>();
        }
        __syncthreads();

        const uint32_t base = sb + (uint32_t)(c & 1) * STAGE2;
#pragma unroll
        for (int ks = 0; ks < 2; ++ks) {
            const uint32_t kb = ks * 32;
            uint32_t a[2][4], bh[5][4], bl[5][4];
#pragma unroll
            for (int im = 0; im < 2; ++im) {
                uint32_t ra = (uint32_t)((wm * 32 + im * 16 + (lane & 15)) * TSTRIDE)
                              + kb + ((lane >> 4) & 1) * 16;
                ldsm4(a[im], base + ra);
            }
#pragma unroll
            for (int p = 0; p < 5; ++p) {
                uint32_t rb = (uint32_t)((wn * 80 + p * 16 + ((lane >> 4) & 1) * 8 +
                                          (lane & 7)) * TSTRIDE)
                              + kb + ((lane >> 3) & 1) * 16;
                ldsm4(bh[p], base + A2TILE + rb);
                ldsm4(bl[p], base + A2TILE + B2TILE + rb);
            }
#pragma unroll
            for (int im = 0; im < 2; ++im)
#pragma unroll
                for (int j = 0; j < 10; ++j) {
                    mma16816h(acc[im][j], a[im], &bh[j >> 1][(j & 1) * 2]);
                    mma16816h(acc[im][j], a[im], &bl[j >> 1][(j & 1) * 2]);
                }
        }
        __syncthreads();
    }

    float* out = Cp + (size_t)blockIdx.z * (N_NODES * F2);
#pragma unroll
    for (int im = 0; im < 2; ++im)
#pragma unroll
        for (int j = 0; j < 10; ++j) {
            int gm = m0 + wm * 32 + im * 16 + (lane >> 2);
            int gn = wn * 80 + j * 8 + (lane & 3) * 2;
            *(float2*)&out[(size_t)gm * F2 + gn] =
                make_float2(acc[im][j][0], acc[im][j][1]);
            *(float2*)&out[(size_t)(gm + 8) * F2 + gn] =
                make_float2(acc[im][j][2], acc[im][j][3]);
        }
}

// ------------- split-K reduce (deterministic) + fused alpha2 dots ------------
__global__ __launch_bounds__(160)
void k_reduce_alpha2(const float* __restrict__ att_s, const float* __restrict__ att_d) {
    const int n = blockIdx.x;
    const int t = threadIdx.x;          // 0..159
    const int lane = t & 31, head = t >> 5;
    float s = 0.f;
#pragma unroll
    for (int z = 0; z < KSPLIT; ++z)
        s += g_h2p[(size_t)z * (N_NODES * F2) + n * F2 + t];
    g_h2[n * F2 + t] = s;
    float vs = s * att_s[t];
    float vd = s * att_d[t];
#pragma unroll
    for (int o = 16; o > 0; o >>= 1) {
        vs += __shfl_down_sync(0xffffffffu, vs, o);
        vd += __shfl_down_sync(0xffffffffu, vd, o);
    }
    if (!lane) { g_as2[n * H2 + head] = vs; g_ad2[n * H2 + head] = vd; }
}

// ------------------------------ layer-1 aggregation + ELU + fp16 out ---------
__global__ __launch_bounds__(256)
void k_agg1(const float* __restrict__ b1) {
    const int n = blockIdx.x;
    const int t = threadIdx.x;
    const int start = g_off[n];
    const int deg = g_off[n + 1] - start;

    __shared__ float sh_m[H1], sh_den[H1], sh_ad[H1];
    __shared__ float sh_w[32 * H1];
    __shared__ int   s_src[32];
    __shared__ float pm[4][H1], pd[4][H1];

    // softmax max/denominator: 4-way parallel over edges, online per stripe
    {
        const int h = t & 63, quarter = t >> 6;
        float adv = g_ad1[n * H1 + h];
        float m = -1e30f, den = 0.f;
        for (int e = quarter; e < deg; e += 4) {
            int s = g_csr_src[start + e];
            float l = g_as1[s * H1 + h] + adv;
            l = l > 0.f ? l : 0.2f * l;
            if (l > m) { den = den * __expf(m - l) + 1.f; m = l; }
            else       { den += __expf(l - m); }
        }
        pm[quarter][h] = m;
        pd[quarter][h] = den;
        if (quarter == 0) sh_ad[h] = adv;
    }
    __syncthreads();
    if (t < H1) {
        float m0 = pm[0][t], m1 = pm[1][t], m2 = pm[2][t], m3 = pm[3][t];
        float M = fmaxf(fmaxf(m0, m1), fmaxf(m2, m3));
        float D = pd[0][t] * __expf(m0 - M) + pd[1][t] * __expf(m1 - M) +
                  pd[2][t] * __expf(m2 - M) + pd[3][t] * __expf(m3 - M);
        sh_m[t] = M; sh_den[t] = D;
    }
    __syncthreads();

    float acc[16];
#pragma unroll
    for (int i = 0; i < 16; i++) acc[i] = 0.f;
    const int h = t >> 2;  // head of this thread's 16-feature slice

    for (int e0 = 0; e0 < deg; e0 += 32) {
        int ce = min(32, deg - e0);
        if (t < ce) s_src[t] = g_csr_src[start + e0 + t];
        __syncthreads();
        for (int k = t; k < ce * H1; k += 256) {
            int e = k >> 6, hh = k & 63;
            float l = g_as1[s_src[e] * H1 + hh] + sh_ad[hh];
            l = l > 0.f ? l : 0.2f * l;
            sh_w[k] = __expf(l - sh_m[hh]);
        }
        __syncthreads();
        for (int e = 0; e < ce; e++) {
            const uint4* hp = reinterpret_cast<const uint4*>(
                g_h1 + (size_t)s_src[e] * F1 + t * 16);
            float wv = sh_w[(e << 6) + h];
#pragma unroll
            for (int q = 0; q < 2; q++) {
                uint4 u = hp[q];
                float2 f0 = __half22float2(*(const __half2*)&u.x);
                float2 f1 = __half22float2(*(const __half2*)&u.y);
                float2 f2 = __half22float2(*(const __half2*)&u.z);
                float2 f3 = __half22float2(*(const __half2*)&u.w);
                acc[8 * q + 0] += wv * f0.x;
                acc[8 * q + 1] += wv * f0.y;
                acc[8 * q + 2] += wv * f1.x;
                acc[8 * q + 3] += wv * f1.y;
                acc[8 * q + 4] += wv * f2.x;
                acc[8 * q + 5] += wv * f2.y;
                acc[8 * q + 6] += wv * f3.x;
                acc[8 * q + 7] += wv * f3.y;
            }
        }
        __syncthreads();
    }

    float invden = 1.f / sh_den[h];
    const float4* bp = reinterpret_cast<const float4*>(b1 + t * 16);
    float vals[16];
#pragma unroll
    for (int q = 0; q < 4; q++) {
        float4 bv = bp[q];
        float v0 = acc[4 * q + 0] * invden + bv.x;
        float v1 = acc[4 * q + 1] * invden + bv.y;
        float v2 = acc[4 * q + 2] * invden + bv.z;
        float v3 = acc[4 * q + 3] * invden + bv.w;
        vals[4 * q + 0] = v0 > 0.f ? v0 : __expf(v0) - 1.f;
        vals[4 * q + 1] = v1 > 0.f ? v1 : __expf(v1) - 1.f;
        vals[4 * q + 2] = v2 > 0.f ? v2 : __expf(v2) - 1.f;
        vals[4 * q + 3] = v3 > 0.f ? v3 : __expf(v3) - 1.f;
    }
    // pack to fp16 single, write as 2x uint4
    uint32_t pk[8];
#pragma unroll
    for (int i = 0; i < 8; i++) {
        __half2 hv = __floats2half2_rn(vals[2 * i], vals[2 * i + 1]);
        pk[i] = *reinterpret_cast<uint32_t*>(&hv);
    }
    size_t off = (size_t)n * F1 + t * 16;
    uint4* op = reinterpret_cast<uint4*>(g_x1 + off);
    op[0] = make_uint4(pk[0], pk[1], pk[2], pk[3]);
    op[1] = make_uint4(pk[4], pk[5], pk[6], pk[7]);
}

// ------------------------------ layer-2 aggregation + head mean --------------
__global__ __launch_bounds__(192)
void k_agg2(const float* __restrict__ b2) {
    const int n = blockIdx.x;
    const int t = threadIdx.x;
    const int start = g_off[n];
    const int deg = g_off[n + 1] - start;

    __shared__ float sh_m[H2], sh_den[H2], sh_ad[H2];
    __shared__ float sh_r[F2];

    if (t < H2) {
        float adv = g_ad2[n * H2 + t];
        float m = -1e30f;
        for (int e = 0; e < deg; e++) {
            int s = g_csr_src[start + e];
            float l = g_as2[s * H2 + t] + adv;
            l = l > 0.f ? l : 0.2f * l;
            m = fmaxf(m, l);
        }
        float den = 0.f;
        for (int e = 0; e < deg; e++) {
            int s = g_csr_src[start + e];
            float l = g_as2[s * H2 + t] + adv;
            l = l > 0.f ? l : 0.2f * l;
            den += __expf(l - m);
        }
        sh_m[t] = m; sh_den[t] = den; sh_ad[t] = adv;
    }
    __syncthreads();

    if (t < F2) {
        int hh = t >> 5;
        float m = sh_m[hh], adv = sh_ad[hh];
        float acc = 0.f;
        for (int e = 0; e < deg; e++) {
            int s = g_csr_src[start + e];
            float l = g_as2[s * H2 + hh] + adv;
            l = l > 0.f ? l : 0.2f * l;
            acc += __expf(l - m) * g_h2[s * F2 + t];
        }
        sh_r[t] = acc / sh_den[hh];
    }
    __syncthreads();

    if (t < OUTF) {
        float v = (sh_r[t] + sh_r[32 + t] + sh_r[64 + t] + sh_r[96 + t] +
                   sh_r[128 + t]) * 0.2f + b2[t];
        g_x2[n * OUTF + t] = v;
    }
}

// ------------------------------ bond scores + softmax ------------------------
__global__ void k_score(const int* __restrict__ lefts,
                        const int* __restrict__ rights,
                        float* __restrict__ out) {
    __shared__ float sm[NB];
    int t = threadIdx.x;
    int l = lefts[t], r = rights[t];
    float s = 0.f;
#pragma unroll
    for (int c = 0; c < OUTF; c++) s += g_x2[l * OUTF + c] + g_x2[r * OUTF + c];
    sm[t] = s;
    __syncthreads();
    float mx = -1e30f;
    for (int j = 0; j < NB; j++) mx = fmaxf(mx, sm[j]);
    float e = __expf(s - mx);
    __syncthreads();
    sm[t] = e;
    __syncthreads();
    float sum = 0.f;
    for (int j = 0; j < NB; j++) sum += sm[j];
    out[t] = e / sum;
}

// ------------------------------ launch ---------------------------------------
extern "C" void kernel_launch(void* const* d_in, const int* in_sizes, int n_in,
                              void* d_out, int out_size) {
    const float* x   = (const float*)d_in[0];
    const int*   ei  = (const int*)d_in[1];
    const int*   lf  = (const int*)d_in[2];
    const int*   rt  = (const int*)d_in[3];
    const float* W1  = (const float*)d_in[4];
    const float* as1 = (const float*)d_in[5];
    const float* ad1 = (const float*)d_in[6];
    const float* b1  = (const float*)d_in[7];
    const float* W2  = (const float*)d_in[8];
    const float* as2 = (const float*)d_in[9];
    const float* ad2 = (const float*)d_in[10];
    const float* b2  = (const float*)d_in[11];
    float* out = (float*)d_out;

    cudaFuncSetAttribute(gemm1_mma, cudaFuncAttributeMaxDynamicSharedMemorySize,
                         GEMM1_SMEM);
    cudaFuncSetAttribute(gemm2_mma, cudaFuncAttributeMaxDynamicSharedMemorySize,
                         GEMM2_SMEM);

    void *p_xf, *p_w1h, *p_w1l, *p_w2h, *p_w2l;
    void *p_h1, *p_h2p, *p_x1;
    cudaGetSymbolAddress(&p_xf, g_xf);
    cudaGetSymbolAddress(&p_w1h, g_w1h);
    cudaGetSymbolAddress(&p_w1l, g_w1l);
    cudaGetSymbolAddress(&p_w2h, g_w2h);
    cudaGetSymbolAddress(&p_w2l, g_w2l);
    cudaGetSymbolAddress(&p_h1, g_h1);
    cudaGetSymbolAddress(&p_h2p, g_h2p);
    cudaGetSymbolAddress(&p_x1, g_x1);

    // fused input conversions + counts init
    k_prep<<<(NSPLIT + 255) / 256, 256>>>(x, W1, W2);

    // CSR by destination (self-loops included)
    k_count<<<(NE + 255) / 256, 256>>>(ei);
    k_scan<<<1, 1024>>>();
    k_scatter<<<(ETOT + 255) / 256, 256>>>(ei);

    // layer 1: h1 = x @ W1^T (fp16 out) + fused alpha1
    gemm1_mma<<<dim3(F1 / 128, N_NODES / 128), 256, GEMM1_SMEM>>>(
        (const __half*)p_xf, (const __half*)p_w1h, (const __half*)p_w1l,
        (__half*)p_h1, as1, ad1);
    k_agg1<<<N_NODES, 256>>>(b1);

    // layer 2: h2 = x1 @ W2^T, split-K x8 + fused reduce/alpha2
    gemm2_mma<<<dim3(1, N_NODES / 128, KSPLIT), 256, GEMM2_SMEM>>>(
        (const __half*)p_x1, (const __half*)p_w2h, (const __half*)p_w2l,
        (float*)p_h2p);
    k_reduce_alpha2<<<N_NODES, 160>>>(as2, ad2);
    k_agg2<<<N_NODES, 192>>>(b2);

    // bonds
    k_score<<<1, NB>>>(lf, rt, out);
}

// round 8
// speedup vs baseline: 7.7027x; 1.2274x over previous
#include <cuda_runtime.h>
#include <cuda_bf16.h>
#include <cuda_fp16.h>
#include <stdint.h>
#include <math.h>

#define N_NODES 8192
#define NE      49152
#define ETOT    (NE + N_NODES)       // 57344
#define IN_F    128
#define H1      64
#define HID     64
#define F1      (H1*HID)             // 4096
#define H2      5
#define OUTF    32
#define F2      (H2*OUTF)            // 160
#define NB      64
#define KSPLIT  8
#define KSLC    (F1 / KSPLIT)        // 512

// ------------------------------ scratch (static, no allocation) --------------
__device__ __half g_h1[(size_t)N_NODES * F1];                // 67 MB
__device__ __half g_x1[(size_t)N_NODES * F1];                // 67 MB
__device__ __half g_xf[N_NODES * IN_F];
__device__ __half g_w1h[F1 * IN_F];
__device__ __half g_w1l[F1 * IN_F];
__device__ __half g_w2h[F2 * F1];
__device__ float g_as1[N_NODES * H1];
__device__ float g_ad1[N_NODES * H1];
__device__ float g_h2p[(size_t)KSPLIT * N_NODES * F2];       // 42 MB partials
__device__ float g_h2[N_NODES * F2];
__device__ float g_as2[N_NODES * H2];
__device__ float g_ad2[N_NODES * H2];
__device__ float g_x2[N_NODES * OUTF];
__device__ int   g_counts[N_NODES];   // zero at start of every call (scan resets)
__device__ int   g_off[N_NODES + 1];
__device__ int   g_cursor[N_NODES];
__device__ int   g_csr_src[ETOT];

// ------------------------------ PTX helpers ----------------------------------
__device__ __forceinline__ uint32_t smem_u32(const void* p) {
    uint32_t a;
    asm("{ .reg .u64 t; cvta.to.shared.u64 t, %1; cvt.u32.u64 %0, t; }"
        : "=r"(a) : "l"(p));
    return a;
}

__device__ __forceinline__ void cpa16(uint32_t d, const void* s) {
    asm volatile("cp.async.cg.shared.global [%0], [%1], 16;" :: "r"(d), "l"(s));
}
__device__ __forceinline__ void cpa_commit() {
    asm volatile("cp.async.commit_group;" ::: "memory");
}
template <int N> __device__ __forceinline__ void cpa_wait() {
    asm volatile("cp.async.wait_group %0;" :: "n"(N) : "memory");
}

__device__ __forceinline__ void ldsm4(uint32_t* r, uint32_t addr) {
    asm volatile("ldmatrix.sync.aligned.m8n8.x4.shared.b16 {%0,%1,%2,%3}, [%4];"
                 : "=r"(r[0]), "=r"(r[1]), "=r"(r[2]), "=r"(r[3]) : "r"(addr));
}

__device__ __forceinline__ void mma16816h(float* c, const uint32_t* a,
                                          const uint32_t* b) {
    asm volatile(
        "mma.sync.aligned.m16n8k16.row.col.f32.f16.f16.f32 "
        "{%0,%1,%2,%3}, {%4,%5,%6,%7}, {%8,%9}, {%0,%1,%2,%3};"
        : "+f"(c[0]), "+f"(c[1]), "+f"(c[2]), "+f"(c[3])
        : "r"(a[0]), "r"(a[1]), "r"(a[2]), "r"(a[3]), "r"(b[0]), "r"(b[1]));
}

// --------- fused input conversion + edge counting (no separate k_count) ------
#define NXE (N_NODES * IN_F)     // 1048576
#define NW1 (F1 * IN_F)          // 524288
#define NW2 (F2 * F1)            // 655360
#define NSPLIT (NXE + NW1 + NW2)

__global__ void k_prep(const float* __restrict__ x, const float* __restrict__ W1,
                       const float* __restrict__ W2, const int* __restrict__ ei) {
    int i = blockIdx.x * blockDim.x + threadIdx.x;
    if (i < NE) atomicAdd(&g_counts[ei[NE + i]], 1);   // edge degree count
    if (i < NXE) {
        g_xf[i] = __float2half_rn(x[i]);               // single fp16 A operand
        return;
    }
    if (i < NXE + NW1) {
        int k = i - NXE;
        float v = W1[k];
        __half h = __float2half_rn(v);
        g_w1h[k] = h;
        g_w1l[k] = __float2half_rn(v - __half2float(h));
    } else if (i < NSPLIT) {
        int k = i - NXE - NW1;
        g_w2h[k] = __float2half_rn(W2[k]);             // single-term W2
    }
}

// ------------------------------ CSR scan (adds self-loop, resets counts) -----
__global__ void k_scan() {
    __shared__ int sh[1024];
    int t = threadIdx.x;
    int loc[8];
    int s = 0;
#pragma unroll
    for (int j = 0; j < 8; j++) {
        int idx = t * 8 + j;
        loc[j] = g_counts[idx] + 1;    // +1 self-loop
        g_counts[idx] = 0;             // reset for next call (graph replay)
        s += loc[j];
    }
    sh[t] = s;
    __syncthreads();
    for (int off = 1; off < 1024; off <<= 1) {
        int v = (t >= off) ? sh[t - off] : 0;
        __syncthreads();
        sh[t] += v;
        __syncthreads();
    }
    int run = (t == 0) ? 0 : sh[t - 1];
#pragma unroll
    for (int j = 0; j < 8; j++) {
        int idx = t * 8 + j;
        g_off[idx] = run;
        g_cursor[idx] = run;
        run += loc[j];
    }
    if (t == 1023) g_off[N_NODES] = run;
}

__global__ void k_scatter(const int* __restrict__ ei) {
    int i = blockIdx.x * blockDim.x + threadIdx.x;
    if (i >= ETOT) return;
    int src, dst;
    if (i < NE) { src = ei[i]; dst = ei[NE + i]; }
    else        { src = i - NE; dst = src; }
    int pos = atomicAdd(&g_cursor[dst], 1);
    g_csr_src[pos] = src;
}

// ------------------------------ GEMM1 (fp16 2-term + fused alpha) ------------
#define TSTRIDE 80                        // bytes per smem row (5 x 16B segs)
#define S1TILE  (128 * TSTRIDE)           // 10240 B
#define STAGE1  (3 * S1TILE)              // A, Bh, Bl
#define GEMM1_SMEM (2 * STAGE1)           // 61440 B

__global__ __launch_bounds__(256, 2)
void gemm1_mma(const __half* __restrict__ Af,
               const __half* __restrict__ Bh, const __half* __restrict__ Bl,
               __half* __restrict__ C,
               const float* __restrict__ att_s, const float* __restrict__ att_d) {
    extern __shared__ char smem[];
    const int N = F1, K = IN_F;
    const int tid = threadIdx.x;
    const int wid = tid >> 5, lane = tid & 31;
    const int m0 = blockIdx.y * 128, n0 = blockIdx.x * 128;
    const int wm = wid >> 1, wn = wid & 1;
    const int NC = K >> 5;                // 4
    const uint32_t sb = smem_u32(smem);

    float acc[2][8][4];
#pragma unroll
    for (int im = 0; im < 2; ++im)
#pragma unroll
        for (int j = 0; j < 8; ++j)
#pragma unroll
            for (int q = 0; q < 4; ++q) acc[im][j][q] = 0.f;

    auto load_stage = [&](int c, int s) {
        uint32_t base = sb + (uint32_t)s * STAGE1;
        const size_t kc = (size_t)c * 32;
#pragma unroll
        for (int i = tid; i < 512; i += 256) {
            int r = i >> 2, seg = i & 3;
            uint32_t off = (uint32_t)(r * TSTRIDE + seg * 16);
            cpa16(base + off, Af + (size_t)(m0 + r) * K + kc + seg * 8);
            const size_t gb = (size_t)(n0 + r) * K + kc + seg * 8;
            cpa16(base + S1TILE + off, Bh + gb);
            cpa16(base + 2 * S1TILE + off, Bl + gb);
        }
        cpa_commit();
    };

    load_stage(0, 0);
    for (int c = 0; c < NC; ++c) {
        if (c + 1 < NC) {
            load_stage(c + 1, (c + 1) & 1);
            cpa_wait<1>();
        } else {
            cpa_wait<0>();
        }
        __syncthreads();

        const uint32_t base = sb + (uint32_t)(c & 1) * STAGE1;
#pragma unroll
        for (int ks = 0; ks < 2; ++ks) {
            const uint32_t kb = ks * 32;
            uint32_t a[2][4], bh[4][4], bl[4][4];
#pragma unroll
            for (int im = 0; im < 2; ++im) {
                uint32_t ra = (uint32_t)((wm * 32 + im * 16 + (lane & 15)) * TSTRIDE)
                              + kb + ((lane >> 4) & 1) * 16;
                ldsm4(a[im], base + ra);
            }
#pragma unroll
            for (int p = 0; p < 4; ++p) {
                uint32_t rb = (uint32_t)((wn * 64 + p * 16 + ((lane >> 4) & 1) * 8 +
                                          (lane & 7)) * TSTRIDE)
                              + kb + ((lane >> 3) & 1) * 16;
                ldsm4(bh[p], base + S1TILE + rb);
                ldsm4(bl[p], base + 2 * S1TILE + rb);
            }
#pragma unroll
            for (int im = 0; im < 2; ++im)
#pragma unroll
                for (int j = 0; j < 8; ++j) {
                    mma16816h(acc[im][j], a[im], &bh[j >> 1][(j & 1) * 2]);
                    mma16816h(acc[im][j], a[im], &bl[j >> 1][(j & 1) * 2]);
                }
        }
        __syncthreads();
    }

    // epilogue 1: fp16 stores (pairs)
#pragma unroll
    for (int im = 0; im < 2; ++im)
#pragma unroll
        for (int j = 0; j < 8; ++j) {
            int gm = m0 + wm * 32 + im * 16 + (lane >> 2);
            int gn = n0 + wn * 64 + j * 8 + (lane & 3) * 2;
            __half2 v0 = __floats2half2_rn(acc[im][j][0], acc[im][j][1]);
            __half2 v1 = __floats2half2_rn(acc[im][j][2], acc[im][j][3]);
            *(__half2*)&C[(size_t)gm * N + gn] = v0;
            *(__half2*)&C[(size_t)(gm + 8) * N + gn] = v1;
        }

    // epilogue 2: fused attention dots for this CTA's (rows, head)
    const int head = (blockIdx.x << 1) + wn;   // this warp's head
    float as_att[16], ad_att[16];
#pragma unroll
    for (int j = 0; j < 8; ++j) {
        int cc = head * HID + j * 8 + (lane & 3) * 2;
        as_att[2 * j] = att_s[cc];     as_att[2 * j + 1] = att_s[cc + 1];
        ad_att[2 * j] = att_d[cc];     ad_att[2 * j + 1] = att_d[cc + 1];
    }
#pragma unroll
    for (int im = 0; im < 2; ++im) {
        float s0 = 0.f, s1 = 0.f, d0 = 0.f, d1 = 0.f;
#pragma unroll
        for (int j = 0; j < 8; ++j) {
            s0 += acc[im][j][0] * as_att[2 * j] + acc[im][j][1] * as_att[2 * j + 1];
            s1 += acc[im][j][2] * as_att[2 * j] + acc[im][j][3] * as_att[2 * j + 1];
            d0 += acc[im][j][0] * ad_att[2 * j] + acc[im][j][1] * ad_att[2 * j + 1];
            d1 += acc[im][j][2] * ad_att[2 * j] + acc[im][j][3] * ad_att[2 * j + 1];
        }
#pragma unroll
        for (int o = 1; o < 4; o <<= 1) {
            s0 += __shfl_xor_sync(0xffffffffu, s0, o);
            s1 += __shfl_xor_sync(0xffffffffu, s1, o);
            d0 += __shfl_xor_sync(0xffffffffu, d0, o);
            d1 += __shfl_xor_sync(0xffffffffu, d1, o);
        }
        if ((lane & 3) == 0) {
            int r = m0 + wm * 32 + im * 16 + (lane >> 2);
            g_as1[r * H1 + head] = s0;
            g_ad1[r * H1 + head] = d0;
            g_as1[(r + 8) * H1 + head] = s1;
            g_ad1[(r + 8) * H1 + head] = d1;
        }
    }
}

// ------------------------------ GEMM2 (split-K, BN=160, fp16 1-term) ---------
#define A2TILE (128 * TSTRIDE)            // 10240
#define B2TILE (160 * TSTRIDE)            // 12800
#define STAGE2 (A2TILE + B2TILE)          // 23040
#define GEMM2_SMEM (2 * STAGE2)           // 46080

__global__ __launch_bounds__(256, 2)
void gemm2_mma(const __half* __restrict__ Af, const __half* __restrict__ Bh,
               float* __restrict__ Cp) {
    extern __shared__ char smem[];
    const int K = F1;
    const int tid = threadIdx.x;
    const int wid = tid >> 5, lane = tid & 31;
    const int m0 = blockIdx.y * 128;
    const size_t kb0 = (size_t)blockIdx.z * KSLC;
    const int wm = wid >> 1, wn = wid & 1;
    const int NC = KSLC >> 5;             // 16
    const uint32_t sb = smem_u32(smem);

    float acc[2][10][4];
#pragma unroll
    for (int im = 0; im < 2; ++im)
#pragma unroll
        for (int j = 0; j < 10; ++j)
#pragma unroll
            for (int q = 0; q < 4; ++q) acc[im][j][q] = 0.f;

    auto load_stage = [&](int c, int s) {
        uint32_t base = sb + (uint32_t)s * STAGE2;
        const size_t kc = kb0 + (size_t)c * 32;
#pragma unroll
        for (int i = tid; i < 512; i += 256) {
            int r = i >> 2, seg = i & 3;
            uint32_t off = (uint32_t)(r * TSTRIDE + seg * 16);
            cpa16(base + off, Af + (size_t)(m0 + r) * K + kc + seg * 8);
        }
#pragma unroll
        for (int i = tid; i < 640; i += 256) {
            int r = i >> 2, seg = i & 3;
            uint32_t off = (uint32_t)(r * TSTRIDE + seg * 16);
            cpa16(base + A2TILE + off, Bh + (size_t)r * K + kc + seg * 8);
        }
        cpa_commit();
    };

    load_stage(0, 0);
    for (int c = 0; c < NC; ++c) {
        if (c + 1 < NC) {
            load_stage(c + 1, (c + 1) & 1);
            cpa_wait<1>();
        } else {
            cpa_wait<0>();
        }
        __syncthreads();

        const uint32_t base = sb + (uint32_t)(c & 1) * STAGE2;
#pragma unroll
        for (int ks = 0; ks < 2; ++ks) {
            const uint32_t kb = ks * 32;
            uint32_t a[2][4], bh[5][4];
#pragma unroll
            for (int im = 0; im < 2; ++im) {
                uint32_t ra = (uint32_t)((wm * 32 + im * 16 + (lane & 15)) * TSTRIDE)
                              + kb + ((lane >> 4) & 1) * 16;
                ldsm4(a[im], base + ra);
            }
#pragma unroll
            for (int p = 0; p < 5; ++p) {
                uint32_t rb = (uint32_t)((wn * 80 + p * 16 + ((lane >> 4) & 1) * 8 +
                                          (lane & 7)) * TSTRIDE)
                              + kb + ((lane >> 3) & 1) * 16;
                ldsm4(bh[p], base + A2TILE + rb);
            }
#pragma unroll
            for (int im = 0; im < 2; ++im)
#pragma unroll
                for (int j = 0; j < 10; ++j)
                    mma16816h(acc[im][j], a[im], &bh[j >> 1][(j & 1) * 2]);
        }
        __syncthreads();
    }

    float* out = Cp + (size_t)blockIdx.z * (N_NODES * F2);
#pragma unroll
    for (int im = 0; im < 2; ++im)
#pragma unroll
        for (int j = 0; j < 10; ++j) {
            int gm = m0 + wm * 32 + im * 16 + (lane >> 2);
            int gn = wn * 80 + j * 8 + (lane & 3) * 2;
            *(float2*)&out[(size_t)gm * F2 + gn] =
                make_float2(acc[im][j][0], acc[im][j][1]);
            *(float2*)&out[(size_t)(gm + 8) * F2 + gn] =
                make_float2(acc[im][j][2], acc[im][j][3]);
        }
}

// ------------- split-K reduce (deterministic) + fused alpha2 dots ------------
__global__ __launch_bounds__(160)
void k_reduce_alpha2(const float* __restrict__ att_s, const float* __restrict__ att_d) {
    const int n = blockIdx.x;
    const int t = threadIdx.x;          // 0..159
    const int lane = t & 31, head = t >> 5;
    float s = 0.f;
#pragma unroll
    for (int z = 0; z < KSPLIT; ++z)
        s += g_h2p[(size_t)z * (N_NODES * F2) + n * F2 + t];
    g_h2[n * F2 + t] = s;
    float vs = s * att_s[t];
    float vd = s * att_d[t];
#pragma unroll
    for (int o = 16; o > 0; o >>= 1) {
        vs += __shfl_down_sync(0xffffffffu, vs, o);
        vd += __shfl_down_sync(0xffffffffu, vd, o);
    }
    if (!lane) { g_as2[n * H2 + head] = vs; g_ad2[n * H2 + head] = vd; }
}

// ------------------------------ layer-1 aggregation + ELU + fp16 out ---------
__global__ __launch_bounds__(256)
void k_agg1(const float* __restrict__ b1) {
    const int n = blockIdx.x;
    const int t = threadIdx.x;
    const int start = g_off[n];
    const int deg = g_off[n + 1] - start;

    __shared__ float sh_m[H1], sh_den[H1], sh_ad[H1];
    __shared__ float sh_w[32 * H1];
    __shared__ int   s_src[32];
    __shared__ float pm[4][H1], pd[4][H1];

    // softmax max/denominator: 4-way parallel over edges, online per stripe
    {
        const int h = t & 63, quarter = t >> 6;
        float adv = g_ad1[n * H1 + h];
        float m = -1e30f, den = 0.f;
        for (int e = quarter; e < deg; e += 4) {
            int s = g_csr_src[start + e];
            float l = g_as1[s * H1 + h] + adv;
            l = l > 0.f ? l : 0.2f * l;
            if (l > m) { den = den * __expf(m - l) + 1.f; m = l; }
            else       { den += __expf(l - m); }
        }
        pm[quarter][h] = m;
        pd[quarter][h] = den;
        if (quarter == 0) sh_ad[h] = adv;
    }
    __syncthreads();
    if (t < H1) {
        float m0 = pm[0][t], m1 = pm[1][t], m2 = pm[2][t], m3 = pm[3][t];
        float M = fmaxf(fmaxf(m0, m1), fmaxf(m2, m3));
        float D = pd[0][t] * __expf(m0 - M) + pd[1][t] * __expf(m1 - M) +
                  pd[2][t] * __expf(m2 - M) + pd[3][t] * __expf(m3 - M);
        sh_m[t] = M; sh_den[t] = D;
    }
    __syncthreads();

    float acc[16];
#pragma unroll
    for (int i = 0; i < 16; i++) acc[i] = 0.f;
    const int h = t >> 2;  // head of this thread's 16-feature slice

    for (int e0 = 0; e0 < deg; e0 += 32) {
        int ce = min(32, deg - e0);
        if (t < ce) s_src[t] = g_csr_src[start + e0 + t];
        __syncthreads();
        for (int k = t; k < ce * H1; k += 256) {
            int e = k >> 6, hh = k & 63;
            float l = g_as1[s_src[e] * H1 + hh] + sh_ad[hh];
            l = l > 0.f ? l : 0.2f * l;
            sh_w[k] = __expf(l - sh_m[hh]);
        }
        __syncthreads();
        for (int e = 0; e < ce; e++) {
            const uint4* hp = reinterpret_cast<const uint4*>(
                g_h1 + (size_t)s_src[e] * F1 + t * 16);
            float wv = sh_w[(e << 6) + h];
#pragma unroll
            for (int q = 0; q < 2; q++) {
                uint4 u = hp[q];
                float2 f0 = __half22float2(*(const __half2*)&u.x);
                float2 f1 = __half22float2(*(const __half2*)&u.y);
                float2 f2 = __half22float2(*(const __half2*)&u.z);
                float2 f3 = __half22float2(*(const __half2*)&u.w);
                acc[8 * q + 0] += wv * f0.x;
                acc[8 * q + 1] += wv * f0.y;
                acc[8 * q + 2] += wv * f1.x;
                acc[8 * q + 3] += wv * f1.y;
                acc[8 * q + 4] += wv * f2.x;
                acc[8 * q + 5] += wv * f2.y;
                acc[8 * q + 6] += wv * f3.x;
                acc[8 * q + 7] += wv * f3.y;
            }
        }
        __syncthreads();
    }

    float invden = 1.f / sh_den[h];
    const float4* bp = reinterpret_cast<const float4*>(b1 + t * 16);
    float vals[16];
#pragma unroll
    for (int q = 0; q < 4; q++) {
        float4 bv = bp[q];
        float v0 = acc[4 * q + 0] * invden + bv.x;
        float v1 = acc[4 * q + 1] * invden + bv.y;
        float v2 = acc[4 * q + 2] * invden + bv.z;
        float v3 = acc[4 * q + 3] * invden + bv.w;
        vals[4 * q + 0] = v0 > 0.f ? v0 : __expf(v0) - 1.f;
        vals[4 * q + 1] = v1 > 0.f ? v1 : __expf(v1) - 1.f;
        vals[4 * q + 2] = v2 > 0.f ? v2 : __expf(v2) - 1.f;
        vals[4 * q + 3] = v3 > 0.f ? v3 : __expf(v3) - 1.f;
    }
    uint32_t pk[8];
#pragma unroll
    for (int i = 0; i < 8; i++) {
        __half2 hv = __floats2half2_rn(vals[2 * i], vals[2 * i + 1]);
        pk[i] = *reinterpret_cast<uint32_t*>(&hv);
    }
    size_t off = (size_t)n * F1 + t * 16;
    uint4* op = reinterpret_cast<uint4*>(g_x1 + off);
    op[0] = make_uint4(pk[0], pk[1], pk[2], pk[3]);
    op[1] = make_uint4(pk[4], pk[5], pk[6], pk[7]);
}

// ------------------------------ layer-2 aggregation + head mean --------------
__global__ __launch_bounds__(192)
void k_agg2(const float* __restrict__ b2) {
    const int n = blockIdx.x;
    const int t = threadIdx.x;
    const int start = g_off[n];
    const int deg = g_off[n + 1] - start;

    __shared__ float sh_m[H2], sh_den[H2], sh_ad[H2];
    __shared__ float sh_r[F2];

    if (t < H2) {
        float adv = g_ad2[n * H2 + t];
        float m = -1e30f;
        for (int e = 0; e < deg; e++) {
            int s = g_csr_src[start + e];
            float l = g_as2[s * H2 + t] + adv;
            l = l > 0.f ? l : 0.2f * l;
            m = fmaxf(m, l);
        }
        float den = 0.f;
        for (int e = 0; e < deg; e++) {
            int s = g_csr_src[start + e];
            float l = g_as2[s * H2 + t] + adv;
            l = l > 0.f ? l : 0.2f * l;
            den += __expf(l - m);
        }
        sh_m[t] = m; sh_den[t] = den; sh_ad[t] = adv;
    }
    __syncthreads();

    if (t < F2) {
        int hh = t >> 5;
        float m = sh_m[hh], adv = sh_ad[hh];
        float acc = 0.f;
        for (int e = 0; e < deg; e++) {
            int s = g_csr_src[start + e];
            float l = g_as2[s * H2 + hh] + adv;
            l = l > 0.f ? l : 0.2f * l;
            acc += __expf(l - m) * g_h2[s * F2 + t];
        }
        sh_r[t] = acc / sh_den[hh];
    }
    __syncthreads();

    if (t < OUTF) {
        float v = (sh_r[t] + sh_r[32 + t] + sh_r[64 + t] + sh_r[96 + t] +
                   sh_r[128 + t]) * 0.2f + b2[t];
        g_x2[n * OUTF + t] = v;
    }
}

// ------------------------------ bond scores + softmax ------------------------
__global__ void k_score(const int* __restrict__ lefts,
                        const int* __restrict__ rights,
                        float* __restrict__ out) {
    __shared__ float sm[NB];
    int t = threadIdx.x;
    int l = lefts[t], r = rights[t];
    float s = 0.f;
#pragma unroll
    for (int c = 0; c < OUTF; c++) s += g_x2[l * OUTF + c] + g_x2[r * OUTF + c];
    sm[t] = s;
    __syncthreads();
    float mx = -1e30f;
    for (int j = 0; j < NB; j++) mx = fmaxf(mx, sm[j]);
    float e = __expf(s - mx);
    __syncthreads();
    sm[t] = e;
    __syncthreads();
    float sum = 0.f;
    for (int j = 0; j < NB; j++) sum += sm[j];
    out[t] = e / sum;
}

// ------------------------------ launch ---------------------------------------
extern "C" void kernel_launch(void* const* d_in, const int* in_sizes, int n_in,
                              void* d_out, int out_size) {
    const float* x   = (const float*)d_in[0];
    const int*   ei  = (const int*)d_in[1];
    const int*   lf  = (const int*)d_in[2];
    const int*   rt  = (const int*)d_in[3];
    const float* W1  = (const float*)d_in[4];
    const float* as1 = (const float*)d_in[5];
    const float* ad1 = (const float*)d_in[6];
    const float* b1  = (const float*)d_in[7];
    const float* W2  = (const float*)d_in[8];
    const float* as2 = (const float*)d_in[9];
    const float* ad2 = (const float*)d_in[10];
    const float* b2  = (const float*)d_in[11];
    float* out = (float*)d_out;

    cudaFuncSetAttribute(gemm1_mma, cudaFuncAttributeMaxDynamicSharedMemorySize,
                         GEMM1_SMEM);
    cudaFuncSetAttribute(gemm2_mma, cudaFuncAttributeMaxDynamicSharedMemorySize,
                         GEMM2_SMEM);

    void *p_xf, *p_w1h, *p_w1l, *p_w2h;
    void *p_h1, *p_h2p, *p_x1;
    cudaGetSymbolAddress(&p_xf, g_xf);
    cudaGetSymbolAddress(&p_w1h, g_w1h);
    cudaGetSymbolAddress(&p_w1l, g_w1l);
    cudaGetSymbolAddress(&p_w2h, g_w2h);
    cudaGetSymbolAddress(&p_h1, g_h1);
    cudaGetSymbolAddress(&p_h2p, g_h2p);
    cudaGetSymbolAddress(&p_x1, g_x1);

    // fused input conversions + edge counting
    k_prep<<<(NSPLIT + 255) / 256, 256>>>(x, W1, W2, ei);

    // CSR by destination (scan adds self-loops, resets counts)
    k_scan<<<1, 1024>>>();
    k_scatter<<<(ETOT + 255) / 256, 256>>>(ei);

    // layer 1: h1 = x @ W1^T (fp16 out) + fused alpha1
    gemm1_mma<<<dim3(F1 / 128, N_NODES / 128), 256, GEMM1_SMEM>>>(
        (const __half*)p_xf, (const __half*)p_w1h, (const __half*)p_w1l,
        (__half*)p_h1, as1, ad1);
    k_agg1<<<N_NODES, 256>>>(b1);

    // layer 2: h2 = x1 @ W2^T, split-K x8 + fused reduce/alpha2
    gemm2_mma<<<dim3(1, N_NODES / 128, KSPLIT), 256, GEMM2_SMEM>>>(
        (const __half*)p_x1, (const __half*)p_w2h, (float*)p_h2p);
    k_reduce_alpha2<<<N_NODES, 160>>>(as2, ad2);
    k_agg2<<<N_NODES, 192>>>(b2);

    // bonds
    k_score<<<1, NB>>>(lf, rt, out);
}

// round 9
// speedup vs baseline: 8.4027x; 1.0909x over previous
#include <cuda_runtime.h>
#include <cuda_bf16.h>
#include <cuda_fp16.h>
#include <stdint.h>
#include <math.h>

#define N_NODES 8192
#define NE      49152
#define ETOT    (NE + N_NODES)       // 57344
#define IN_F    128
#define H1      64
#define HID     64
#define F1      (H1*HID)             // 4096
#define H2      5
#define OUTF    32
#define F2      (H2*OUTF)            // 160
#define NB      64
#define KSPLIT  4
#define KSLC    (F1 / KSPLIT)        // 1024

// ------------------------------ scratch (static, no allocation) --------------
__device__ __half g_h1[(size_t)N_NODES * F1];                // 67 MB
__device__ __half g_x1[(size_t)N_NODES * F1];                // 67 MB
__device__ __half g_xf[N_NODES * IN_F];
__device__ __half g_w1h[F1 * IN_F];
__device__ __half g_w2h[F2 * F1];
__device__ float g_as1[N_NODES * H1];
__device__ float g_ad1[N_NODES * H1];
__device__ float g_h2p[(size_t)KSPLIT * N_NODES * F2];       // 21 MB partials
__device__ float g_h2[N_NODES * F2];
__device__ float g_as2[N_NODES * H2];
__device__ float g_ad2[N_NODES * H2];
__device__ float g_x2[N_NODES * OUTF];
__device__ int   g_counts[N_NODES];   // zero at start of every call (scan resets)
__device__ int   g_off[N_NODES + 1];
__device__ int   g_cursor[N_NODES];
__device__ int   g_csr_src[ETOT];

// ------------------------------ PTX helpers ----------------------------------
__device__ __forceinline__ uint32_t smem_u32(const void* p) {
    uint32_t a;
    asm("{ .reg .u64 t; cvta.to.shared.u64 t, %1; cvt.u32.u64 %0, t; }"
        : "=r"(a) : "l"(p));
    return a;
}

__device__ __forceinline__ void cpa16(uint32_t d, const void* s) {
    asm volatile("cp.async.cg.shared.global [%0], [%1], 16;" :: "r"(d), "l"(s));
}
__device__ __forceinline__ void cpa_commit() {
    asm volatile("cp.async.commit_group;" ::: "memory");
}
template <int N> __device__ __forceinline__ void cpa_wait() {
    asm volatile("cp.async.wait_group %0;" :: "n"(N) : "memory");
}

__device__ __forceinline__ void ldsm4(uint32_t* r, uint32_t addr) {
    asm volatile("ldmatrix.sync.aligned.m8n8.x4.shared.b16 {%0,%1,%2,%3}, [%4];"
                 : "=r"(r[0]), "=r"(r[1]), "=r"(r[2]), "=r"(r[3]) : "r"(addr));
}

__device__ __forceinline__ void mma16816h(float* c, const uint32_t* a,
                                          const uint32_t* b) {
    asm volatile(
        "mma.sync.aligned.m16n8k16.row.col.f32.f16.f16.f32 "
        "{%0,%1,%2,%3}, {%4,%5,%6,%7}, {%8,%9}, {%0,%1,%2,%3};"
        : "+f"(c[0]), "+f"(c[1]), "+f"(c[2]), "+f"(c[3])
        : "r"(a[0]), "r"(a[1]), "r"(a[2]), "r"(a[3]), "r"(b[0]), "r"(b[1]));
}

// --------- fused input conversion + edge counting ----------------------------
#define NXE (N_NODES * IN_F)     // 1048576
#define NW1 (F1 * IN_F)          // 524288
#define NW2 (F2 * F1)            // 655360
#define NSPLIT (NXE + NW1 + NW2)

__global__ void k_prep(const float* __restrict__ x, const float* __restrict__ W1,
                       const float* __restrict__ W2, const int* __restrict__ ei) {
    int i = blockIdx.x * blockDim.x + threadIdx.x;
    if (i < NE) atomicAdd(&g_counts[ei[NE + i]], 1);   // edge degree count
    if (i < NXE) {
        g_xf[i] = __float2half_rn(x[i]);
        return;
    }
    if (i < NXE + NW1) {
        int k = i - NXE;
        g_w1h[k] = __float2half_rn(W1[k]);             // single-term W1
    } else if (i < NSPLIT) {
        int k = i - NXE - NW1;
        g_w2h[k] = __float2half_rn(W2[k]);             // single-term W2
    }
}

// ------------------------------ CSR scan (adds self-loop, resets counts) -----
__global__ void k_scan() {
    __shared__ int sh[1024];
    int t = threadIdx.x;
    int loc[8];
    int s = 0;
#pragma unroll
    for (int j = 0; j < 8; j++) {
        int idx = t * 8 + j;
        loc[j] = g_counts[idx] + 1;    // +1 self-loop
        g_counts[idx] = 0;             // reset for next call (graph replay)
        s += loc[j];
    }
    sh[t] = s;
    __syncthreads();
    for (int off = 1; off < 1024; off <<= 1) {
        int v = (t >= off) ? sh[t - off] : 0;
        __syncthreads();
        sh[t] += v;
        __syncthreads();
    }
    int run = (t == 0) ? 0 : sh[t - 1];
#pragma unroll
    for (int j = 0; j < 8; j++) {
        int idx = t * 8 + j;
        g_off[idx] = run;
        g_cursor[idx] = run;
        run += loc[j];
    }
    if (t == 1023) g_off[N_NODES] = run;
}

__global__ void k_scatter(const int* __restrict__ ei) {
    int i = blockIdx.x * blockDim.x + threadIdx.x;
    if (i >= ETOT) return;
    int src, dst;
    if (i < NE) { src = ei[i]; dst = ei[NE + i]; }
    else        { src = i - NE; dst = src; }
    int pos = atomicAdd(&g_cursor[dst], 1);
    g_csr_src[pos] = src;
}

// ------------------------------ GEMM1 (fp16 1-term + fused alpha) ------------
#define TSTRIDE 80                        // bytes per smem row (5 x 16B segs)
#define S1TILE  (128 * TSTRIDE)           // 10240 B
#define STAGE1  (2 * S1TILE)              // A, B
#define GEMM1_SMEM (2 * STAGE1)           // 40960 B

__global__ __launch_bounds__(256, 2)
void gemm1_mma(const __half* __restrict__ Af, const __half* __restrict__ Bh,
               __half* __restrict__ C,
               const float* __restrict__ att_s, const float* __restrict__ att_d) {
    extern __shared__ char smem[];
    const int N = F1, K = IN_F;
    const int tid = threadIdx.x;
    const int wid = tid >> 5, lane = tid & 31;
    const int m0 = blockIdx.y * 128, n0 = blockIdx.x * 128;
    const int wm = wid >> 1, wn = wid & 1;
    const int NC = K >> 5;                // 4
    const uint32_t sb = smem_u32(smem);

    float acc[2][8][4];
#pragma unroll
    for (int im = 0; im < 2; ++im)
#pragma unroll
        for (int j = 0; j < 8; ++j)
#pragma unroll
            for (int q = 0; q < 4; ++q) acc[im][j][q] = 0.f;

    auto load_stage = [&](int c, int s) {
        uint32_t base = sb + (uint32_t)s * STAGE1;
        const size_t kc = (size_t)c * 32;
#pragma unroll
        for (int i = tid; i < 512; i += 256) {
            int r = i >> 2, seg = i & 3;
            uint32_t off = (uint32_t)(r * TSTRIDE + seg * 16);
            cpa16(base + off, Af + (size_t)(m0 + r) * K + kc + seg * 8);
            cpa16(base + S1TILE + off, Bh + (size_t)(n0 + r) * K + kc + seg * 8);
        }
        cpa_commit();
    };

    load_stage(0, 0);
    for (int c = 0; c < NC; ++c) {
        if (c + 1 < NC) {
            load_stage(c + 1, (c + 1) & 1);
            cpa_wait<1>();
        } else {
            cpa_wait<0>();
        }
        __syncthreads();

        const uint32_t base = sb + (uint32_t)(c & 1) * STAGE1;
#pragma unroll
        for (int ks = 0; ks < 2; ++ks) {
            const uint32_t kb = ks * 32;
            uint32_t a[2][4], bh[4][4];
#pragma unroll
            for (int im = 0; im < 2; ++im) {
                uint32_t ra = (uint32_t)((wm * 32 + im * 16 + (lane & 15)) * TSTRIDE)
                              + kb + ((lane >> 4) & 1) * 16;
                ldsm4(a[im], base + ra);
            }
#pragma unroll
            for (int p = 0; p < 4; ++p) {
                uint32_t rb = (uint32_t)((wn * 64 + p * 16 + ((lane >> 4) & 1) * 8 +
                                          (lane & 7)) * TSTRIDE)
                              + kb + ((lane >> 3) & 1) * 16;
                ldsm4(bh[p], base + S1TILE + rb);
            }
#pragma unroll
            for (int im = 0; im < 2; ++im)
#pragma unroll
                for (int j = 0; j < 8; ++j)
                    mma16816h(acc[im][j], a[im], &bh[j >> 1][(j & 1) * 2]);
        }
        __syncthreads();
    }

    // epilogue 1: fp16 stores (pairs)
#pragma unroll
    for (int im = 0; im < 2; ++im)
#pragma unroll
        for (int j = 0; j < 8; ++j) {
            int gm = m0 + wm * 32 + im * 16 + (lane >> 2);
            int gn = n0 + wn * 64 + j * 8 + (lane & 3) * 2;
            __half2 v0 = __floats2half2_rn(acc[im][j][0], acc[im][j][1]);
            __half2 v1 = __floats2half2_rn(acc[im][j][2], acc[im][j][3]);
            *(__half2*)&C[(size_t)gm * N + gn] = v0;
            *(__half2*)&C[(size_t)(gm + 8) * N + gn] = v1;
        }

    // epilogue 2: fused attention dots for this CTA's (rows, head)
    const int head = (blockIdx.x << 1) + wn;   // this warp's head
    float as_att[16], ad_att[16];
#pragma unroll
    for (int j = 0; j < 8; ++j) {
        int cc = head * HID + j * 8 + (lane & 3) * 2;
        as_att[2 * j] = att_s[cc];     as_att[2 * j + 1] = att_s[cc + 1];
        ad_att[2 * j] = att_d[cc];     ad_att[2 * j + 1] = att_d[cc + 1];
    }
#pragma unroll
    for (int im = 0; im < 2; ++im) {
        float s0 = 0.f, s1 = 0.f, d0 = 0.f, d1 = 0.f;
#pragma unroll
        for (int j = 0; j < 8; ++j) {
            s0 += acc[im][j][0] * as_att[2 * j] + acc[im][j][1] * as_att[2 * j + 1];
            s1 += acc[im][j][2] * as_att[2 * j] + acc[im][j][3] * as_att[2 * j + 1];
            d0 += acc[im][j][0] * ad_att[2 * j] + acc[im][j][1] * ad_att[2 * j + 1];
            d1 += acc[im][j][2] * ad_att[2 * j] + acc[im][j][3] * ad_att[2 * j + 1];
        }
#pragma unroll
        for (int o = 1; o < 4; o <<= 1) {
            s0 += __shfl_xor_sync(0xffffffffu, s0, o);
            s1 += __shfl_xor_sync(0xffffffffu, s1, o);
            d0 += __shfl_xor_sync(0xffffffffu, d0, o);
            d1 += __shfl_xor_sync(0xffffffffu, d1, o);
        }
        if ((lane & 3) == 0) {
            int r = m0 + wm * 32 + im * 16 + (lane >> 2);
            g_as1[r * H1 + head] = s0;
            g_ad1[r * H1 + head] = d0;
            g_as1[(r + 8) * H1 + head] = s1;
            g_ad1[(r + 8) * H1 + head] = d1;
        }
    }
}

// ------------------------------ GEMM2 (split-K x4, BN=160, fp16 1-term) ------
#define A2TILE (128 * TSTRIDE)            // 10240
#define B2TILE (160 * TSTRIDE)            // 12800
#define STAGE2 (A2TILE + B2TILE)          // 23040
#define GEMM2_SMEM (2 * STAGE2)           // 46080

__global__ __launch_bounds__(256, 2)
void gemm2_mma(const __half* __restrict__ Af, const __half* __restrict__ Bh,
               float* __restrict__ Cp) {
    extern __shared__ char smem[];
    const int K = F1;
    const int tid = threadIdx.x;
    const int wid = tid >> 5, lane = tid & 31;
    const int m0 = blockIdx.y * 128;
    const size_t kb0 = (size_t)blockIdx.z * KSLC;
    const int wm = wid >> 1, wn = wid & 1;
    const int NC = KSLC >> 5;             // 32
    const uint32_t sb = smem_u32(smem);

    float acc[2][10][4];
#pragma unroll
    for (int im = 0; im < 2; ++im)
#pragma unroll
        for (int j = 0; j < 10; ++j)
#pragma unroll
            for (int q = 0; q < 4; ++q) acc[im][j][q] = 0.f;

    auto load_stage = [&](int c, int s) {
        uint32_t base = sb + (uint32_t)s * STAGE2;
        const size_t kc = kb0 + (size_t)c * 32;
#pragma unroll
        for (int i = tid; i < 512; i += 256) {
            int r = i >> 2, seg = i & 3;
            uint32_t off = (uint32_t)(r * TSTRIDE + seg * 16);
            cpa16(base + off, Af + (size_t)(m0 + r) * K + kc + seg * 8);
        }
#pragma unroll
        for (int i = tid; i < 640; i += 256) {
            int r = i >> 2, seg = i & 3;
            uint32_t off = (uint32_t)(r * TSTRIDE + seg * 16);
            cpa16(base + A2TILE + off, Bh + (size_t)r * K + kc + seg * 8);
        }
        cpa_commit();
    };

    load_stage(0, 0);
    for (int c = 0; c < NC; ++c) {
        if (c + 1 < NC) {
            load_stage(c + 1, (c + 1) & 1);
            cpa_wait<1>();
        } else {
            cpa_wait<0>();
        }
        __syncthreads();

        const uint32_t base = sb + (uint32_t)(c & 1) * STAGE2;
#pragma unroll
        for (int ks = 0; ks < 2; ++ks) {
            const uint32_t kb = ks * 32;
            uint32_t a[2][4], bh[5][4];
#pragma unroll
            for (int im = 0; im < 2; ++im) {
                uint32_t ra = (uint32_t)((wm * 32 + im * 16 + (lane & 15)) * TSTRIDE)
                              + kb + ((lane >> 4) & 1) * 16;
                ldsm4(a[im], base + ra);
            }
#pragma unroll
            for (int p = 0; p < 5; ++p) {
                uint32_t rb = (uint32_t)((wn * 80 + p * 16 + ((lane >> 4) & 1) * 8 +
                                          (lane & 7)) * TSTRIDE)
                              + kb + ((lane >> 3) & 1) * 16;
                ldsm4(bh[p], base + A2TILE + rb);
            }
#pragma unroll
            for (int im = 0; im < 2; ++im)
#pragma unroll
                for (int j = 0; j < 10; ++j)
                    mma16816h(acc[im][j], a[im], &bh[j >> 1][(j & 1) * 2]);
        }
        __syncthreads();
    }

    float* out = Cp + (size_t)blockIdx.z * (N_NODES * F2);
#pragma unroll
    for (int im = 0; im < 2; ++im)
#pragma unroll
        for (int j = 0; j < 10; ++j) {
            int gm = m0 + wm * 32 + im * 16 + (lane >> 2);
            int gn = wn * 80 + j * 8 + (lane & 3) * 2;
            *(float2*)&out[(size_t)gm * F2 + gn] =
                make_float2(acc[im][j][0], acc[im][j][1]);
            *(float2*)&out[(size_t)(gm + 8) * F2 + gn] =
                make_float2(acc[im][j][2], acc[im][j][3]);
        }
}

// ------------- split-K reduce (deterministic) + fused alpha2 dots ------------
__global__ __launch_bounds__(160)
void k_reduce_alpha2(const float* __restrict__ att_s, const float* __restrict__ att_d) {
    const int n = blockIdx.x;
    const int t = threadIdx.x;          // 0..159
    const int lane = t & 31, head = t >> 5;
    float s = 0.f;
#pragma unroll
    for (int z = 0; z < KSPLIT; ++z)
        s += g_h2p[(size_t)z * (N_NODES * F2) + n * F2 + t];
    g_h2[n * F2 + t] = s;
    float vs = s * att_s[t];
    float vd = s * att_d[t];
#pragma unroll
    for (int o = 16; o > 0; o >>= 1) {
        vs += __shfl_down_sync(0xffffffffu, vs, o);
        vd += __shfl_down_sync(0xffffffffu, vd, o);
    }
    if (!lane) { g_as2[n * H2 + head] = vs; g_ad2[n * H2 + head] = vd; }
}

// ------------------------------ layer-1 aggregation + ELU + fp16 out ---------
__global__ __launch_bounds__(256)
void k_agg1(const float* __restrict__ b1) {
    const int n = blockIdx.x;
    const int t = threadIdx.x;
    const int start = g_off[n];
    const int deg = g_off[n + 1] - start;

    __shared__ float sh_m[H1], sh_den[H1], sh_ad[H1];
    __shared__ float sh_w[32 * H1];
    __shared__ int   s_src[32];
    __shared__ float pm[4][H1], pd[4][H1];

    // softmax max/denominator: 4-way parallel over edges, online per stripe
    {
        const int h = t & 63, quarter = t >> 6;
        float adv = g_ad1[n * H1 + h];
        float m = -1e30f, den = 0.f;
        for (int e = quarter; e < deg; e += 4) {
            int s = g_csr_src[start + e];
            float l = g_as1[s * H1 + h] + adv;
            l = l > 0.f ? l : 0.2f * l;
            if (l > m) { den = den * __expf(m - l) + 1.f; m = l; }
            else       { den += __expf(l - m); }
        }
        pm[quarter][h] = m;
        pd[quarter][h] = den;
        if (quarter == 0) sh_ad[h] = adv;
    }
    __syncthreads();
    if (t < H1) {
        float m0 = pm[0][t], m1 = pm[1][t], m2 = pm[2][t], m3 = pm[3][t];
        float M = fmaxf(fmaxf(m0, m1), fmaxf(m2, m3));
        float D = pd[0][t] * __expf(m0 - M) + pd[1][t] * __expf(m1 - M) +
                  pd[2][t] * __expf(m2 - M) + pd[3][t] * __expf(m3 - M);
        sh_m[t] = M; sh_den[t] = D;
    }
    __syncthreads();

    float acc[16];
#pragma unroll
    for (int i = 0; i < 16; i++) acc[i] = 0.f;
    const int h = t >> 2;  // head of this thread's 16-feature slice

    for (int e0 = 0; e0 < deg; e0 += 32) {
        int ce = min(32, deg - e0);
        if (t < ce) s_src[t] = g_csr_src[start + e0 + t];
        __syncthreads();
        for (int k = t; k < ce * H1; k += 256) {
            int e = k >> 6, hh = k & 63;
            float l = g_as1[s_src[e] * H1 + hh] + sh_ad[hh];
            l = l > 0.f ? l : 0.2f * l;
            sh_w[k] = __expf(l - sh_m[hh]);
        }
        __syncthreads();
        for (int e = 0; e < ce; e++) {
            const uint4* hp = reinterpret_cast<const uint4*>(
                g_h1 + (size_t)s_src[e] * F1 + t * 16);
            float wv = sh_w[(e << 6) + h];
#pragma unroll
            for (int q = 0; q < 2; q++) {
                uint4 u = hp[q];
                float2 f0 = __half22float2(*(const __half2*)&u.x);
                float2 f1 = __half22float2(*(const __half2*)&u.y);
                float2 f2 = __half22float2(*(const __half2*)&u.z);
                float2 f3 = __half22float2(*(const __half2*)&u.w);
                acc[8 * q + 0] += wv * f0.x;
                acc[8 * q + 1] += wv * f0.y;
                acc[8 * q + 2] += wv * f1.x;
                acc[8 * q + 3] += wv * f1.y;
                acc[8 * q + 4] += wv * f2.x;
                acc[8 * q + 5] += wv * f2.y;
                acc[8 * q + 6] += wv * f3.x;
                acc[8 * q + 7] += wv * f3.y;
            }
        }
        __syncthreads();
    }

    float invden = 1.f / sh_den[h];
    const float4* bp = reinterpret_cast<const float4*>(b1 + t * 16);
    float vals[16];
#pragma unroll
    for (int q = 0; q < 4; q++) {
        float4 bv = bp[q];
        float v0 = acc[4 * q + 0] * invden + bv.x;
        float v1 = acc[4 * q + 1] * invden + bv.y;
        float v2 = acc[4 * q + 2] * invden + bv.z;
        float v3 = acc[4 * q + 3] * invden + bv.w;
        vals[4 * q + 0] = v0 > 0.f ? v0 : __expf(v0) - 1.f;
        vals[4 * q + 1] = v1 > 0.f ? v1 : __expf(v1) - 1.f;
        vals[4 * q + 2] = v2 > 0.f ? v2 : __expf(v2) - 1.f;
        vals[4 * q + 3] = v3 > 0.f ? v3 : __expf(v3) - 1.f;
    }
    uint32_t pk[8];
#pragma unroll
    for (int i = 0; i < 8; i++) {
        __half2 hv = __floats2half2_rn(vals[2 * i], vals[2 * i + 1]);
        pk[i] = *reinterpret_cast<uint32_t*>(&hv);
    }
    size_t off = (size_t)n * F1 + t * 16;
    uint4* op = reinterpret_cast<uint4*>(g_x1 + off);
    op[0] = make_uint4(pk[0], pk[1], pk[2], pk[3]);
    op[1] = make_uint4(pk[4], pk[5], pk[6], pk[7]);
}

// ------------------------------ layer-2 aggregation + head mean --------------
__global__ __launch_bounds__(192)
void k_agg2(const float* __restrict__ b2) {
    const int n = blockIdx.x;
    const int t = threadIdx.x;
    const int start = g_off[n];
    const int deg = g_off[n + 1] - start;

    __shared__ float sh_m[H2], sh_den[H2], sh_ad[H2];
    __shared__ float sh_r[F2];

    if (t < H2) {
        float adv = g_ad2[n * H2 + t];
        float m = -1e30f;
        for (int e = 0; e < deg; e++) {
            int s = g_csr_src[start + e];
            float l = g_as2[s * H2 + t] + adv;
            l = l > 0.f ? l : 0.2f * l;
            m = fmaxf(m, l);
        }
        float den = 0.f;
        for (int e = 0; e < deg; e++) {
            int s = g_csr_src[start + e];
            float l = g_as2[s * H2 + t] + adv;
            l = l > 0.f ? l : 0.2f * l;
            den += __expf(l - m);
        }
        sh_m[t] = m; sh_den[t] = den; sh_ad[t] = adv;
    }
    __syncthreads();

    if (t < F2) {
        int hh = t >> 5;
        float m = sh_m[hh], adv = sh_ad[hh];
        float acc = 0.f;
        for (int e = 0; e < deg; e++) {
            int s = g_csr_src[start + e];
            float l = g_as2[s * H2 + hh] + adv;
            l = l > 0.f ? l : 0.2f * l;
            acc += __expf(l - m) * g_h2[s * F2 + t];
        }
        sh_r[t] = acc / sh_den[hh];
    }
    __syncthreads();

    if (t < OUTF) {
        float v = (sh_r[t] + sh_r[32 + t] + sh_r[64 + t] + sh_r[96 + t] +
                   sh_r[128 + t]) * 0.2f + b2[t];
        g_x2[n * OUTF + t] = v;
    }
}

// ------------------------------ bond scores + softmax ------------------------
__global__ void k_score(const int* __restrict__ lefts,
                        const int* __restrict__ rights,
                        float* __restrict__ out) {
    __shared__ float sm[NB];
    int t = threadIdx.x;
    int l = lefts[t], r = rights[t];
    float s = 0.f;
#pragma unroll
    for (int c = 0; c < OUTF; c++) s += g_x2[l * OUTF + c] + g_x2[r * OUTF + c];
    sm[t] = s;
    __syncthreads();
    float mx = -1e30f;
    for (int j = 0; j < NB; j++) mx = fmaxf(mx, sm[j]);
    float e = __expf(s - mx);
    __syncthreads();
    sm[t] = e;
    __syncthreads();
    float sum = 0.f;
    for (int j = 0; j < NB; j++) sum += sm[j];
    out[t] = e / sum;
}

// ------------------------------ launch ---------------------------------------
extern "C" void kernel_launch(void* const* d_in, const int* in_sizes, int n_in,
                              void* d_out, int out_size) {
    const float* x   = (const float*)d_in[0];
    const int*   ei  = (const int*)d_in[1];
    const int*   lf  = (const int*)d_in[2];
    const int*   rt  = (const int*)d_in[3];
    const float* W1  = (const float*)d_in[4];
    const float* as1 = (const float*)d_in[5];
    const float* ad1 = (const float*)d_in[6];
    const float* b1  = (const float*)d_in[7];
    const float* W2  = (const float*)d_in[8];
    const float* as2 = (const float*)d_in[9];
    const float* ad2 = (const float*)d_in[10];
    const float* b2  = (const float*)d_in[11];
    float* out = (float*)d_out;

    cudaFuncSetAttribute(gemm1_mma, cudaFuncAttributeMaxDynamicSharedMemorySize,
                         GEMM1_SMEM);
    cudaFuncSetAttribute(gemm2_mma, cudaFuncAttributeMaxDynamicSharedMemorySize,
                         GEMM2_SMEM);

    void *p_xf, *p_w1h, *p_w2h;
    void *p_h1, *p_h2p, *p_x1;
    cudaGetSymbolAddress(&p_xf, g_xf);
    cudaGetSymbolAddress(&p_w1h, g_w1h);
    cudaGetSymbolAddress(&p_w2h, g_w2h);
    cudaGetSymbolAddress(&p_h1, g_h1);
    cudaGetSymbolAddress(&p_h2p, g_h2p);
    cudaGetSymbolAddress(&p_x1, g_x1);

    // fused input conversions + edge counting
    k_prep<<<(NSPLIT + 255) / 256, 256>>>(x, W1, W2, ei);

    // CSR by destination (scan adds self-loops, resets counts)
    k_scan<<<1, 1024>>>();
    k_scatter<<<(ETOT + 255) / 256, 256>>>(ei);

    // layer 1: h1 = x @ W1^T (fp16 out) + fused alpha1
    gemm1_mma<<<dim3(F1 / 128, N_NODES / 128), 256, GEMM1_SMEM>>>(
        (const __half*)p_xf, (const __half*)p_w1h, (__half*)p_h1, as1, ad1);
    k_agg1<<<N_NODES, 256>>>(b1);

    // layer 2: h2 = x1 @ W2^T, split-K x4 + fused reduce/alpha2
    gemm2_mma<<<dim3(1, N_NODES / 128, KSPLIT), 256, GEMM2_SMEM>>>(
        (const __half*)p_x1, (const __half*)p_w2h, (float*)p_h2p);
    k_reduce_alpha2<<<N_NODES, 160>>>(as2, ad2);
    k_agg2<<<N_NODES, 192>>>(b2);

    // bonds
    k_score<<<1, NB>>>(lf, rt, out);
}

// round 10
// speedup vs baseline: 8.6382x; 1.0280x over previous
#include <cuda_runtime.h>
#include <cuda_bf16.h>
#include <cuda_fp16.h>
#include <stdint.h>
#include <math.h>

#define N_NODES 8192
#define NE      49152
#define ETOT    (NE + N_NODES)       // 57344
#define IN_F    128
#define H1      64
#define HID     64
#define F1      (H1*HID)             // 4096
#define H2      5
#define OUTF    32
#define F2      (H2*OUTF)            // 160
#define NB      64
#define KSPLIT  4
#define KSLC    (F1 / KSPLIT)        // 1024

// ------------------------------ scratch (static, no allocation) --------------
__device__ __half g_h1[(size_t)N_NODES * F1];                // 67 MB
__device__ __half g_x1[(size_t)N_NODES * F1];                // 67 MB
__device__ __half g_xf[N_NODES * IN_F];
__device__ __half g_w1h[F1 * IN_F];
__device__ __half g_w2h[F2 * F1];
__device__ float g_as1[N_NODES * H1];
__device__ float g_ad1[N_NODES * H1];
__device__ float g_h2p[(size_t)KSPLIT * N_NODES * F2];       // 21 MB partials
__device__ float g_h2[N_NODES * F2];
__device__ float g_as2[N_NODES * H2];
__device__ float g_ad2[N_NODES * H2];
__device__ float g_x2[N_NODES * OUTF];
__device__ int   g_counts[N_NODES];   // zero at start of every call (scan resets)
__device__ int   g_off[N_NODES + 1];
__device__ int   g_cursor[N_NODES];
__device__ int   g_csr_src[ETOT];

// ------------------------------ PTX helpers ----------------------------------
__device__ __forceinline__ uint32_t smem_u32(const void* p) {
    uint32_t a;
    asm("{ .reg .u64 t; cvta.to.shared.u64 t, %1; cvt.u32.u64 %0, t; }"
        : "=r"(a) : "l"(p));
    return a;
}

__device__ __forceinline__ void cpa16(uint32_t d, const void* s) {
    asm volatile("cp.async.cg.shared.global [%0], [%1], 16;" :: "r"(d), "l"(s));
}
__device__ __forceinline__ void cpa_commit() {
    asm volatile("cp.async.commit_group;" ::: "memory");
}
template <int N> __device__ __forceinline__ void cpa_wait() {
    asm volatile("cp.async.wait_group %0;" :: "n"(N) : "memory");
}

__device__ __forceinline__ void ldsm4(uint32_t* r, uint32_t addr) {
    asm volatile("ldmatrix.sync.aligned.m8n8.x4.shared.b16 {%0,%1,%2,%3}, [%4];"
                 : "=r"(r[0]), "=r"(r[1]), "=r"(r[2]), "=r"(r[3]) : "r"(addr));
}

__device__ __forceinline__ void mma16816h(float* c, const uint32_t* a,
                                          const uint32_t* b) {
    asm volatile(
        "mma.sync.aligned.m16n8k16.row.col.f32.f16.f16.f32 "
        "{%0,%1,%2,%3}, {%4,%5,%6,%7}, {%8,%9}, {%0,%1,%2,%3};"
        : "+f"(c[0]), "+f"(c[1]), "+f"(c[2]), "+f"(c[3])
        : "r"(a[0]), "r"(a[1]), "r"(a[2]), "r"(a[3]), "r"(b[0]), "r"(b[1]));
}

// --------- fused input conversion + edge counting ----------------------------
#define NXE (N_NODES * IN_F)     // 1048576
#define NW1 (F1 * IN_F)          // 524288
#define NW2 (F2 * F1)            // 655360
#define NSPLIT (NXE + NW1 + NW2)

__global__ void k_prep(const float* __restrict__ x, const float* __restrict__ W1,
                       const float* __restrict__ W2, const int* __restrict__ ei) {
    int i = blockIdx.x * blockDim.x + threadIdx.x;
    if (i < NE) atomicAdd(&g_counts[ei[NE + i]], 1);   // edge degree count
    if (i < NXE) {
        g_xf[i] = __float2half_rn(x[i]);
        return;
    }
    if (i < NXE + NW1) {
        int k = i - NXE;
        g_w1h[k] = __float2half_rn(W1[k]);
    } else if (i < NSPLIT) {
        int k = i - NXE - NW1;
        g_w2h[k] = __float2half_rn(W2[k]);
    }
}

// ------------------------------ CSR scan (adds self-loop, resets counts) -----
__global__ void k_scan() {
    __shared__ int sh[1024];
    int t = threadIdx.x;
    int loc[8];
    int s = 0;
#pragma unroll
    for (int j = 0; j < 8; j++) {
        int idx = t * 8 + j;
        loc[j] = g_counts[idx] + 1;    // +1 self-loop
        g_counts[idx] = 0;             // reset for next call (graph replay)
        s += loc[j];
    }
    sh[t] = s;
    __syncthreads();
    for (int off = 1; off < 1024; off <<= 1) {
        int v = (t >= off) ? sh[t - off] : 0;
        __syncthreads();
        sh[t] += v;
        __syncthreads();
    }
    int run = (t == 0) ? 0 : sh[t - 1];
#pragma unroll
    for (int j = 0; j < 8; j++) {
        int idx = t * 8 + j;
        g_off[idx] = run;
        g_cursor[idx] = run;
        run += loc[j];
    }
    if (t == 1023) g_off[N_NODES] = run;
}

__global__ void k_scatter(const int* __restrict__ ei) {
    int i = blockIdx.x * blockDim.x + threadIdx.x;
    if (i >= ETOT) return;
    int src, dst;
    if (i < NE) { src = ei[i]; dst = ei[NE + i]; }
    else        { src = i - NE; dst = src; }
    int pos = atomicAdd(&g_cursor[dst], 1);
    g_csr_src[pos] = src;
}

// ------------------------------ GEMM1 (fp16 1-term + fused alpha) ------------
#define TSTRIDE 80                        // bytes per smem row (5 x 16B segs)
#define S1TILE  (128 * TSTRIDE)           // 10240 B
#define STAGE1  (2 * S1TILE)              // A, B
#define GEMM1_SMEM 40960                  // 2 stages (also >= 128*68*4 staging)

__global__ __launch_bounds__(256, 2)
void gemm1_mma(const __half* __restrict__ Af, const __half* __restrict__ Bh,
               __half* __restrict__ C,
               const float* __restrict__ att_s, const float* __restrict__ att_d) {
    extern __shared__ char smem[];
    const int N = F1, K = IN_F;
    const int tid = threadIdx.x;
    const int wid = tid >> 5, lane = tid & 31;
    const int m0 = blockIdx.y * 128, n0 = blockIdx.x * 128;
    const int wm = wid >> 1, wn = wid & 1;
    const int NC = K >> 5;                // 4
    const uint32_t sb = smem_u32(smem);

    float acc[2][8][4];
#pragma unroll
    for (int im = 0; im < 2; ++im)
#pragma unroll
        for (int j = 0; j < 8; ++j)
#pragma unroll
            for (int q = 0; q < 4; ++q) acc[im][j][q] = 0.f;

    auto load_stage = [&](int c, int s) {
        uint32_t base = sb + (uint32_t)s * STAGE1;
        const size_t kc = (size_t)c * 32;
#pragma unroll
        for (int i = tid; i < 512; i += 256) {
            int r = i >> 2, seg = i & 3;
            uint32_t off = (uint32_t)(r * TSTRIDE + seg * 16);
            cpa16(base + off, Af + (size_t)(m0 + r) * K + kc + seg * 8);
            cpa16(base + S1TILE + off, Bh + (size_t)(n0 + r) * K + kc + seg * 8);
        }
        cpa_commit();
    };

    load_stage(0, 0);
    for (int c = 0; c < NC; ++c) {
        if (c + 1 < NC) {
            load_stage(c + 1, (c + 1) & 1);
            cpa_wait<1>();
        } else {
            cpa_wait<0>();
        }
        __syncthreads();

        const uint32_t base = sb + (uint32_t)(c & 1) * STAGE1;
#pragma unroll
        for (int ks = 0; ks < 2; ++ks) {
            const uint32_t kb = ks * 32;
            uint32_t a[2][4], bh[4][4];
#pragma unroll
            for (int im = 0; im < 2; ++im) {
                uint32_t ra = (uint32_t)((wm * 32 + im * 16 + (lane & 15)) * TSTRIDE)
                              + kb + ((lane >> 4) & 1) * 16;
                ldsm4(a[im], base + ra);
            }
#pragma unroll
            for (int p = 0; p < 4; ++p) {
                uint32_t rb = (uint32_t)((wn * 64 + p * 16 + ((lane >> 4) & 1) * 8 +
                                          (lane & 7)) * TSTRIDE)
                              + kb + ((lane >> 3) & 1) * 16;
                ldsm4(bh[p], base + S1TILE + rb);
            }
#pragma unroll
            for (int im = 0; im < 2; ++im)
#pragma unroll
                for (int j = 0; j < 8; ++j)
                    mma16816h(acc[im][j], a[im], &bh[j >> 1][(j & 1) * 2]);
        }
        __syncthreads();
    }

    // epilogue 1a: stage fp16 tile into smem (row stride 68 u32 = 272 B)
    uint32_t* ep = reinterpret_cast<uint32_t*>(smem);
#pragma unroll
    for (int im = 0; im < 2; ++im)
#pragma unroll
        for (int j = 0; j < 8; ++j) {
            int r = wm * 32 + im * 16 + (lane >> 2);
            int c32 = wn * 32 + j * 4 + (lane & 3);
            __half2 v0 = __floats2half2_rn(acc[im][j][0], acc[im][j][1]);
            __half2 v1 = __floats2half2_rn(acc[im][j][2], acc[im][j][3]);
            ep[r * 68 + c32] = *reinterpret_cast<uint32_t*>(&v0);
            ep[(r + 8) * 68 + c32] = *reinterpret_cast<uint32_t*>(&v1);
        }

    // epilogue 2: fused attention dots (register-only, overlaps staging)
    const int head = (blockIdx.x << 1) + wn;
    float as_att[16], ad_att[16];
#pragma unroll
    for (int j = 0; j < 8; ++j) {
        int cc = head * HID + j * 8 + (lane & 3) * 2;
        as_att[2 * j] = att_s[cc];     as_att[2 * j + 1] = att_s[cc + 1];
        ad_att[2 * j] = att_d[cc];     ad_att[2 * j + 1] = att_d[cc + 1];
    }
#pragma unroll
    for (int im = 0; im < 2; ++im) {
        float s0 = 0.f, s1 = 0.f, d0 = 0.f, d1 = 0.f;
#pragma unroll
        for (int j = 0; j < 8; ++j) {
            s0 += acc[im][j][0] * as_att[2 * j] + acc[im][j][1] * as_att[2 * j + 1];
            s1 += acc[im][j][2] * as_att[2 * j] + acc[im][j][3] * as_att[2 * j + 1];
            d0 += acc[im][j][0] * ad_att[2 * j] + acc[im][j][1] * ad_att[2 * j + 1];
            d1 += acc[im][j][2] * ad_att[2 * j] + acc[im][j][3] * ad_att[2 * j + 1];
        }
#pragma unroll
        for (int o = 1; o < 4; o <<= 1) {
            s0 += __shfl_xor_sync(0xffffffffu, s0, o);
            s1 += __shfl_xor_sync(0xffffffffu, s1, o);
            d0 += __shfl_xor_sync(0xffffffffu, d0, o);
            d1 += __shfl_xor_sync(0xffffffffu, d1, o);
        }
        if ((lane & 3) == 0) {
            int r = m0 + wm * 32 + im * 16 + (lane >> 2);
            g_as1[r * H1 + head] = s0;
            g_ad1[r * H1 + head] = d0;
            g_as1[(r + 8) * H1 + head] = s1;
            g_ad1[(r + 8) * H1 + head] = d1;
        }
    }

    // epilogue 1b: coalesced 16B stores
    __syncthreads();
#pragma unroll
    for (int it = 0; it < 8; ++it) {
        int idx = tid + it * 256;         // 0..2047
        int row = idx >> 4, c16 = idx & 15;
        uint4 v = *reinterpret_cast<uint4*>(&ep[row * 68 + c16 * 4]);
        *reinterpret_cast<uint4*>(&C[(size_t)(m0 + row) * N + n0 + c16 * 8]) = v;
    }
}

// ------------------------------ GEMM2 (split-K x4, BN=160, fp16 1-term) ------
#define A2TILE (128 * TSTRIDE)            // 10240
#define B2TILE (160 * TSTRIDE)            // 12800
#define STAGE2 (A2TILE + B2TILE)          // 23040
#define GEMM2_SMEM (2 * STAGE2)           // 46080 (also >= 64*164*4 staging)

__global__ __launch_bounds__(256, 2)
void gemm2_mma(const __half* __restrict__ Af, const __half* __restrict__ Bh,
               float* __restrict__ Cp) {
    extern __shared__ char smem[];
    const int K = F1;
    const int tid = threadIdx.x;
    const int wid = tid >> 5, lane = tid & 31;
    const int m0 = blockIdx.y * 128;
    const size_t kb0 = (size_t)blockIdx.z * KSLC;
    const int wm = wid >> 1, wn = wid & 1;
    const int NC = KSLC >> 5;             // 32
    const uint32_t sb = smem_u32(smem);

    float acc[2][10][4];
#pragma unroll
    for (int im = 0; im < 2; ++im)
#pragma unroll
        for (int j = 0; j < 10; ++j)
#pragma unroll
            for (int q = 0; q < 4; ++q) acc[im][j][q] = 0.f;

    auto load_stage = [&](int c, int s) {
        uint32_t base = sb + (uint32_t)s * STAGE2;
        const size_t kc = kb0 + (size_t)c * 32;
#pragma unroll
        for (int i = tid; i < 512; i += 256) {
            int r = i >> 2, seg = i & 3;
            uint32_t off = (uint32_t)(r * TSTRIDE + seg * 16);
            cpa16(base + off, Af + (size_t)(m0 + r) * K + kc + seg * 8);
        }
#pragma unroll
        for (int i = tid; i < 640; i += 256) {
            int r = i >> 2, seg = i & 3;
            uint32_t off = (uint32_t)(r * TSTRIDE + seg * 16);
            cpa16(base + A2TILE + off, Bh + (size_t)r * K + kc + seg * 8);
        }
        cpa_commit();
    };

    load_stage(0, 0);
    for (int c = 0; c < NC; ++c) {
        if (c + 1 < NC) {
            load_stage(c + 1, (c + 1) & 1);
            cpa_wait<1>();
        } else {
            cpa_wait<0>();
        }
        __syncthreads();

        const uint32_t base = sb + (uint32_t)(c & 1) * STAGE2;
#pragma unroll
        for (int ks = 0; ks < 2; ++ks) {
            const uint32_t kb = ks * 32;
            uint32_t a[2][4], bh[5][4];
#pragma unroll
            for (int im = 0; im < 2; ++im) {
                uint32_t ra = (uint32_t)((wm * 32 + im * 16 + (lane & 15)) * TSTRIDE)
                              + kb + ((lane >> 4) & 1) * 16;
                ldsm4(a[im], base + ra);
            }
#pragma unroll
            for (int p = 0; p < 5; ++p) {
                uint32_t rb = (uint32_t)((wn * 80 + p * 16 + ((lane >> 4) & 1) * 8 +
                                          (lane & 7)) * TSTRIDE)
                              + kb + ((lane >> 3) & 1) * 16;
                ldsm4(bh[p], base + A2TILE + rb);
            }
#pragma unroll
            for (int im = 0; im < 2; ++im)
#pragma unroll
                for (int j = 0; j < 10; ++j)
                    mma16816h(acc[im][j], a[im], &bh[j >> 1][(j & 1) * 2]);
        }
        __syncthreads();
    }

    // epilogue: stage 64-row chunks in smem (row stride 164 floats), coalesced out
    float* ep = reinterpret_cast<float*>(smem);
    float* out = Cp + (size_t)blockIdx.z * (N_NODES * F2);
#pragma unroll
    for (int chunk = 0; chunk < 2; ++chunk) {
        if ((wm >> 1) == chunk) {
            int rbase = (wm & 1) * 32;
#pragma unroll
            for (int im = 0; im < 2; ++im)
#pragma unroll
                for (int j = 0; j < 10; ++j) {
                    int r = rbase + im * 16 + (lane >> 2);
                    int cc = wn * 80 + j * 8 + (lane & 3) * 2;
                    *(float2*)&ep[r * 164 + cc] =
                        make_float2(acc[im][j][0], acc[im][j][1]);
                    *(float2*)&ep[(r + 8) * 164 + cc] =
                        make_float2(acc[im][j][2], acc[im][j][3]);
                }
        }
        __syncthreads();
#pragma unroll
        for (int it = 0; it < 10; ++it) {
            int idx = tid + it * 256;        // 0..2559
            int row = idx / 40, c4 = idx % 40;
            float4 v = *reinterpret_cast<float4*>(&ep[row * 164 + c4 * 4]);
            *reinterpret_cast<float4*>(
                &out[(size_t)(m0 + chunk * 64 + row) * F2 + c4 * 4]) = v;
        }
        __syncthreads();
    }
}

// ------------- split-K reduce (deterministic) + fused alpha2 dots ------------
__global__ __launch_bounds__(160)
void k_reduce_alpha2(const float* __restrict__ att_s, const float* __restrict__ att_d) {
    const int n = blockIdx.x;
    const int t = threadIdx.x;          // 0..159
    const int lane = t & 31, head = t >> 5;
    float s = 0.f;
#pragma unroll
    for (int z = 0; z < KSPLIT; ++z)
        s += g_h2p[(size_t)z * (N_NODES * F2) + n * F2 + t];
    g_h2[n * F2 + t] = s;
    float vs = s * att_s[t];
    float vd = s * att_d[t];
#pragma unroll
    for (int o = 16; o > 0; o >>= 1) {
        vs += __shfl_down_sync(0xffffffffu, vs, o);
        vd += __shfl_down_sync(0xffffffffu, vd, o);
    }
    if (!lane) { g_as2[n * H2 + head] = vs; g_ad2[n * H2 + head] = vd; }
}

// ------------------------------ layer-1 aggregation + ELU + fp16 out ---------
__global__ __launch_bounds__(256)
void k_agg1(const float* __restrict__ b1) {
    const int n = blockIdx.x;
    const int t = threadIdx.x;
    const int start = g_off[n];
    const int deg = g_off[n + 1] - start;

    __shared__ float sh_m[H1], sh_den[H1], sh_ad[H1];
    __shared__ float sh_w[32 * H1];
    __shared__ int   s_src[32];
    __shared__ float pm[4][H1], pd[4][H1];

    // softmax max/denominator: 4-way parallel over edges, online per stripe
    {
        const int h = t & 63, quarter = t >> 6;
        float adv = g_ad1[n * H1 + h];
        float m = -1e30f, den = 0.f;
        for (int e = quarter; e < deg; e += 4) {
            int s = g_csr_src[start + e];
            float l = g_as1[s * H1 + h] + adv;
            l = l > 0.f ? l : 0.2f * l;
            if (l > m) { den = den * __expf(m - l) + 1.f; m = l; }
            else       { den += __expf(l - m); }
        }
        pm[quarter][h] = m;
        pd[quarter][h] = den;
        if (quarter == 0) sh_ad[h] = adv;
    }
    __syncthreads();
    if (t < H1) {
        float m0 = pm[0][t], m1 = pm[1][t], m2 = pm[2][t], m3 = pm[3][t];
        float M = fmaxf(fmaxf(m0, m1), fmaxf(m2, m3));
        float D = pd[0][t] * __expf(m0 - M) + pd[1][t] * __expf(m1 - M) +
                  pd[2][t] * __expf(m2 - M) + pd[3][t] * __expf(m3 - M);
        sh_m[t] = M; sh_den[t] = D;
    }
    __syncthreads();

    float acc[16];
#pragma unroll
    for (int i = 0; i < 16; i++) acc[i] = 0.f;
    const int h = t >> 2;  // head of this thread's 16-feature slice

    for (int e0 = 0; e0 < deg; e0 += 32) {
        int ce = min(32, deg - e0);
        if (t < ce) s_src[t] = g_csr_src[start + e0 + t];
        __syncthreads();
        for (int k = t; k < ce * H1; k += 256) {
            int e = k >> 6, hh = k & 63;
            float l = g_as1[s_src[e] * H1 + hh] + sh_ad[hh];
            l = l > 0.f ? l : 0.2f * l;
            sh_w[k] = __expf(l - sh_m[hh]);
        }
        __syncthreads();
        for (int e = 0; e < ce; e++) {
            const uint4* hp = reinterpret_cast<const uint4*>(
                g_h1 + (size_t)s_src[e] * F1 + t * 16);
            float wv = sh_w[(e << 6) + h];
#pragma unroll
            for (int q = 0; q < 2; q++) {
                uint4 u = hp[q];
                float2 f0 = __half22float2(*(const __half2*)&u.x);
                float2 f1 = __half22float2(*(const __half2*)&u.y);
                float2 f2 = __half22float2(*(const __half2*)&u.z);
                float2 f3 = __half22float2(*(const __half2*)&u.w);
                acc[8 * q + 0] += wv * f0.x;
                acc[8 * q + 1] += wv * f0.y;
                acc[8 * q + 2] += wv * f1.x;
                acc[8 * q + 3] += wv * f1.y;
                acc[8 * q + 4] += wv * f2.x;
                acc[8 * q + 5] += wv * f2.y;
                acc[8 * q + 6] += wv * f3.x;
                acc[8 * q + 7] += wv * f3.y;
            }
        }
        __syncthreads();
    }

    float invden = 1.f / sh_den[h];
    const float4* bp = reinterpret_cast<const float4*>(b1 + t * 16);
    float vals[16];
#pragma unroll
    for (int q = 0; q < 4; q++) {
        float4 bv = bp[q];
        float v0 = acc[4 * q + 0] * invden + bv.x;
        float v1 = acc[4 * q + 1] * invden + bv.y;
        float v2 = acc[4 * q + 2] * invden + bv.z;
        float v3 = acc[4 * q + 3] * invden + bv.w;
        vals[4 * q + 0] = v0 > 0.f ? v0 : __expf(v0) - 1.f;
        vals[4 * q + 1] = v1 > 0.f ? v1 : __expf(v1) - 1.f;
        vals[4 * q + 2] = v2 > 0.f ? v2 : __expf(v2) - 1.f;
        vals[4 * q + 3] = v3 > 0.f ? v3 : __expf(v3) - 1.f;
    }
    uint32_t pk[8];
#pragma unroll
    for (int i = 0; i < 8; i++) {
        __half2 hv = __floats2half2_rn(vals[2 * i], vals[2 * i + 1]);
        pk[i] = *reinterpret_cast<uint32_t*>(&hv);
    }
    size_t off = (size_t)n * F1 + t * 16;
    uint4* op = reinterpret_cast<uint4*>(g_x1 + off);
    op[0] = make_uint4(pk[0], pk[1], pk[2], pk[3]);
    op[1] = make_uint4(pk[4], pk[5], pk[6], pk[7]);
}

// ------------------------------ layer-2 aggregation + head mean --------------
__global__ __launch_bounds__(192)
void k_agg2(const float* __restrict__ b2) {
    const int n = blockIdx.x;
    const int t = threadIdx.x;
    const int start = g_off[n];
    const int deg = g_off[n + 1] - start;

    __shared__ float sh_m[H2], sh_den[H2], sh_ad[H2];
    __shared__ float sh_r[F2];
    __shared__ float pm2[4][H2], pd2[4][H2];

    // phase 1: 4-way striped online softmax over edges (20 threads)
    if (t < 20) {
        const int stripe = t / 5, hh = t % 5;
        float adv = g_ad2[n * H2 + hh];
        float m = -1e30f, den = 0.f;
        for (int e = stripe; e < deg; e += 4) {
            int s = g_csr_src[start + e];
            float l = g_as2[s * H2 + hh] + adv;
            l = l > 0.f ? l : 0.2f * l;
            if (l > m) { den = den * __expf(m - l) + 1.f; m = l; }
            else       { den += __expf(l - m); }
        }
        pm2[stripe][hh] = m;
        pd2[stripe][hh] = den;
        if (stripe == 0) sh_ad[hh] = adv;
    }
    __syncthreads();
    if (t < H2) {
        float m0 = pm2[0][t], m1 = pm2[1][t], m2 = pm2[2][t], m3 = pm2[3][t];
        float M = fmaxf(fmaxf(m0, m1), fmaxf(m2, m3));
        float D = pd2[0][t] * __expf(m0 - M) + pd2[1][t] * __expf(m1 - M) +
                  pd2[2][t] * __expf(m2 - M) + pd2[3][t] * __expf(m3 - M);
        sh_m[t] = M; sh_den[t] = D;
    }
    __syncthreads();

    if (t < F2) {
        int hh = t >> 5;
        float m = sh_m[hh], adv = sh_ad[hh];
        float acc = 0.f;
        for (int e = 0; e < deg; e++) {
            int s = g_csr_src[start + e];
            float l = g_as2[s * H2 + hh] + adv;
            l = l > 0.f ? l : 0.2f * l;
            acc += __expf(l - m) * g_h2[s * F2 + t];
        }
        sh_r[t] = acc / sh_den[hh];
    }
    __syncthreads();

    if (t < OUTF) {
        float v = (sh_r[t] + sh_r[32 + t] + sh_r[64 + t] + sh_r[96 + t] +
                   sh_r[128 + t]) * 0.2f + b2[t];
        g_x2[n * OUTF + t] = v;
    }
}

// ------------------------------ bond scores + softmax ------------------------
__global__ void k_score(const int* __restrict__ lefts,
                        const int* __restrict__ rights,
                        float* __restrict__ out) {
    __shared__ float sm[NB];
    int t = threadIdx.x;
    int l = lefts[t], r = rights[t];
    float s = 0.f;
#pragma unroll
    for (int c = 0; c < OUTF; c++) s += g_x2[l * OUTF + c] + g_x2[r * OUTF + c];
    sm[t] = s;
    __syncthreads();
    float mx = -1e30f;
    for (int j = 0; j < NB; j++) mx = fmaxf(mx, sm[j]);
    float e = __expf(s - mx);
    __syncthreads();
    sm[t] = e;
    __syncthreads();
    float sum = 0.f;
    for (int j = 0; j < NB; j++) sum += sm[j];
    out[t] = e / sum;
}

// ------------------------------ launch ---------------------------------------
extern "C" void kernel_launch(void* const* d_in, const int* in_sizes, int n_in,
                              void* d_out, int out_size) {
    const float* x   = (const float*)d_in[0];
    const int*   ei  = (const int*)d_in[1];
    const int*   lf  = (const int*)d_in[2];
    const int*   rt  = (const int*)d_in[3];
    const float* W1  = (const float*)d_in[4];
    const float* as1 = (const float*)d_in[5];
    const float* ad1 = (const float*)d_in[6];
    const float* b1  = (const float*)d_in[7];
    const float* W2  = (const float*)d_in[8];
    const float* as2 = (const float*)d_in[9];
    const float* ad2 = (const float*)d_in[10];
    const float* b2  = (const float*)d_in[11];
    float* out = (float*)d_out;

    cudaFuncSetAttribute(gemm1_mma, cudaFuncAttributeMaxDynamicSharedMemorySize,
                         GEMM1_SMEM);
    cudaFuncSetAttribute(gemm2_mma, cudaFuncAttributeMaxDynamicSharedMemorySize,
                         GEMM2_SMEM);

    void *p_xf, *p_w1h, *p_w2h;
    void *p_h1, *p_h2p, *p_x1;
    cudaGetSymbolAddress(&p_xf, g_xf);
    cudaGetSymbolAddress(&p_w1h, g_w1h);
    cudaGetSymbolAddress(&p_w2h, g_w2h);
    cudaGetSymbolAddress(&p_h1, g_h1);
    cudaGetSymbolAddress(&p_h2p, g_h2p);
    cudaGetSymbolAddress(&p_x1, g_x1);

    // fused input conversions + edge counting
    k_prep<<<(NSPLIT + 255) / 256, 256>>>(x, W1, W2, ei);

    // CSR by destination (scan adds self-loops, resets counts)
    k_scan<<<1, 1024>>>();
    k_scatter<<<(ETOT + 255) / 256, 256>>>(ei);

    // layer 1: h1 = x @ W1^T (fp16 out) + fused alpha1
    gemm1_mma<<<dim3(F1 / 128, N_NODES / 128), 256, GEMM1_SMEM>>>(
        (const __half*)p_xf, (const __half*)p_w1h, (__half*)p_h1, as1, ad1);
    k_agg1<<<N_NODES, 256>>>(b1);

    // layer 2: h2 = x1 @ W2^T, split-K x4 + fused reduce/alpha2
    gemm2_mma<<<dim3(1, N_NODES / 128, KSPLIT), 256, GEMM2_SMEM>>>(
        (const __half*)p_x1, (const __half*)p_w2h, (float*)p_h2p);
    k_reduce_alpha2<<<N_NODES, 160>>>(as2, ad2);
    k_agg2<<<N_NODES, 192>>>(b2);

    // bonds
    k_score<<<1, NB>>>(lf, rt, out);
}